// round 1
// baseline (speedup 1.0000x reference)
#include <cuda_runtime.h>
#include <math.h>

#define NPIX 4096
#define NB 4
#define NHEADS 4
#define DHEAD 32
#define CIN 256
#define HID 128

// Scratch (alloc-free rule): qkv = 4*384*4096 floats (25.2MB), attn out = 4*128*4096 (8.4MB)
__device__ float g_qkv[(size_t)NB * 3 * HID * NPIX];
__device__ float g_ao[(size_t)NB * HID * NPIX];

// ---------------------------------------------------------------------------
// Tiled SIMT GEMM: Y[z] = W (MxK) @ X[z] (KxN) (+ bias), row-major, z = batch.
// BM=BN=64, BK=16, 256 threads, 4x4 register tile per thread.
// All problem dims divide the tile sizes exactly (M in {384,256}, K in {256,128}, N=4096).
// ---------------------------------------------------------------------------
__global__ __launch_bounds__(256) void gemm_kernel(
    const float* __restrict__ W, const float* __restrict__ X,
    float* __restrict__ Y, const float* __restrict__ bias,
    int M, int N, int K)
{
    X += (size_t)blockIdx.z * (size_t)K * N;
    Y += (size_t)blockIdx.z * (size_t)M * N;

    __shared__ float Ws[16][65];   // +1 pad: conflict-free transposed store
    __shared__ float Xs[16][64];

    const int tx = threadIdx.x & 15;
    const int ty = threadIdx.x >> 4;
    const int row0 = blockIdx.y * 64;
    const int col0 = blockIdx.x * 64;

    float acc[4][4];
#pragma unroll
    for (int i = 0; i < 4; i++)
#pragma unroll
        for (int j = 0; j < 4; j++) acc[i][j] = 0.f;

    for (int kk = 0; kk < K; kk += 16) {
#pragma unroll
        for (int i = 0; i < 4; i++) {
            int idx = threadIdx.x + i * 256;
            int m = idx >> 4, k = idx & 15;          // W tile 64x16, coalesced over K
            Ws[k][m] = W[(size_t)(row0 + m) * K + kk + k];
            int k2 = idx >> 6, n = idx & 63;         // X tile 16x64, coalesced over N
            Xs[k2][n] = X[(size_t)(kk + k2) * N + col0 + n];
        }
        __syncthreads();
#pragma unroll
        for (int k = 0; k < 16; k++) {
            float wr[4], xr[4];
#pragma unroll
            for (int i = 0; i < 4; i++) wr[i] = Ws[k][ty * 4 + i];
#pragma unroll
            for (int j = 0; j < 4; j++) xr[j] = Xs[k][tx * 4 + j];
#pragma unroll
            for (int i = 0; i < 4; i++)
#pragma unroll
                for (int j = 0; j < 4; j++)
                    acc[i][j] = fmaf(wr[i], xr[j], acc[i][j]);
        }
        __syncthreads();
    }

#pragma unroll
    for (int i = 0; i < 4; i++) {
        float bv = bias ? bias[row0 + ty * 4 + i] : 0.f;
#pragma unroll
        for (int j = 0; j < 4; j++)
            Y[(size_t)(row0 + ty * 4 + i) * N + col0 + tx * 4 + j] = acc[i][j] + bv;
    }
}

// ---------------------------------------------------------------------------
// L2-normalize q and k in-place over d (32 strided rows). SCALE=10 folded into q.
// One thread per (b, sel, head, pix); loads coalesced across pix.
// ---------------------------------------------------------------------------
__global__ __launch_bounds__(256) void l2norm_kernel(float* __restrict__ qkv)
{
    int idx = blockIdx.x * 256 + threadIdx.x;   // 4*2*4*4096 = 131072 total
    int pix = idx & (NPIX - 1);
    int t = idx >> 12;                          // 0..31
    int head = t & 3;
    int sel = (t >> 2) & 1;                     // 0 = q, 1 = k
    int b = t >> 3;

    float* p = qkv + ((size_t)b * 384 + sel * 128 + head * 32) * NPIX + pix;
    float v[32];
    float ss = 0.f;
#pragma unroll
    for (int d = 0; d < 32; d++) {
        v[d] = p[(size_t)d * NPIX];
        ss = fmaf(v[d], v[d], ss);
    }
    float inv = 1.f / fmaxf(sqrtf(ss), 1e-12f);
    if (sel == 0) inv *= 10.f;                  // fold SCALE into q
#pragma unroll
    for (int d = 0; d < 32; d++) p[(size_t)d * NPIX] = v[d] * inv;
}

// ---------------------------------------------------------------------------
// Flash attention, fp32. Each thread owns ONE query: q[32], o[32] in registers.
// K/V staged in smem tiles of 64 keys; all threads read the same key -> broadcast.
// Online softmax with per-16-key-chunk max update and rescale.
// Grid: (4096/128 q-tiles, b*h=16). 128 threads/block.
// Output layout matches reference transpose: out[b][h*32+d][pix].
// ---------------------------------------------------------------------------
__global__ __launch_bounds__(128, 4) void flash_kernel(
    const float* __restrict__ qkv, float* __restrict__ out)
{
    __shared__ float sk[32][64];
    __shared__ float sv[32][64];

    const int bh = blockIdx.y;
    const int b = bh >> 2, h = bh & 3;
    const float* qp = qkv + ((size_t)b * 384 + h * 32) * NPIX;
    const float* kp = qkv + ((size_t)b * 384 + 128 + h * 32) * NPIX;
    const float* vp = qkv + ((size_t)b * 384 + 256 + h * 32) * NPIX;

    const int qi = blockIdx.x * 128 + threadIdx.x;

    float q[32], o[32];
#pragma unroll
    for (int d = 0; d < 32; d++) {
        q[d] = qp[(size_t)d * NPIX + qi];
        o[d] = 0.f;
    }
    float m = -1e30f, l = 0.f;

    for (int j0 = 0; j0 < NPIX; j0 += 64) {
        __syncthreads();
#pragma unroll
        for (int i = threadIdx.x; i < 32 * 64; i += 128) {
            int d = i >> 6, j = i & 63;
            sk[d][j] = kp[(size_t)d * NPIX + j0 + j];
            sv[d][j] = vp[(size_t)d * NPIX + j0 + j];
        }
        __syncthreads();

#pragma unroll 1
        for (int c0 = 0; c0 < 64; c0 += 16) {
            float s[16];
#pragma unroll
            for (int c = 0; c < 16; c++) s[c] = 0.f;
#pragma unroll
            for (int d = 0; d < 32; d++) {
                float qd = q[d];
#pragma unroll
                for (int c = 0; c < 16; c++)
                    s[c] = fmaf(qd, sk[d][c0 + c], s[c]);
            }
            float mt = m;
#pragma unroll
            for (int c = 0; c < 16; c++) mt = fmaxf(mt, s[c]);
            float corr = __expf(m - mt);   // m=-1e30 first time -> exp(-huge)=0
            m = mt;
            l *= corr;
#pragma unroll
            for (int d = 0; d < 32; d++) o[d] *= corr;
#pragma unroll
            for (int c = 0; c < 16; c++) {
                s[c] = __expf(s[c] - m);
                l += s[c];
            }
#pragma unroll
            for (int d = 0; d < 32; d++) {
                float acc = o[d];
#pragma unroll
                for (int c = 0; c < 16; c++)
                    acc = fmaf(s[c], sv[d][c0 + c], acc);
                o[d] = acc;
            }
        }
    }

    const float inv = 1.f / l;
    float* op = out + ((size_t)b * 128 + h * 32) * NPIX + qi;
#pragma unroll
    for (int d = 0; d < 32; d++) op[(size_t)d * NPIX] = o[d] * inv;
}

// ---------------------------------------------------------------------------
// kernel_launch: qkv GEMM -> l2norm -> flash attention -> out GEMM (+bias)
// ---------------------------------------------------------------------------
extern "C" void kernel_launch(void* const* d_in, const int* in_sizes, int n_in,
                              void* d_out, int out_size)
{
    const float* x     = (const float*)d_in[0];  // (4, 256, 64, 64)
    const float* w_qkv = (const float*)d_in[1];  // (384, 256)
    const float* w_out = (const float*)d_in[2];  // (256, 128)
    const float* b_out = (const float*)d_in[3];  // (256,)
    float* out = (float*)d_out;                  // (4, 256, 64, 64)

    static float* qkv = nullptr;
    static float* ao  = nullptr;
    if (!qkv) {
        cudaGetSymbolAddress((void**)&qkv, g_qkv);
        cudaGetSymbolAddress((void**)&ao,  g_ao);
    }

    // 1) QKV projection: (384x256) @ (256x4096) per batch
    dim3 g1(NPIX / 64, 384 / 64, NB);
    gemm_kernel<<<g1, 256>>>(w_qkv, x, qkv, nullptr, 384, NPIX, CIN);

    // 2) L2-normalize q,k (SCALE folded into q)
    l2norm_kernel<<<(NB * 2 * NHEADS * NPIX) / 256, 256>>>(qkv);

    // 3) Flash attention per (b,h)
    dim3 g3(NPIX / 128, NB * NHEADS);
    flash_kernel<<<g3, 128>>>(qkv, ao);

    // 4) Output projection + bias: (256x128) @ (128x4096) per batch
    dim3 g4(NPIX / 64, 256 / 64, NB);
    gemm_kernel<<<g4, 256>>>(w_out, ao, out, b_out, 256, NPIX, HID);
}

// round 2
// speedup vs baseline: 2.1468x; 2.1468x over previous
#include <cuda_runtime.h>
#include <math.h>

#define NPIX 4096
#define NB 4
#define NHEADS 4
#define CIN 256
#define HID 128

// Scratch (alloc-free rule)
__device__ float g_qkv[(size_t)NB * 3 * HID * NPIX];
__device__ float g_ao[(size_t)NB * HID * NPIX];

// ---------------------------------------------------------------------------
// Tiled SIMT GEMM: Y[z] = W (MxK) @ X[z] (KxN) (+ bias)
// ---------------------------------------------------------------------------
__global__ __launch_bounds__(256) void gemm_kernel(
    const float* __restrict__ W, const float* __restrict__ X,
    float* __restrict__ Y, const float* __restrict__ bias,
    int M, int N, int K)
{
    X += (size_t)blockIdx.z * (size_t)K * N;
    Y += (size_t)blockIdx.z * (size_t)M * N;

    __shared__ float Ws[16][65];
    __shared__ float Xs[16][64];

    const int tx = threadIdx.x & 15;
    const int ty = threadIdx.x >> 4;
    const int row0 = blockIdx.y * 64;
    const int col0 = blockIdx.x * 64;

    float acc[4][4];
#pragma unroll
    for (int i = 0; i < 4; i++)
#pragma unroll
        for (int j = 0; j < 4; j++) acc[i][j] = 0.f;

    for (int kk = 0; kk < K; kk += 16) {
#pragma unroll
        for (int i = 0; i < 4; i++) {
            int idx = threadIdx.x + i * 256;
            int m = idx >> 4, k = idx & 15;
            Ws[k][m] = W[(size_t)(row0 + m) * K + kk + k];
            int k2 = idx >> 6, n = idx & 63;
            Xs[k2][n] = X[(size_t)(kk + k2) * N + col0 + n];
        }
        __syncthreads();
#pragma unroll
        for (int k = 0; k < 16; k++) {
            float wr[4], xr[4];
#pragma unroll
            for (int i = 0; i < 4; i++) wr[i] = Ws[k][ty * 4 + i];
#pragma unroll
            for (int j = 0; j < 4; j++) xr[j] = Xs[k][tx * 4 + j];
#pragma unroll
            for (int i = 0; i < 4; i++)
#pragma unroll
                for (int j = 0; j < 4; j++)
                    acc[i][j] = fmaf(wr[i], xr[j], acc[i][j]);
        }
        __syncthreads();
    }

#pragma unroll
    for (int i = 0; i < 4; i++) {
        float bv = bias ? bias[row0 + ty * 4 + i] : 0.f;
#pragma unroll
        for (int j = 0; j < 4; j++)
            Y[(size_t)(row0 + ty * 4 + i) * N + col0 + tx * 4 + j] = acc[i][j] + bv;
    }
}

// ---------------------------------------------------------------------------
// L2-normalize q and k in-place over d. SCALE=10 folded into q.
// ---------------------------------------------------------------------------
__global__ __launch_bounds__(256) void l2norm_kernel(float* __restrict__ qkv)
{
    int idx = blockIdx.x * 256 + threadIdx.x;
    int pix = idx & (NPIX - 1);
    int t = idx >> 12;
    int head = t & 3;
    int sel = (t >> 2) & 1;
    int b = t >> 3;

    float* p = qkv + ((size_t)b * 384 + sel * 128 + head * 32) * NPIX + pix;
    float v[32];
    float ss = 0.f;
#pragma unroll
    for (int d = 0; d < 32; d++) {
        v[d] = p[(size_t)d * NPIX];
        ss = fmaf(v[d], v[d], ss);
    }
    float inv = 1.f / fmaxf(sqrtf(ss), 1e-12f);
    if (sel == 0) inv *= 10.f;
#pragma unroll
    for (int d = 0; d < 32; d++) p[(size_t)d * NPIX] = v[d] * inv;
}

// ---------------------------------------------------------------------------
// Tensor-core flash attention (tf32 mma.sync.m16n8k8).
//
// Per block: 8 warps, 128 queries (16/warp). Key loop in tiles of 64.
// Phase 1: S^T = K @ Q^T  (A = K [key x d], B = Q^T [d x q]; Q frags persistent
//          in registers). Accumulator: rows = keys (g axis), cols = queries
//          (2c axis). Online softmax: column max via 3 shfl.xor; corr/l are
//          thread-local on the query(=column) axis.
// Phase 2: O^T = V^T @ P^T (A = V^T [d x key] from smem, B = P^T [key x q]
//          round-tripped through a 32-key half-tile smem buffer, same-warp
//          write->read with __syncwarp only). O columns = queries (2c axis),
//          so the phase-1 corr factors apply directly.
// ---------------------------------------------------------------------------
__device__ __forceinline__ unsigned f2tf32(float x) {
    unsigned r; asm("cvt.rna.tf32.f32 %0, %1;" : "=r"(r) : "f"(x)); return r;
}
__device__ __forceinline__ void mma_tf32(float* d, const unsigned* a, const unsigned* b) {
    asm volatile("mma.sync.aligned.m16n8k8.row.col.f32.tf32.tf32.f32 "
                 "{%0,%1,%2,%3}, {%4,%5,%6,%7}, {%8,%9}, {%0,%1,%2,%3};"
                 : "+f"(d[0]), "+f"(d[1]), "+f"(d[2]), "+f"(d[3])
                 : "r"(a[0]), "r"(a[1]), "r"(a[2]), "r"(a[3]),
                   "r"(b[0]), "r"(b[1]));
}

#define SKS 72   // [d][key] stride: 72 % 32 == 8 -> bank = 8d + key, conflict-free frags
#define SPS 132  // P^T buffer stride

__global__ __launch_bounds__(256, 2) void flash_tc_kernel(
    const float* __restrict__ qkv, float* __restrict__ out)
{
    __shared__ unsigned sk[32][SKS];
    __shared__ unsigned sv[32][SKS];
    __shared__ unsigned sp[32][SPS];   // 32-key half-tile of P^T, 128 q columns

    const int tid  = threadIdx.x;
    const int lane = tid & 31, warp = tid >> 5;
    const int g = lane >> 2, c = lane & 3;
    const int bh = blockIdx.y, b = bh >> 2, h = bh & 3;

    const float* qp = qkv + ((size_t)b * 384 + h * 32) * NPIX;
    const float* kp = qp + (size_t)128 * NPIX;
    const float* vp = qp + (size_t)256 * NPIX;
    const int qw = blockIdx.x * 128 + warp * 16;   // warp's first query

    // Persistent Q B-fragments: [kstep][ntile][2].  B(k=d, n=q) col-major:
    // b0 at (d = 8ks+c, q = 8n+g), b1 at (d = 8ks+c+4, q = 8n+g)
    unsigned bq[4][2][2];
#pragma unroll
    for (int ks = 0; ks < 4; ks++)
#pragma unroll
        for (int n = 0; n < 2; n++) {
            bq[ks][n][0] = f2tf32(qp[(size_t)(8 * ks + c) * NPIX + qw + 8 * n + g]);
            bq[ks][n][1] = f2tf32(qp[(size_t)(8 * ks + c + 4) * NPIX + qw + 8 * n + g]);
        }

    float O[2][2][4];      // [d-tile][n-tile][reg]
    float mrun[2][2], lrun[2][2];
#pragma unroll
    for (int m2 = 0; m2 < 2; m2++)
#pragma unroll
        for (int n = 0; n < 2; n++)
#pragma unroll
            for (int r = 0; r < 4; r++) O[m2][n][r] = 0.f;
#pragma unroll
    for (int n = 0; n < 2; n++)
#pragma unroll
        for (int p = 0; p < 2; p++) { mrun[n][p] = -1e30f; lrun[n][p] = 0.f; }

    for (int j0 = 0; j0 < NPIX; j0 += 64) {
        __syncthreads();
#pragma unroll
        for (int i = tid; i < 2048; i += 256) {
            int d = i >> 6, j = i & 63;
            sk[d][j] = f2tf32(kp[(size_t)d * NPIX + j0 + j]);
            sv[d][j] = f2tf32(vp[(size_t)d * NPIX + j0 + j]);
        }
        __syncthreads();

        // ---- Phase 1: S^T tiles (keys 64 x q 16 per warp) ----
        float acc[4][2][4];
#pragma unroll
        for (int m = 0; m < 4; m++)
#pragma unroll
            for (int n = 0; n < 2; n++)
#pragma unroll
                for (int r = 0; r < 4; r++) acc[m][n][r] = 0.f;

#pragma unroll
        for (int m = 0; m < 4; m++) {
#pragma unroll
            for (int ks = 0; ks < 4; ks++) {
                unsigned a[4];
                a[0] = sk[8 * ks + c][16 * m + g];
                a[1] = sk[8 * ks + c][16 * m + g + 8];
                a[2] = sk[8 * ks + c + 4][16 * m + g];
                a[3] = sk[8 * ks + c + 4][16 * m + g + 8];
                mma_tf32(acc[m][0], a, bq[ks][0]);
                mma_tf32(acc[m][1], a, bq[ks][1]);
            }
        }

        // ---- Online softmax on columns (q axis) ----
        float corr[2][2];
#pragma unroll
        for (int n = 0; n < 2; n++) {
#pragma unroll
            for (int p = 0; p < 2; p++) {
                float t = -1e30f;
#pragma unroll
                for (int m = 0; m < 4; m++)
                    t = fmaxf(t, fmaxf(acc[m][n][p], acc[m][n][p + 2]));
                t = fmaxf(t, __shfl_xor_sync(0xffffffffu, t, 4));
                t = fmaxf(t, __shfl_xor_sync(0xffffffffu, t, 8));
                t = fmaxf(t, __shfl_xor_sync(0xffffffffu, t, 16));
                float mn = fmaxf(mrun[n][p], t);
                corr[n][p] = __expf(mrun[n][p] - mn);
                mrun[n][p] = mn;
                float ls = 0.f;
#pragma unroll
                for (int m = 0; m < 4; m++) {
                    acc[m][n][p]     = __expf(acc[m][n][p] - mn);
                    acc[m][n][p + 2] = __expf(acc[m][n][p + 2] - mn);
                    ls += acc[m][n][p] + acc[m][n][p + 2];
                }
                lrun[n][p] = lrun[n][p] * corr[n][p] + ls;
            }
        }
#pragma unroll
        for (int m2 = 0; m2 < 2; m2++)
#pragma unroll
            for (int n = 0; n < 2; n++) {
                O[m2][n][0] *= corr[n][0];
                O[m2][n][1] *= corr[n][1];
                O[m2][n][2] *= corr[n][0];
                O[m2][n][3] *= corr[n][1];
            }

        // ---- Phase 2: PV in two 32-key halves through sp ----
#pragma unroll
        for (int half = 0; half < 2; half++) {
            __syncwarp();
#pragma unroll
            for (int mt = 0; mt < 2; mt++) {
                int m = half * 2 + mt;      // phase-1 m-tile
                int kl = 16 * mt + g;       // local key row in sp
#pragma unroll
                for (int n = 0; n < 2; n++) {
                    int qc = 16 * warp + 8 * n + 2 * c;
                    sp[kl][qc]         = f2tf32(acc[m][n][0]);
                    sp[kl][qc + 1]     = f2tf32(acc[m][n][1]);
                    sp[kl + 8][qc]     = f2tf32(acc[m][n][2]);
                    sp[kl + 8][qc + 1] = f2tf32(acc[m][n][3]);
                }
            }
            __syncwarp();
#pragma unroll
            for (int ks = 0; ks < 4; ks++) {
                unsigned bb[2][2];
#pragma unroll
                for (int n = 0; n < 2; n++) {
                    bb[n][0] = sp[8 * ks + c][16 * warp + 8 * n + g];
                    bb[n][1] = sp[8 * ks + c + 4][16 * warp + 8 * n + g];
                }
                int kg = 32 * half + 8 * ks;
#pragma unroll
                for (int m2 = 0; m2 < 2; m2++) {
                    unsigned a[4];
                    a[0] = sv[16 * m2 + g][kg + c];
                    a[1] = sv[16 * m2 + g + 8][kg + c];
                    a[2] = sv[16 * m2 + g][kg + c + 4];
                    a[3] = sv[16 * m2 + g + 8][kg + c + 4];
                    mma_tf32(O[m2][0], a, bb[0]);
                    mma_tf32(O[m2][1], a, bb[1]);
                }
            }
        }
    }

    // ---- Epilogue: normalize and store O^T[d][q] ----
    float inv[2][2];
#pragma unroll
    for (int n = 0; n < 2; n++)
#pragma unroll
        for (int p = 0; p < 2; p++) {
            float l = lrun[n][p];
            l += __shfl_xor_sync(0xffffffffu, l, 4);
            l += __shfl_xor_sync(0xffffffffu, l, 8);
            l += __shfl_xor_sync(0xffffffffu, l, 16);
            inv[n][p] = 1.f / l;
        }

    float* op = out + ((size_t)b * 128 + h * 32) * NPIX;
#pragma unroll
    for (int m2 = 0; m2 < 2; m2++)
#pragma unroll
        for (int n = 0; n < 2; n++) {
            int q0 = qw + 8 * n + 2 * c;
            op[(size_t)(16 * m2 + g) * NPIX + q0]          = O[m2][n][0] * inv[n][0];
            op[(size_t)(16 * m2 + g) * NPIX + q0 + 1]      = O[m2][n][1] * inv[n][1];
            op[(size_t)(16 * m2 + g + 8) * NPIX + q0]      = O[m2][n][2] * inv[n][0];
            op[(size_t)(16 * m2 + g + 8) * NPIX + q0 + 1]  = O[m2][n][3] * inv[n][1];
        }
}

// ---------------------------------------------------------------------------
extern "C" void kernel_launch(void* const* d_in, const int* in_sizes, int n_in,
                              void* d_out, int out_size)
{
    const float* x     = (const float*)d_in[0];
    const float* w_qkv = (const float*)d_in[1];
    const float* w_out = (const float*)d_in[2];
    const float* b_out = (const float*)d_in[3];
    float* out = (float*)d_out;

    static float* qkv = nullptr;
    static float* ao  = nullptr;
    if (!qkv) {
        cudaGetSymbolAddress((void**)&qkv, g_qkv);
        cudaGetSymbolAddress((void**)&ao,  g_ao);
    }

    dim3 g1(NPIX / 64, 384 / 64, NB);
    gemm_kernel<<<g1, 256>>>(w_qkv, x, qkv, nullptr, 384, NPIX, CIN);

    l2norm_kernel<<<(NB * 2 * NHEADS * NPIX) / 256, 256>>>(qkv);

    dim3 g3(NPIX / 128, NB * NHEADS);
    flash_tc_kernel<<<g3, 256>>>(qkv, ao);

    dim3 g4(NPIX / 64, 256 / 64, NB);
    gemm_kernel<<<g4, 256>>>(w_out, ao, out, b_out, 256, NPIX, HID);
}

// round 3
// speedup vs baseline: 3.0607x; 1.4257x over previous
#include <cuda_runtime.h>
#include <math.h>

#define NPIX 4096
#define NB 4
#define NHEADS 4
#define CIN 256
#define HID 128

__device__ float g_qkv[(size_t)NB * 3 * HID * NPIX];
__device__ float g_ao[(size_t)NB * HID * NPIX];

// ---------------------------------------------------------------------------
// Tiled SIMT GEMM: Y[z] = W (MxK) @ X[z] (KxN) (+ bias)
// ---------------------------------------------------------------------------
__global__ __launch_bounds__(256) void gemm_kernel(
    const float* __restrict__ W, const float* __restrict__ X,
    float* __restrict__ Y, const float* __restrict__ bias,
    int M, int N, int K)
{
    X += (size_t)blockIdx.z * (size_t)K * N;
    Y += (size_t)blockIdx.z * (size_t)M * N;

    __shared__ float Ws[16][65];
    __shared__ float Xs[16][64];

    const int tx = threadIdx.x & 15;
    const int ty = threadIdx.x >> 4;
    const int row0 = blockIdx.y * 64;
    const int col0 = blockIdx.x * 64;

    float acc[4][4];
#pragma unroll
    for (int i = 0; i < 4; i++)
#pragma unroll
        for (int j = 0; j < 4; j++) acc[i][j] = 0.f;

    for (int kk = 0; kk < K; kk += 16) {
#pragma unroll
        for (int i = 0; i < 4; i++) {
            int idx = threadIdx.x + i * 256;
            int m = idx >> 4, k = idx & 15;
            Ws[k][m] = W[(size_t)(row0 + m) * K + kk + k];
            int k2 = idx >> 6, n = idx & 63;
            Xs[k2][n] = X[(size_t)(kk + k2) * N + col0 + n];
        }
        __syncthreads();
#pragma unroll
        for (int k = 0; k < 16; k++) {
            float wr[4], xr[4];
#pragma unroll
            for (int i = 0; i < 4; i++) wr[i] = Ws[k][ty * 4 + i];
#pragma unroll
            for (int j = 0; j < 4; j++) xr[j] = Xs[k][tx * 4 + j];
#pragma unroll
            for (int i = 0; i < 4; i++)
#pragma unroll
                for (int j = 0; j < 4; j++)
                    acc[i][j] = fmaf(wr[i], xr[j], acc[i][j]);
        }
        __syncthreads();
    }

#pragma unroll
    for (int i = 0; i < 4; i++) {
        float bv = bias ? bias[row0 + ty * 4 + i] : 0.f;
#pragma unroll
        for (int j = 0; j < 4; j++)
            Y[(size_t)(row0 + ty * 4 + i) * N + col0 + tx * 4 + j] = acc[i][j] + bv;
    }
}

__device__ __forceinline__ unsigned f2tf32(float x) {
    unsigned r; asm("cvt.rna.tf32.f32 %0, %1;" : "=r"(r) : "f"(x)); return r;
}

// ---------------------------------------------------------------------------
// L2-normalize q,k (SCALE folded into q) and pre-round q,k,v to tf32 values.
// sel: 0=q (norm*10), 1=k (norm), 2=v (round only).
// ---------------------------------------------------------------------------
__global__ __launch_bounds__(256) void l2norm_kernel(float* __restrict__ qkv)
{
    int idx = blockIdx.x * 256 + threadIdx.x;   // 4*3*4*4096 threads
    int pix = idx & (NPIX - 1);
    int t = idx >> 12;                          // 0..47
    int b = t / 12;
    int rem = t % 12;
    int sel = rem >> 2;
    int head = rem & 3;

    float* p = qkv + ((size_t)b * 384 + sel * 128 + head * 32) * NPIX + pix;
    float v[32];
    float ss = 0.f;
#pragma unroll
    for (int d = 0; d < 32; d++) {
        v[d] = p[(size_t)d * NPIX];
        ss = fmaf(v[d], v[d], ss);
    }
    float inv = 1.f;
    if (sel < 2) {
        inv = 1.f / fmaxf(sqrtf(ss), 1e-12f);
        if (sel == 0) inv *= 10.f;
    }
#pragma unroll
    for (int d = 0; d < 32; d++)
        p[(size_t)d * NPIX] = __uint_as_float(f2tf32(v[d] * inv));
}

// ---------------------------------------------------------------------------
// Tensor-core flash attention, tf32 mma.sync.m16n8k8, NO online softmax
// (logits bounded by 10 -> exp(s) directly, merge-by-sum).
// 4 warps, 32 queries/warp (128 q/block). Keys in tiles of 64, processed as
// two 32-key halves (acc for 2 m-tiles at a time keeps regs ~150).
// ---------------------------------------------------------------------------
__device__ __forceinline__ void mma_tf32(float* d, const unsigned* a, const unsigned* b) {
    asm volatile("mma.sync.aligned.m16n8k8.row.col.f32.tf32.tf32.f32 "
                 "{%0,%1,%2,%3}, {%4,%5,%6,%7}, {%8,%9}, {%0,%1,%2,%3};"
                 : "+f"(d[0]), "+f"(d[1]), "+f"(d[2]), "+f"(d[3])
                 : "r"(a[0]), "r"(a[1]), "r"(a[2]), "r"(a[3]),
                   "r"(b[0]), "r"(b[1]));
}
__device__ __forceinline__ void cpasync16(unsigned dst, const float* src) {
    asm volatile("cp.async.ca.shared.global [%0], [%1], 16;" :: "r"(dst), "l"(src));
}

#define SKS 72   // K smem stride (72%32==8): phase-1 A reads bank = 8c+g, conflict-free
#define SVS 68   // V smem stride (68%32==4): phase-2 A reads bank = 4g+c, conflict-free
#define SPS 136  // P^T buffer stride (136%32==8): B reads bank = 8c+g, conflict-free

__global__ __launch_bounds__(128, 3) void flash_tc_kernel(
    const float* __restrict__ qkv, float* __restrict__ out)
{
    __shared__ unsigned sk[32][SKS];
    __shared__ unsigned sv[32][SVS];
    __shared__ unsigned sp[32][SPS];   // 32 keys x 128 q of P^T

    const int tid  = threadIdx.x;
    const int lane = tid & 31, warp = tid >> 5;
    const int g = lane >> 2, c = lane & 3;
    const int bh = blockIdx.y, b = bh >> 2, h = bh & 3;

    const float* qp = qkv + ((size_t)b * 384 + h * 32) * NPIX;
    const float* kp = qp + (size_t)128 * NPIX;
    const float* vp = qp + (size_t)256 * NPIX;
    const int qw = blockIdx.x * 128 + warp * 32;   // warp's first query

    const unsigned sk0 = (unsigned)__cvta_generic_to_shared(&sk[0][0]);
    const unsigned sv0 = (unsigned)__cvta_generic_to_shared(&sv[0][0]);

    // Persistent Q B-frags (already tf32-rounded in gmem): [ks][n][2]
    unsigned bq[4][4][2];
#pragma unroll
    for (int ks = 0; ks < 4; ks++)
#pragma unroll
        for (int n = 0; n < 4; n++) {
            const float* qq = qp + (size_t)(8 * ks + c) * NPIX + qw + 8 * n + g;
            bq[ks][n][0] = __float_as_uint(qq[0]);
            bq[ks][n][1] = __float_as_uint(qq[4 * NPIX]);
        }

    float O[2][4][4];
    float lrun[4][2];
#pragma unroll
    for (int m2 = 0; m2 < 2; m2++)
#pragma unroll
        for (int n = 0; n < 4; n++)
#pragma unroll
            for (int r = 0; r < 4; r++) O[m2][n][r] = 0.f;
#pragma unroll
    for (int n = 0; n < 4; n++) { lrun[n][0] = 0.f; lrun[n][1] = 0.f; }

    for (int j0 = 0; j0 < NPIX; j0 += 64) {
        __syncthreads();
        // Fill K/V tiles via cp.async (pure copy: values pre-rounded to tf32)
#pragma unroll
        for (int r = 0; r < 4; r++) {
            int ch = tid + r * 128;            // 0..511
            int d = ch >> 4, cj = ch & 15;
            cpasync16(sk0 + (unsigned)(d * SKS + cj * 4) * 4, kp + (size_t)d * NPIX + j0 + cj * 4);
            cpasync16(sv0 + (unsigned)(d * SVS + cj * 4) * 4, vp + (size_t)d * NPIX + j0 + cj * 4);
        }
        asm volatile("cp.async.commit_group;");
        asm volatile("cp.async.wait_group 0;");
        __syncthreads();

#pragma unroll
        for (int half = 0; half < 2; half++) {
            // ---- Phase 1: S^T for 32 keys (2 m-tiles) x 32 q ----
            float acc[2][4][4];
#pragma unroll
            for (int mt = 0; mt < 2; mt++)
#pragma unroll
                for (int n = 0; n < 4; n++)
#pragma unroll
                    for (int r = 0; r < 4; r++) acc[mt][n][r] = 0.f;

#pragma unroll
            for (int mt = 0; mt < 2; mt++) {
                int km = 32 * half + 16 * mt;
#pragma unroll
                for (int ks = 0; ks < 4; ks++) {
                    unsigned a[4];
                    a[0] = sk[8 * ks + c][km + g];
                    a[1] = sk[8 * ks + c][km + g + 8];
                    a[2] = sk[8 * ks + c + 4][km + g];
                    a[3] = sk[8 * ks + c + 4][km + g + 8];
#pragma unroll
                    for (int n = 0; n < 4; n++)
                        mma_tf32(acc[mt][n], a, bq[ks][n]);
                }
            }

            // ---- exp (no max: logits bounded by ~10) + l accumulation ----
#pragma unroll
            for (int mt = 0; mt < 2; mt++)
#pragma unroll
                for (int n = 0; n < 4; n++) {
#pragma unroll
                    for (int r = 0; r < 4; r++) acc[mt][n][r] = __expf(acc[mt][n][r]);
                    lrun[n][0] += acc[mt][n][0] + acc[mt][n][2];
                    lrun[n][1] += acc[mt][n][1] + acc[mt][n][3];
                }

            // ---- P^T -> smem (same-warp round trip) ----
            __syncwarp();
#pragma unroll
            for (int mt = 0; mt < 2; mt++) {
                int kl = 16 * mt + g;
#pragma unroll
                for (int n = 0; n < 4; n++) {
                    int qc = 32 * warp + 8 * n + 2 * c;
                    sp[kl][qc]         = f2tf32(acc[mt][n][0]);
                    sp[kl][qc + 1]     = f2tf32(acc[mt][n][1]);
                    sp[kl + 8][qc]     = f2tf32(acc[mt][n][2]);
                    sp[kl + 8][qc + 1] = f2tf32(acc[mt][n][3]);
                }
            }
            __syncwarp();

            // ---- Phase 2: O^T += V^T @ P^T ----
#pragma unroll
            for (int ks = 0; ks < 4; ks++) {
                unsigned bb[4][2];
#pragma unroll
                for (int n = 0; n < 4; n++) {
                    bb[n][0] = sp[8 * ks + c][32 * warp + 8 * n + g];
                    bb[n][1] = sp[8 * ks + c + 4][32 * warp + 8 * n + g];
                }
                int kg = 32 * half + 8 * ks;
#pragma unroll
                for (int m2 = 0; m2 < 2; m2++) {
                    unsigned a[4];
                    a[0] = sv[16 * m2 + g][kg + c];
                    a[1] = sv[16 * m2 + g + 8][kg + c];
                    a[2] = sv[16 * m2 + g][kg + c + 4];
                    a[3] = sv[16 * m2 + g + 8][kg + c + 4];
#pragma unroll
                    for (int n = 0; n < 4; n++)
                        mma_tf32(O[m2][n], a, bb[n]);
                }
            }
        }
    }

    // ---- Epilogue: reduce l across the g-lane groups, normalize, store ----
    float inv[4][2];
#pragma unroll
    for (int n = 0; n < 4; n++)
#pragma unroll
        for (int p = 0; p < 2; p++) {
            float l = lrun[n][p];
            l += __shfl_xor_sync(0xffffffffu, l, 4);
            l += __shfl_xor_sync(0xffffffffu, l, 8);
            l += __shfl_xor_sync(0xffffffffu, l, 16);
            inv[n][p] = 1.f / l;
        }

    float* op = out + ((size_t)b * 128 + h * 32) * NPIX;
#pragma unroll
    for (int m2 = 0; m2 < 2; m2++)
#pragma unroll
        for (int n = 0; n < 4; n++) {
            int q0 = qw + 8 * n + 2 * c;
            op[(size_t)(16 * m2 + g) * NPIX + q0]         = O[m2][n][0] * inv[n][0];
            op[(size_t)(16 * m2 + g) * NPIX + q0 + 1]     = O[m2][n][1] * inv[n][1];
            op[(size_t)(16 * m2 + g + 8) * NPIX + q0]     = O[m2][n][2] * inv[n][0];
            op[(size_t)(16 * m2 + g + 8) * NPIX + q0 + 1] = O[m2][n][3] * inv[n][1];
        }
}

// ---------------------------------------------------------------------------
extern "C" void kernel_launch(void* const* d_in, const int* in_sizes, int n_in,
                              void* d_out, int out_size)
{
    const float* x     = (const float*)d_in[0];
    const float* w_qkv = (const float*)d_in[1];
    const float* w_out = (const float*)d_in[2];
    const float* b_out = (const float*)d_in[3];
    float* out = (float*)d_out;

    static float* qkv = nullptr;
    static float* ao  = nullptr;
    if (!qkv) {
        cudaGetSymbolAddress((void**)&qkv, g_qkv);
        cudaGetSymbolAddress((void**)&ao,  g_ao);
    }

    dim3 g1(NPIX / 64, 384 / 64, NB);
    gemm_kernel<<<g1, 256>>>(w_qkv, x, qkv, nullptr, 384, NPIX, CIN);

    l2norm_kernel<<<(NB * 3 * NHEADS * NPIX) / 256, 256>>>(qkv);

    dim3 g3(NPIX / 128, NB * NHEADS);
    flash_tc_kernel<<<g3, 128>>>(qkv, ao);

    dim3 g4(NPIX / 64, 256 / 64, NB);
    gemm_kernel<<<g4, 256>>>(w_out, ao, out, b_out, 256, NPIX, HID);
}

// round 4
// speedup vs baseline: 3.0708x; 1.0033x over previous
#include <cuda_runtime.h>
#include <math.h>

#define NPIX 4096
#define NB 4
#define NHEADS 4
#define CIN 256
#define HID 128

__device__ float g_qkv[(size_t)NB * 3 * HID * NPIX];
__device__ float g_ao[(size_t)NB * HID * NPIX];

// ---------------------------------------------------------------------------
// Tiled SIMT GEMM: Y[z] = W (MxK) @ X[z] (KxN) (+ bias)
// ---------------------------------------------------------------------------
__global__ __launch_bounds__(256) void gemm_kernel(
    const float* __restrict__ W, const float* __restrict__ X,
    float* __restrict__ Y, const float* __restrict__ bias,
    int M, int N, int K)
{
    X += (size_t)blockIdx.z * (size_t)K * N;
    Y += (size_t)blockIdx.z * (size_t)M * N;

    __shared__ float Ws[16][65];
    __shared__ float Xs[16][64];

    const int tx = threadIdx.x & 15;
    const int ty = threadIdx.x >> 4;
    const int row0 = blockIdx.y * 64;
    const int col0 = blockIdx.x * 64;

    float acc[4][4];
#pragma unroll
    for (int i = 0; i < 4; i++)
#pragma unroll
        for (int j = 0; j < 4; j++) acc[i][j] = 0.f;

    for (int kk = 0; kk < K; kk += 16) {
#pragma unroll
        for (int i = 0; i < 4; i++) {
            int idx = threadIdx.x + i * 256;
            int m = idx >> 4, k = idx & 15;
            Ws[k][m] = W[(size_t)(row0 + m) * K + kk + k];
            int k2 = idx >> 6, n = idx & 63;
            Xs[k2][n] = X[(size_t)(kk + k2) * N + col0 + n];
        }
        __syncthreads();
#pragma unroll
        for (int k = 0; k < 16; k++) {
            float wr[4], xr[4];
#pragma unroll
            for (int i = 0; i < 4; i++) wr[i] = Ws[k][ty * 4 + i];
#pragma unroll
            for (int j = 0; j < 4; j++) xr[j] = Xs[k][tx * 4 + j];
#pragma unroll
            for (int i = 0; i < 4; i++)
#pragma unroll
                for (int j = 0; j < 4; j++)
                    acc[i][j] = fmaf(wr[i], xr[j], acc[i][j]);
        }
        __syncthreads();
    }

#pragma unroll
    for (int i = 0; i < 4; i++) {
        float bv = bias ? bias[row0 + ty * 4 + i] : 0.f;
#pragma unroll
        for (int j = 0; j < 4; j++)
            Y[(size_t)(row0 + ty * 4 + i) * N + col0 + tx * 4 + j] = acc[i][j] + bv;
    }
}

__device__ __forceinline__ unsigned f2tf32(float x) {
    unsigned r; asm("cvt.rna.tf32.f32 %0, %1;" : "=r"(r) : "f"(x)); return r;
}

// ---------------------------------------------------------------------------
// L2-normalize q,k (SCALE folded into q) and pre-round q,k,v to tf32 values.
// sel: 0=q (norm*10), 1=k (norm), 2=v (round only).
// ---------------------------------------------------------------------------
__global__ __launch_bounds__(256) void l2norm_kernel(float* __restrict__ qkv)
{
    int idx = blockIdx.x * 256 + threadIdx.x;   // 4*3*4*4096 threads
    int pix = idx & (NPIX - 1);
    int t = idx >> 12;                          // 0..47
    int b = t / 12;
    int rem = t % 12;
    int sel = rem >> 2;
    int head = rem & 3;

    float* p = qkv + ((size_t)b * 384 + sel * 128 + head * 32) * NPIX + pix;
    float v[32];
    float ss = 0.f;
#pragma unroll
    for (int d = 0; d < 32; d++) {
        v[d] = p[(size_t)d * NPIX];
        ss = fmaf(v[d], v[d], ss);
    }
    float inv = 1.f;
    if (sel < 2) {
        inv = 1.f / fmaxf(sqrtf(ss), 1e-12f);
        if (sel == 0) inv *= 10.f;
    }
#pragma unroll
    for (int d = 0; d < 32; d++)
        p[(size_t)d * NPIX] = __uint_as_float(f2tf32(v[d] * inv));
}

// ---------------------------------------------------------------------------
// Tensor-core flash attention, tf32 mma.sync.m16n8k8, NO online softmax
// (logits bounded by 10 -> exp(s) directly, merge-by-sum).
// 4 warps, 32 queries/warp (128 q/block). Keys in tiles of 64, processed as
// two 32-key halves (acc for 2 m-tiles at a time keeps regs ~150).
// ---------------------------------------------------------------------------
__device__ __forceinline__ void mma_tf32(float* d, const unsigned* a, const unsigned* b) {
    asm volatile("mma.sync.aligned.m16n8k8.row.col.f32.tf32.tf32.f32 "
                 "{%0,%1,%2,%3}, {%4,%5,%6,%7}, {%8,%9}, {%0,%1,%2,%3};"
                 : "+f"(d[0]), "+f"(d[1]), "+f"(d[2]), "+f"(d[3])
                 : "r"(a[0]), "r"(a[1]), "r"(a[2]), "r"(a[3]),
                   "r"(b[0]), "r"(b[1]));
}
__device__ __forceinline__ void cpasync16(unsigned dst, const float* src) {
    asm volatile("cp.async.ca.shared.global [%0], [%1], 16;" :: "r"(dst), "l"(src));
}

#define SKS 72   // K smem stride (72%32==8): phase-1 A reads bank = 8c+g, conflict-free
#define SVS 68   // V smem stride (68%32==4): phase-2 A reads bank = 4g+c, conflict-free
#define SPS 136  // P^T buffer stride (136%32==8): B reads bank = 8c+g, conflict-free

__global__ __launch_bounds__(128, 3) void flash_tc_kernel(
    const float* __restrict__ qkv, float* __restrict__ out)
{
    __shared__ unsigned sk[32][SKS];
    __shared__ unsigned sv[32][SVS];
    __shared__ unsigned sp[32][SPS];   // 32 keys x 128 q of P^T

    const int tid  = threadIdx.x;
    const int lane = tid & 31, warp = tid >> 5;
    const int g = lane >> 2, c = lane & 3;
    const int bh = blockIdx.y, b = bh >> 2, h = bh & 3;

    const float* qp = qkv + ((size_t)b * 384 + h * 32) * NPIX;
    const float* kp = qp + (size_t)128 * NPIX;
    const float* vp = qp + (size_t)256 * NPIX;
    const int qw = blockIdx.x * 128 + warp * 32;   // warp's first query

    const unsigned sk0 = (unsigned)__cvta_generic_to_shared(&sk[0][0]);
    const unsigned sv0 = (unsigned)__cvta_generic_to_shared(&sv[0][0]);

    // Persistent Q B-frags (already tf32-rounded in gmem): [ks][n][2]
    unsigned bq[4][4][2];
#pragma unroll
    for (int ks = 0; ks < 4; ks++)
#pragma unroll
        for (int n = 0; n < 4; n++) {
            const float* qq = qp + (size_t)(8 * ks + c) * NPIX + qw + 8 * n + g;
            bq[ks][n][0] = __float_as_uint(qq[0]);
            bq[ks][n][1] = __float_as_uint(qq[4 * NPIX]);
        }

    float O[2][4][4];
    float lrun[4][2];
#pragma unroll
    for (int m2 = 0; m2 < 2; m2++)
#pragma unroll
        for (int n = 0; n < 4; n++)
#pragma unroll
            for (int r = 0; r < 4; r++) O[m2][n][r] = 0.f;
#pragma unroll
    for (int n = 0; n < 4; n++) { lrun[n][0] = 0.f; lrun[n][1] = 0.f; }

    for (int j0 = 0; j0 < NPIX; j0 += 64) {
        __syncthreads();
        // Fill K/V tiles via cp.async (pure copy: values pre-rounded to tf32)
#pragma unroll
        for (int r = 0; r < 4; r++) {
            int ch = tid + r * 128;            // 0..511
            int d = ch >> 4, cj = ch & 15;
            cpasync16(sk0 + (unsigned)(d * SKS + cj * 4) * 4, kp + (size_t)d * NPIX + j0 + cj * 4);
            cpasync16(sv0 + (unsigned)(d * SVS + cj * 4) * 4, vp + (size_t)d * NPIX + j0 + cj * 4);
        }
        asm volatile("cp.async.commit_group;");
        asm volatile("cp.async.wait_group 0;");
        __syncthreads();

#pragma unroll
        for (int half = 0; half < 2; half++) {
            // ---- Phase 1: S^T for 32 keys (2 m-tiles) x 32 q ----
            float acc[2][4][4];
#pragma unroll
            for (int mt = 0; mt < 2; mt++)
#pragma unroll
                for (int n = 0; n < 4; n++)
#pragma unroll
                    for (int r = 0; r < 4; r++) acc[mt][n][r] = 0.f;

#pragma unroll
            for (int mt = 0; mt < 2; mt++) {
                int km = 32 * half + 16 * mt;
#pragma unroll
                for (int ks = 0; ks < 4; ks++) {
                    unsigned a[4];
                    a[0] = sk[8 * ks + c][km + g];
                    a[1] = sk[8 * ks + c][km + g + 8];
                    a[2] = sk[8 * ks + c + 4][km + g];
                    a[3] = sk[8 * ks + c + 4][km + g + 8];
#pragma unroll
                    for (int n = 0; n < 4; n++)
                        mma_tf32(acc[mt][n], a, bq[ks][n]);
                }
            }

            // ---- exp (no max: logits bounded by ~10) + l accumulation ----
#pragma unroll
            for (int mt = 0; mt < 2; mt++)
#pragma unroll
                for (int n = 0; n < 4; n++) {
#pragma unroll
                    for (int r = 0; r < 4; r++) acc[mt][n][r] = __expf(acc[mt][n][r]);
                    lrun[n][0] += acc[mt][n][0] + acc[mt][n][2];
                    lrun[n][1] += acc[mt][n][1] + acc[mt][n][3];
                }

            // ---- P^T -> smem (same-warp round trip) ----
            __syncwarp();
#pragma unroll
            for (int mt = 0; mt < 2; mt++) {
                int kl = 16 * mt + g;
#pragma unroll
                for (int n = 0; n < 4; n++) {
                    int qc = 32 * warp + 8 * n + 2 * c;
                    sp[kl][qc]         = f2tf32(acc[mt][n][0]);
                    sp[kl][qc + 1]     = f2tf32(acc[mt][n][1]);
                    sp[kl + 8][qc]     = f2tf32(acc[mt][n][2]);
                    sp[kl + 8][qc + 1] = f2tf32(acc[mt][n][3]);
                }
            }
            __syncwarp();

            // ---- Phase 2: O^T += V^T @ P^T ----
#pragma unroll
            for (int ks = 0; ks < 4; ks++) {
                unsigned bb[4][2];
#pragma unroll
                for (int n = 0; n < 4; n++) {
                    bb[n][0] = sp[8 * ks + c][32 * warp + 8 * n + g];
                    bb[n][1] = sp[8 * ks + c + 4][32 * warp + 8 * n + g];
                }
                int kg = 32 * half + 8 * ks;
#pragma unroll
                for (int m2 = 0; m2 < 2; m2++) {
                    unsigned a[4];
                    a[0] = sv[16 * m2 + g][kg + c];
                    a[1] = sv[16 * m2 + g + 8][kg + c];
                    a[2] = sv[16 * m2 + g][kg + c + 4];
                    a[3] = sv[16 * m2 + g + 8][kg + c + 4];
#pragma unroll
                    for (int n = 0; n < 4; n++)
                        mma_tf32(O[m2][n], a, bb[n]);
                }
            }
        }
    }

    // ---- Epilogue: reduce l across the g-lane groups, normalize, store ----
    float inv[4][2];
#pragma unroll
    for (int n = 0; n < 4; n++)
#pragma unroll
        for (int p = 0; p < 2; p++) {
            float l = lrun[n][p];
            l += __shfl_xor_sync(0xffffffffu, l, 4);
            l += __shfl_xor_sync(0xffffffffu, l, 8);
            l += __shfl_xor_sync(0xffffffffu, l, 16);
            inv[n][p] = 1.f / l;
        }

    float* op = out + ((size_t)b * 128 + h * 32) * NPIX;
#pragma unroll
    for (int m2 = 0; m2 < 2; m2++)
#pragma unroll
        for (int n = 0; n < 4; n++) {
            int q0 = qw + 8 * n + 2 * c;
            op[(size_t)(16 * m2 + g) * NPIX + q0]         = O[m2][n][0] * inv[n][0];
            op[(size_t)(16 * m2 + g) * NPIX + q0 + 1]     = O[m2][n][1] * inv[n][1];
            op[(size_t)(16 * m2 + g + 8) * NPIX + q0]     = O[m2][n][2] * inv[n][0];
            op[(size_t)(16 * m2 + g + 8) * NPIX + q0 + 1] = O[m2][n][3] * inv[n][1];
        }
}

// ---------------------------------------------------------------------------
extern "C" void kernel_launch(void* const* d_in, const int* in_sizes, int n_in,
                              void* d_out, int out_size)
{
    const float* x     = (const float*)d_in[0];
    const float* w_qkv = (const float*)d_in[1];
    const float* w_out = (const float*)d_in[2];
    const float* b_out = (const float*)d_in[3];
    float* out = (float*)d_out;

    static float* qkv = nullptr;
    static float* ao  = nullptr;
    if (!qkv) {
        cudaGetSymbolAddress((void**)&qkv, g_qkv);
        cudaGetSymbolAddress((void**)&ao,  g_ao);
    }

    dim3 g1(NPIX / 64, 384 / 64, NB);
    gemm_kernel<<<g1, 256>>>(w_qkv, x, qkv, nullptr, 384, NPIX, CIN);

    l2norm_kernel<<<(NB * 3 * NHEADS * NPIX) / 256, 256>>>(qkv);

    dim3 g3(NPIX / 128, NB * NHEADS);
    flash_tc_kernel<<<g3, 128>>>(qkv, ao);

    dim3 g4(NPIX / 64, 256 / 64, NB);
    gemm_kernel<<<g4, 256>>>(w_out, ao, out, b_out, 256, NPIX, HID);
}

// round 6
// speedup vs baseline: 3.3778x; 1.1000x over previous
#include <cuda_runtime.h>
#include <cstdint>
#include <math.h>

#define NPIX 4096
#define NB 4
#define NHEADS 4
#define CIN 256
#define HID 128

__device__ float g_qkv[(size_t)NB * 3 * HID * NPIX];
__device__ float g_ao[(size_t)NB * HID * NPIX];

// ---------------------------------------------------------------------------
// Tiled SIMT GEMM: Y[z] = W (MxK) @ X[z] (KxN) (+ bias)
// ---------------------------------------------------------------------------
__global__ __launch_bounds__(256) void gemm_kernel(
    const float* __restrict__ W, const float* __restrict__ X,
    float* __restrict__ Y, const float* __restrict__ bias,
    int M, int N, int K)
{
    X += (size_t)blockIdx.z * (size_t)K * N;
    Y += (size_t)blockIdx.z * (size_t)M * N;
    __shared__ float Ws[16][65];
    __shared__ float Xs[16][64];
    const int tx = threadIdx.x & 15, ty = threadIdx.x >> 4;
    const int row0 = blockIdx.y * 64, col0 = blockIdx.x * 64;
    float acc[4][4];
#pragma unroll
    for (int i = 0; i < 4; i++)
#pragma unroll
        for (int j = 0; j < 4; j++) acc[i][j] = 0.f;
    for (int kk = 0; kk < K; kk += 16) {
#pragma unroll
        for (int i = 0; i < 4; i++) {
            int idx = threadIdx.x + i * 256;
            int m = idx >> 4, k = idx & 15;
            Ws[k][m] = W[(size_t)(row0 + m) * K + kk + k];
            int k2 = idx >> 6, n = idx & 63;
            Xs[k2][n] = X[(size_t)(kk + k2) * N + col0 + n];
        }
        __syncthreads();
#pragma unroll
        for (int k = 0; k < 16; k++) {
            float wr[4], xr[4];
#pragma unroll
            for (int i = 0; i < 4; i++) wr[i] = Ws[k][ty * 4 + i];
#pragma unroll
            for (int j = 0; j < 4; j++) xr[j] = Xs[k][tx * 4 + j];
#pragma unroll
            for (int i = 0; i < 4; i++)
#pragma unroll
                for (int j = 0; j < 4; j++) acc[i][j] = fmaf(wr[i], xr[j], acc[i][j]);
        }
        __syncthreads();
    }
#pragma unroll
    for (int i = 0; i < 4; i++) {
        float bv = bias ? bias[row0 + ty * 4 + i] : 0.f;
#pragma unroll
        for (int j = 0; j < 4; j++)
            Y[(size_t)(row0 + ty * 4 + i) * N + col0 + tx * 4 + j] = acc[i][j] + bv;
    }
}

__device__ __forceinline__ unsigned f2tf32(float x) {
    unsigned r; asm("cvt.rna.tf32.f32 %0, %1;" : "=r"(r) : "f"(x)); return r;
}
__device__ __forceinline__ float ex2(float x) {
    float y; asm("ex2.approx.ftz.f32 %0, %1;" : "=f"(y) : "f"(x)); return y;
}

// ---------------------------------------------------------------------------
// L2-normalize q,k; q additionally scaled by 10*log2(e) (softmax uses exp2).
// All of q,k,v pre-rounded to tf32 values in place.
// ---------------------------------------------------------------------------
__global__ __launch_bounds__(256) void l2norm_kernel(float* __restrict__ qkv)
{
    int idx = blockIdx.x * 256 + threadIdx.x;
    int pix = idx & (NPIX - 1);
    int t = idx >> 12;
    int b = t / 12, rem = t % 12;
    int sel = rem >> 2, head = rem & 3;
    float* p = qkv + ((size_t)b * 384 + sel * 128 + head * 32) * NPIX + pix;
    float v[32]; float ss = 0.f;
#pragma unroll
    for (int d = 0; d < 32; d++) { v[d] = p[(size_t)d * NPIX]; ss = fmaf(v[d], v[d], ss); }
    float inv = 1.f;
    if (sel < 2) {
        inv = 1.f / fmaxf(sqrtf(ss), 1e-12f);
        if (sel == 0) inv *= 14.426950408889634f;   // 10 * log2(e)
    }
#pragma unroll
    for (int d = 0; d < 32; d++)
        p[(size_t)d * NPIX] = __uint_as_float(f2tf32(v[d] * inv));
}

// ---------------------------------------------------------------------------
// Tensor-core flash attention (mma.sync tf32), double-buffered K/V cp.async,
// exp2-based softmax (scale folded into q), STS.64 P stores.
// 4 warps, 32 q/warp (128 q/block); keys in tiles of 64 (two 32-key halves).
// ---------------------------------------------------------------------------
__device__ __forceinline__ void mma_tf32(float* d, const unsigned* a, const unsigned* b) {
    asm volatile("mma.sync.aligned.m16n8k8.row.col.f32.tf32.tf32.f32 "
                 "{%0,%1,%2,%3}, {%4,%5,%6,%7}, {%8,%9}, {%0,%1,%2,%3};"
                 : "+f"(d[0]), "+f"(d[1]), "+f"(d[2]), "+f"(d[3])
                 : "r"(a[0]), "r"(a[1]), "r"(a[2]), "r"(a[3]),
                   "r"(b[0]), "r"(b[1]));
}
__device__ __forceinline__ void cpasync16(unsigned dst, const float* src) {
    asm volatile("cp.async.ca.shared.global [%0], [%1], 16;" :: "r"(dst), "l"(src));
}

#define SKS 72
#define SVS 68
#define SPS 136
#define STAGEF (32 * SKS + 32 * SVS)            // floats per K/V stage (4480)
#define SMEMB ((2 * STAGEF + 32 * SPS) * 4)     // 53248 bytes

__global__ __launch_bounds__(128, 3) void flash_tc_kernel(
    const float* __restrict__ qkv, float* __restrict__ out)
{
    extern __shared__ float dsm[];
    const int tid  = threadIdx.x;
    const int lane = tid & 31, warp = tid >> 5;
    const int g = lane >> 2, c = lane & 3;
    const int bh = blockIdx.y, b = bh >> 2, h = bh & 3;

    const float* qp = qkv + ((size_t)b * 384 + h * 32) * NPIX;
    const float* kp = qp + (size_t)128 * NPIX;
    const float* vp = qp + (size_t)256 * NPIX;
    const int qw = blockIdx.x * 128 + warp * 32;

    const unsigned sbase = (unsigned)__cvta_generic_to_shared(dsm);
    unsigned (*sp)[SPS] = (unsigned(*)[SPS])(dsm + 2 * STAGEF);

    // Persistent Q B-frags (tf32-rounded + 10*log2e-scaled in gmem)
    unsigned bq[4][4][2];
#pragma unroll
    for (int ks = 0; ks < 4; ks++)
#pragma unroll
        for (int n = 0; n < 4; n++) {
            const float* qq = qp + (size_t)(8 * ks + c) * NPIX + qw + 8 * n + g;
            bq[ks][n][0] = __float_as_uint(qq[0]);
            bq[ks][n][1] = __float_as_uint(qq[4 * NPIX]);
        }

    float O[2][4][4];
    float lrun[4][2];
#pragma unroll
    for (int m2 = 0; m2 < 2; m2++)
#pragma unroll
        for (int n = 0; n < 4; n++)
#pragma unroll
            for (int r = 0; r < 4; r++) O[m2][n][r] = 0.f;
#pragma unroll
    for (int n = 0; n < 4; n++) { lrun[n][0] = 0.f; lrun[n][1] = 0.f; }

    // ---- fill helper (macro-ish lambda) ----
    auto fill = [&](int it, int s) {
        unsigned ka = sbase + (unsigned)(s * STAGEF) * 4u;
        unsigned va = ka + 32u * SKS * 4u;
        int j0 = it * 64;
#pragma unroll
        for (int r = 0; r < 4; r++) {
            int ch = tid + r * 128;
            int d = ch >> 4, cj = ch & 15;
            cpasync16(ka + (unsigned)(d * SKS + cj * 4) * 4u, kp + (size_t)d * NPIX + j0 + cj * 4);
            cpasync16(va + (unsigned)(d * SVS + cj * 4) * 4u, vp + (size_t)d * NPIX + j0 + cj * 4);
        }
        asm volatile("cp.async.commit_group;");
    };

    fill(0, 0);

    for (int it = 0; it < 64; ++it) {
        if (it < 63) {
            fill(it + 1, (it + 1) & 1);
            asm volatile("cp.async.wait_group 1;");
        } else {
            asm volatile("cp.async.wait_group 0;");
        }
        __syncthreads();

        const unsigned (*sk)[SKS] = (const unsigned(*)[SKS])(dsm + (it & 1) * STAGEF);
        const unsigned (*sv)[SVS] = (const unsigned(*)[SVS])(dsm + (it & 1) * STAGEF + 32 * SKS);

#pragma unroll
        for (int half = 0; half < 2; half++) {
            // ---- Phase 1: S^T for 32 keys x 32 q ----
            float acc[2][4][4];
#pragma unroll
            for (int mt = 0; mt < 2; mt++)
#pragma unroll
                for (int n = 0; n < 4; n++)
#pragma unroll
                    for (int r = 0; r < 4; r++) acc[mt][n][r] = 0.f;

#pragma unroll
            for (int mt = 0; mt < 2; mt++) {
                int km = 32 * half + 16 * mt;
#pragma unroll
                for (int ks = 0; ks < 4; ks++) {
                    unsigned a[4];
                    a[0] = sk[8 * ks + c][km + g];
                    a[1] = sk[8 * ks + c][km + g + 8];
                    a[2] = sk[8 * ks + c + 4][km + g];
                    a[3] = sk[8 * ks + c + 4][km + g + 8];
#pragma unroll
                    for (int n = 0; n < 4; n++)
                        mma_tf32(acc[mt][n], a, bq[ks][n]);
                }
            }

            // ---- exp2 (scale pre-folded) + l ----
#pragma unroll
            for (int mt = 0; mt < 2; mt++)
#pragma unroll
                for (int n = 0; n < 4; n++) {
#pragma unroll
                    for (int r = 0; r < 4; r++) acc[mt][n][r] = ex2(acc[mt][n][r]);
                    lrun[n][0] += acc[mt][n][0] + acc[mt][n][2];
                    lrun[n][1] += acc[mt][n][1] + acc[mt][n][3];
                }

            // ---- P^T -> smem (STS.64, same-warp round trip) ----
            __syncwarp();
#pragma unroll
            for (int mt = 0; mt < 2; mt++) {
                int kl = 16 * mt + g;
#pragma unroll
                for (int n = 0; n < 4; n++) {
                    int qc = 32 * warp + 8 * n + 2 * c;
                    *(uint2*)&sp[kl][qc]     = make_uint2(f2tf32(acc[mt][n][0]), f2tf32(acc[mt][n][1]));
                    *(uint2*)&sp[kl + 8][qc] = make_uint2(f2tf32(acc[mt][n][2]), f2tf32(acc[mt][n][3]));
                }
            }
            __syncwarp();

            // ---- Phase 2: O^T += V^T @ P^T ----
#pragma unroll
            for (int ks = 0; ks < 4; ks++) {
                unsigned bb[4][2];
#pragma unroll
                for (int n = 0; n < 4; n++) {
                    bb[n][0] = sp[8 * ks + c][32 * warp + 8 * n + g];
                    bb[n][1] = sp[8 * ks + c + 4][32 * warp + 8 * n + g];
                }
                int kg = 32 * half + 8 * ks;
#pragma unroll
                for (int m2 = 0; m2 < 2; m2++) {
                    unsigned a[4];
                    a[0] = sv[16 * m2 + g][kg + c];
                    a[1] = sv[16 * m2 + g + 8][kg + c];
                    a[2] = sv[16 * m2 + g][kg + c + 4];
                    a[3] = sv[16 * m2 + g + 8][kg + c + 4];
#pragma unroll
                    for (int n = 0; n < 4; n++)
                        mma_tf32(O[m2][n], a, bb[n]);
                }
            }
        }
        __syncthreads();   // before next iteration's prefetch overwrites buf[it&1]
    }

    // ---- Epilogue ----
    float inv[4][2];
#pragma unroll
    for (int n = 0; n < 4; n++)
#pragma unroll
        for (int p = 0; p < 2; p++) {
            float l = lrun[n][p];
            l += __shfl_xor_sync(0xffffffffu, l, 4);
            l += __shfl_xor_sync(0xffffffffu, l, 8);
            l += __shfl_xor_sync(0xffffffffu, l, 16);
            inv[n][p] = 1.f / l;
        }

    float* op = out + ((size_t)b * 128 + h * 32) * NPIX;
#pragma unroll
    for (int m2 = 0; m2 < 2; m2++)
#pragma unroll
        for (int n = 0; n < 4; n++) {
            int q0 = qw + 8 * n + 2 * c;
            op[(size_t)(16 * m2 + g) * NPIX + q0]         = O[m2][n][0] * inv[n][0];
            op[(size_t)(16 * m2 + g) * NPIX + q0 + 1]     = O[m2][n][1] * inv[n][1];
            op[(size_t)(16 * m2 + g + 8) * NPIX + q0]     = O[m2][n][2] * inv[n][0];
            op[(size_t)(16 * m2 + g + 8) * NPIX + q0 + 1] = O[m2][n][3] * inv[n][1];
        }
}

// ---------------------------------------------------------------------------
extern "C" void kernel_launch(void* const* d_in, const int* in_sizes, int n_in,
                              void* d_out, int out_size)
{
    const float* x     = (const float*)d_in[0];
    const float* w_qkv = (const float*)d_in[1];
    const float* w_out = (const float*)d_in[2];
    const float* b_out = (const float*)d_in[3];
    float* out = (float*)d_out;

    static float *qkv = nullptr, *ao = nullptr;
    if (!qkv) {
        cudaGetSymbolAddress((void**)&qkv, g_qkv);
        cudaGetSymbolAddress((void**)&ao,  g_ao);
        cudaFuncSetAttribute(flash_tc_kernel,
                             cudaFuncAttributeMaxDynamicSharedMemorySize, SMEMB);
    }

    dim3 g1(NPIX / 64, 384 / 64, NB);
    gemm_kernel<<<g1, 256>>>(w_qkv, x, qkv, nullptr, 384, NPIX, CIN);

    l2norm_kernel<<<(NB * 3 * NHEADS * NPIX) / 256, 256>>>(qkv);

    dim3 g3(NPIX / 128, NB * NHEADS);
    flash_tc_kernel<<<g3, 128, SMEMB>>>(qkv, ao);

    dim3 g4(NPIX / 64, 256 / 64, NB);
    gemm_kernel<<<g4, 256>>>(w_out, ao, out, b_out, 256, NPIX, HID);
}

// round 7
// speedup vs baseline: 4.8876x; 1.4470x over previous
#include <cuda_runtime.h>
#include <cuda_fp16.h>
#include <cstdint>
#include <math.h>

#define NPIX 4096
#define NB 4
#define NHEADS 4
#define CIN 256
#define HID 128

__device__ float g_qkv[(size_t)NB * 3 * HID * NPIX];
__device__ float g_ao[(size_t)NB * HID * NPIX];
__device__ unsigned g_qh[(size_t)16 * NPIX * 16];        // [bh][pix][16 h2-pairs]
__device__ unsigned g_kh[(size_t)16 * NPIX * 16];
__device__ unsigned g_vh[(size_t)16 * 32 * (NPIX / 2)];  // [bh][d][2048 h2-pairs]

// ---------------------------------------------------------------------------
// Tiled SIMT GEMM: Y[z] = W (MxK) @ X[z] (KxN) (+ bias)
// ---------------------------------------------------------------------------
__global__ __launch_bounds__(256) void gemm_kernel(
    const float* __restrict__ W, const float* __restrict__ X,
    float* __restrict__ Y, const float* __restrict__ bias,
    int M, int N, int K)
{
    X += (size_t)blockIdx.z * (size_t)K * N;
    Y += (size_t)blockIdx.z * (size_t)M * N;
    __shared__ float Ws[16][65];
    __shared__ float Xs[16][64];
    const int tx = threadIdx.x & 15, ty = threadIdx.x >> 4;
    const int row0 = blockIdx.y * 64, col0 = blockIdx.x * 64;
    float acc[4][4];
#pragma unroll
    for (int i = 0; i < 4; i++)
#pragma unroll
        for (int j = 0; j < 4; j++) acc[i][j] = 0.f;
    for (int kk = 0; kk < K; kk += 16) {
#pragma unroll
        for (int i = 0; i < 4; i++) {
            int idx = threadIdx.x + i * 256;
            int m = idx >> 4, k = idx & 15;
            Ws[k][m] = W[(size_t)(row0 + m) * K + kk + k];
            int k2 = idx >> 6, n = idx & 63;
            Xs[k2][n] = X[(size_t)(kk + k2) * N + col0 + n];
        }
        __syncthreads();
#pragma unroll
        for (int k = 0; k < 16; k++) {
            float wr[4], xr[4];
#pragma unroll
            for (int i = 0; i < 4; i++) wr[i] = Ws[k][ty * 4 + i];
#pragma unroll
            for (int j = 0; j < 4; j++) xr[j] = Xs[k][tx * 4 + j];
#pragma unroll
            for (int i = 0; i < 4; i++)
#pragma unroll
                for (int j = 0; j < 4; j++) acc[i][j] = fmaf(wr[i], xr[j], acc[i][j]);
        }
        __syncthreads();
    }
#pragma unroll
    for (int i = 0; i < 4; i++) {
        float bv = bias ? bias[row0 + ty * 4 + i] : 0.f;
#pragma unroll
        for (int j = 0; j < 4; j++)
            Y[(size_t)(row0 + ty * 4 + i) * N + col0 + tx * 4 + j] = acc[i][j] + bv;
    }
}

__device__ __forceinline__ float ex2(float x) {
    float y; asm("ex2.approx.ftz.f32 %0, %1;" : "=f"(y) : "f"(x)); return y;
}
__device__ __forceinline__ unsigned packh2(float hi, float lo) {
    unsigned r; asm("cvt.rn.f16x2.f32 %0, %1, %2;" : "=r"(r) : "f"(hi), "f"(lo)); return r;
}
__device__ __forceinline__ unsigned movm(unsigned x) {
    unsigned r; asm("movmatrix.sync.aligned.m8n8.trans.b16 %0, %1;" : "=r"(r) : "r"(x)); return r;
}
__device__ __forceinline__ void mma_f16(float* d, unsigned a0, unsigned a1,
                                        unsigned a2, unsigned a3, unsigned b0, unsigned b1) {
    asm volatile("mma.sync.aligned.m16n8k16.row.col.f32.f16.f16.f32 "
                 "{%0,%1,%2,%3}, {%4,%5,%6,%7}, {%8,%9}, {%0,%1,%2,%3};"
                 : "+f"(d[0]), "+f"(d[1]), "+f"(d[2]), "+f"(d[3])
                 : "r"(a0), "r"(a1), "r"(a2), "r"(a3), "r"(b0), "r"(b1));
}
__device__ __forceinline__ void cpasync16(unsigned dst, const void* src) {
    asm volatile("cp.async.ca.shared.global [%0], [%1], 16;" :: "r"(dst), "l"(src));
}

// ---------------------------------------------------------------------------
// L2-normalize q,k; q scaled by 10*log2(e); write fp16 TRANSPOSED [pix][32d].
// ---------------------------------------------------------------------------
__global__ __launch_bounds__(256) void l2norm_kernel(
    const float* __restrict__ qkv, unsigned* __restrict__ qh, unsigned* __restrict__ kh)
{
    int idx = blockIdx.x * 256 + threadIdx.x;   // 4*2*4*4096
    int pix = idx & (NPIX - 1);
    int t = idx >> 12;
    int head = t & 3, sel = (t >> 2) & 1, b = t >> 3;
    const float* p = qkv + ((size_t)b * 384 + sel * 128 + head * 32) * NPIX + pix;
    float v[32]; float ss = 0.f;
#pragma unroll
    for (int d = 0; d < 32; d++) { v[d] = p[(size_t)d * NPIX]; ss = fmaf(v[d], v[d], ss); }
    float inv = 1.f / fmaxf(sqrtf(ss), 1e-12f);
    if (sel == 0) inv *= 14.426950408889634f;   // 10 * log2(e)
    unsigned o[16];
#pragma unroll
    for (int j = 0; j < 16; j++) o[j] = packh2(v[2 * j + 1] * inv, v[2 * j] * inv);
    uint4* dst = (uint4*)((sel ? kh : qh) + ((size_t)(b * 4 + head) * NPIX + pix) * 16);
#pragma unroll
    for (int j = 0; j < 4; j++) dst[j] = make_uint4(o[4*j], o[4*j+1], o[4*j+2], o[4*j+3]);
}

// v -> fp16 [bh][d][pix]
__global__ __launch_bounds__(256) void vcvt_kernel(
    const float* __restrict__ qkv, unsigned* __restrict__ vh)
{
    int idx = blockIdx.x * 256 + threadIdx.x;    // 16*32*512
    int px8 = idx & 511;
    int t = idx >> 9;
    int d = t & 31, bh = t >> 5, b = bh >> 2, h = bh & 3;
    const float* src = qkv + ((size_t)b * 384 + 256 + h * 32 + d) * NPIX + px8 * 8;
    unsigned o[4];
#pragma unroll
    for (int j = 0; j < 4; j++) o[j] = packh2(src[2 * j + 1], src[2 * j]);
    *(uint4*)(vh + ((size_t)bh * 32 + d) * (NPIX / 2) + px8 * 4) =
        make_uint4(o[0], o[1], o[2], o[3]);
}

// ---------------------------------------------------------------------------
// fp16 flash attention: m16n8k16 mma, P transposed in registers via movmatrix
// (no P smem). 4 warps x 32 q; 64-key tiles, double-buffered K/V cp.async.
// ---------------------------------------------------------------------------
#define SKH 20                       // K row stride (u32 pairs): banks 20g+c distinct
#define SVH 36                       // V row stride: banks 4g+c distinct
#define STAGE (64 * SKH + 32 * SVH)  // 2432 u32 per stage

__global__ __launch_bounds__(128, 3) void flash_h_kernel(
    const unsigned* __restrict__ qh, const unsigned* __restrict__ kh,
    const unsigned* __restrict__ vh, float* __restrict__ out)
{
    __shared__ unsigned sm[2 * STAGE];
    __shared__ float lw[4][32];

    const int tid = threadIdx.x, lane = tid & 31, warp = tid >> 5;
    const int g = lane >> 2, c = lane & 3;
    const int bh = blockIdx.y, b = bh >> 2, h = bh & 3;
    const int qw = blockIdx.x * 128 + warp * 32;

    const unsigned* qbh = qh + (size_t)bh * NPIX * 16;
    const unsigned* kbh = kh + (size_t)bh * NPIX * 16;
    const unsigned* vbh = vh + (size_t)bh * 32 * (NPIX / 2);
    const unsigned sbase = (unsigned)__cvta_generic_to_shared(sm);

    // Persistent Q B-frags: bq[ks][n] = {(d=16ks+2c, q=8n+g), (d=16ks+8+2c, q)}
    unsigned bq[2][4][2];
#pragma unroll
    for (int n = 0; n < 4; n++) {
        const unsigned* qq = qbh + (size_t)(qw + 8 * n + g) * 16;
#pragma unroll
        for (int ks = 0; ks < 2; ks++) {
            bq[ks][n][0] = qq[8 * ks + c];
            bq[ks][n][1] = qq[8 * ks + c + 4];
        }
    }

    float O[2][4][4];
    float lrun[4][2];
#pragma unroll
    for (int mq = 0; mq < 2; mq++)
#pragma unroll
        for (int nd = 0; nd < 4; nd++)
#pragma unroll
            for (int r = 0; r < 4; r++) O[mq][nd][r] = 0.f;
#pragma unroll
    for (int n = 0; n < 4; n++) { lrun[n][0] = 0.f; lrun[n][1] = 0.f; }

    auto fill = [&](int it, int s) {
        unsigned base = sbase + (unsigned)(s * STAGE) * 4u;
        int j0 = it * 64;
#pragma unroll
        for (int r = 0; r < 2; r++) {
            int id = tid + r * 128;
            int row = id >> 2, j = id & 3;
            cpasync16(base + (unsigned)(row * SKH + 4 * j) * 4u,
                      kbh + (size_t)(j0 + row) * 16 + 4 * j);
            int d = id >> 3, jj = id & 7;
            cpasync16(base + (unsigned)(64 * SKH + d * SVH + 4 * jj) * 4u,
                      vbh + (size_t)d * (NPIX / 2) + j0 / 2 + 4 * jj);
        }
        asm volatile("cp.async.commit_group;");
    };

    fill(0, 0);

    for (int it = 0; it < 64; ++it) {
        if (it < 63) {
            fill(it + 1, (it + 1) & 1);
            asm volatile("cp.async.wait_group 1;");
        } else {
            asm volatile("cp.async.wait_group 0;");
        }
        __syncthreads();

        const unsigned* skh = sm + (it & 1) * STAGE;
        const unsigned* svh = skh + 64 * SKH;

#pragma unroll
        for (int m = 0; m < 4; m++) {
            // Phase 1: S^T (16 keys x 32 q): A=K rows 16m..16m+15, B=Q frags
            float acc[4][4];
#pragma unroll
            for (int n = 0; n < 4; n++)
#pragma unroll
                for (int r = 0; r < 4; r++) acc[n][r] = 0.f;
#pragma unroll
            for (int ks = 0; ks < 2; ks++) {
                unsigned a0 = skh[(16 * m + g) * SKH + 8 * ks + c];
                unsigned a1 = skh[(16 * m + 8 + g) * SKH + 8 * ks + c];
                unsigned a2 = skh[(16 * m + g) * SKH + 8 * ks + c + 4];
                unsigned a3 = skh[(16 * m + 8 + g) * SKH + 8 * ks + c + 4];
#pragma unroll
                for (int n = 0; n < 4; n++)
                    mma_f16(acc[n], a0, a1, a2, a3, bq[ks][n][0], bq[ks][n][1]);
            }
            // exp2, l, pack to fp16, transpose in registers
            unsigned t0[4], t1[4];
#pragma unroll
            for (int n = 0; n < 4; n++) {
                float e0 = ex2(acc[n][0]), e1 = ex2(acc[n][1]);
                float e2 = ex2(acc[n][2]), e3 = ex2(acc[n][3]);
                lrun[n][0] += e0 + e2;
                lrun[n][1] += e1 + e3;
                t0[n] = movm(packh2(e1, e0));   // (q=8n+g, keys 16m+2c,2c+1)
                t1[n] = movm(packh2(e3, e2));   // (q=8n+g, keys 16m+8+2c,2c+1)
            }
            // Phase 2: O[q][d] += P[q][key-chunk m] @ V[key][d]
#pragma unroll
            for (int nd = 0; nd < 4; nd++) {
                unsigned b0 = svh[(8 * nd + g) * SVH + 8 * m + c];
                unsigned b1 = svh[(8 * nd + g) * SVH + 8 * m + c + 4];
                mma_f16(O[0][nd], t0[0], t0[1], t1[0], t1[1], b0, b1);
                mma_f16(O[1][nd], t0[2], t0[3], t1[2], t1[3], b0, b1);
            }
        }
        __syncthreads();
    }

    // ---- Epilogue: l full-reduce, exchange to q=g rows, normalize, store ----
#pragma unroll
    for (int n = 0; n < 4; n++)
#pragma unroll
        for (int p = 0; p < 2; p++) {
            float l = lrun[n][p];
            l += __shfl_xor_sync(0xffffffffu, l, 4);
            l += __shfl_xor_sync(0xffffffffu, l, 8);
            l += __shfl_xor_sync(0xffffffffu, l, 16);
            lrun[n][p] = l;
        }
    if (g == 0) {
#pragma unroll
        for (int n = 0; n < 4; n++) {
            lw[warp][8 * n + 2 * c]     = lrun[n][0];
            lw[warp][8 * n + 2 * c + 1] = lrun[n][1];
        }
    }
    __syncwarp();
    float linv[2][2];
#pragma unroll
    for (int mq = 0; mq < 2; mq++) {
        linv[mq][0] = 1.f / lw[warp][16 * mq + g];
        linv[mq][1] = 1.f / lw[warp][16 * mq + 8 + g];
    }

    float* op = out + ((size_t)b * 128 + h * 32) * NPIX;
#pragma unroll
    for (int mq = 0; mq < 2; mq++)
#pragma unroll
        for (int nd = 0; nd < 4; nd++) {
            int q0 = qw + 16 * mq + g;
            int dd = 8 * nd + 2 * c;
            op[(size_t)dd * NPIX + q0]           = O[mq][nd][0] * linv[mq][0];
            op[(size_t)(dd + 1) * NPIX + q0]     = O[mq][nd][1] * linv[mq][0];
            op[(size_t)dd * NPIX + q0 + 8]       = O[mq][nd][2] * linv[mq][1];
            op[(size_t)(dd + 1) * NPIX + q0 + 8] = O[mq][nd][3] * linv[mq][1];
        }
}

// ---------------------------------------------------------------------------
extern "C" void kernel_launch(void* const* d_in, const int* in_sizes, int n_in,
                              void* d_out, int out_size)
{
    const float* x     = (const float*)d_in[0];
    const float* w_qkv = (const float*)d_in[1];
    const float* w_out = (const float*)d_in[2];
    const float* b_out = (const float*)d_in[3];
    float* out = (float*)d_out;

    static float *qkv = nullptr, *ao = nullptr;
    static unsigned *qh = nullptr, *kh = nullptr, *vh = nullptr;
    if (!qkv) {
        cudaGetSymbolAddress((void**)&qkv, g_qkv);
        cudaGetSymbolAddress((void**)&ao,  g_ao);
        cudaGetSymbolAddress((void**)&qh,  g_qh);
        cudaGetSymbolAddress((void**)&kh,  g_kh);
        cudaGetSymbolAddress((void**)&vh,  g_vh);
    }

    dim3 g1(NPIX / 64, 384 / 64, NB);
    gemm_kernel<<<g1, 256>>>(w_qkv, x, qkv, nullptr, 384, NPIX, CIN);

    l2norm_kernel<<<(NB * 2 * NHEADS * NPIX) / 256, 256>>>(qkv, qh, kh);
    vcvt_kernel<<<(16 * 32 * 512) / 256, 256>>>(qkv, vh);

    dim3 g3(NPIX / 128, 16);
    flash_h_kernel<<<g3, 128>>>(qh, kh, vh, ao);

    dim3 g4(NPIX / 64, 256 / 64, NB);
    gemm_kernel<<<g4, 256>>>(w_out, ao, out, b_out, 256, NPIX, HID);
}

// round 8
// speedup vs baseline: 5.5779x; 1.1412x over previous
#include <cuda_runtime.h>
#include <cuda_fp16.h>
#include <cstdint>
#include <math.h>

#define NPIX 4096
#define NB 4
#define NHEADS 4
#define CIN 256
#define HID 128

__device__ float g_qkv[(size_t)NB * 3 * HID * NPIX];
__device__ float g_ao[(size_t)NB * HID * NPIX];
__device__ unsigned g_qh[(size_t)16 * NPIX * 16];
__device__ unsigned g_kh[(size_t)16 * NPIX * 16];
__device__ unsigned g_vh[(size_t)16 * 32 * (NPIX / 2)];
__device__ float g_wt1[256 * 384];   // w_qkv^T  [K][M]
__device__ float g_wt2[128 * 256];   // w_out^T  [K][M]

__device__ __forceinline__ void cpasync16(unsigned dst, const void* src) {
    asm volatile("cp.async.ca.shared.global [%0], [%1], 16;" :: "r"(dst), "l"(src));
}

// ---------------------------------------------------------------------------
// Tiled transpose: out[k][m] = in[m][k]   (M, K multiples of 32)
// ---------------------------------------------------------------------------
__global__ void transpose_kernel(const float* __restrict__ in, float* __restrict__ out,
                                 int M, int K)
{
    __shared__ float t[32][33];
    int bx = blockIdx.x * 32, by = blockIdx.y * 32;
#pragma unroll
    for (int i = 0; i < 32; i += 8)
        t[threadIdx.y + i][threadIdx.x] = in[(size_t)(by + threadIdx.y + i) * K + bx + threadIdx.x];
    __syncthreads();
#pragma unroll
    for (int i = 0; i < 32; i += 8)
        out[(size_t)(bx + threadIdx.y + i) * M + by + threadIdx.x] = t[threadIdx.x][threadIdx.y + i];
}

// ---------------------------------------------------------------------------
// fp32 SGEMM: Y[z] = W @ X[z] (+bias), W given TRANSPOSED as Wt[K][M].
// BM=128, BN=64, BK=16; 128 threads, 8x8 register tile; cp.async double-buffer.
// ---------------------------------------------------------------------------
__global__ __launch_bounds__(128) void gemm_tn(
    const float* __restrict__ Wt, const float* __restrict__ X,
    float* __restrict__ Y, const float* __restrict__ bias,
    int M, int N, int K)
{
    X += (size_t)blockIdx.z * (size_t)K * N;
    Y += (size_t)blockIdx.z * (size_t)M * N;

    __shared__ float Ws[2][16][128];
    __shared__ float Xs[2][16][64];

    const int tid = threadIdx.x;
    const int tm = tid >> 3, tn = tid & 7;
    const int row0 = blockIdx.y * 128, col0 = blockIdx.x * 64;
    const unsigned wsb = (unsigned)__cvta_generic_to_shared(&Ws[0][0][0]);
    const unsigned xsb = (unsigned)__cvta_generic_to_shared(&Xs[0][0][0]);

    float acc[8][8];
#pragma unroll
    for (int i = 0; i < 8; i++)
#pragma unroll
        for (int j = 0; j < 8; j++) acc[i][j] = 0.f;

    auto fill = [&](int kk, int s) {
#pragma unroll
        for (int i = 0; i < 4; i++) {
            int idx = tid + i * 128;              // 0..511
            int k = idx >> 5, m4 = idx & 31;
            cpasync16(wsb + (unsigned)((s * 16 + k) * 128 + m4 * 4) * 4u,
                      Wt + (size_t)(kk + k) * M + row0 + m4 * 4);
        }
#pragma unroll
        for (int i = 0; i < 2; i++) {
            int idx = tid + i * 128;              // 0..255
            int k = idx >> 4, n4 = idx & 15;
            cpasync16(xsb + (unsigned)((s * 16 + k) * 64 + n4 * 4) * 4u,
                      X + (size_t)(kk + k) * N + col0 + n4 * 4);
        }
        asm volatile("cp.async.commit_group;");
    };

    const int nchunk = K >> 4;
    fill(0, 0);
    for (int c = 0; c < nchunk; ++c) {
        if (c + 1 < nchunk) {
            fill((c + 1) << 4, (c + 1) & 1);
            asm volatile("cp.async.wait_group 1;");
        } else {
            asm volatile("cp.async.wait_group 0;");
        }
        __syncthreads();
        const int s = c & 1;
#pragma unroll
        for (int k = 0; k < 16; k++) {
            float4 w0 = *(const float4*)&Ws[s][k][tm * 4];
            float4 w1 = *(const float4*)&Ws[s][k][64 + tm * 4];
            float4 x0 = *(const float4*)&Xs[s][k][tn * 4];
            float4 x1 = *(const float4*)&Xs[s][k][32 + tn * 4];
            float wr[8] = {w0.x, w0.y, w0.z, w0.w, w1.x, w1.y, w1.z, w1.w};
            float xr[8] = {x0.x, x0.y, x0.z, x0.w, x1.x, x1.y, x1.z, x1.w};
#pragma unroll
            for (int i = 0; i < 8; i++)
#pragma unroll
                for (int j = 0; j < 8; j++)
                    acc[i][j] = fmaf(wr[i], xr[j], acc[i][j]);
        }
        __syncthreads();
    }

    // epilogue
#pragma unroll
    for (int ih = 0; ih < 2; ih++)
#pragma unroll
        for (int i = 0; i < 4; i++) {
            int row = row0 + ih * 64 + tm * 4 + i;
            float bv = bias ? bias[row] : 0.f;
            float4 o0 = make_float4(acc[ih*4+i][0] + bv, acc[ih*4+i][1] + bv,
                                    acc[ih*4+i][2] + bv, acc[ih*4+i][3] + bv);
            float4 o1 = make_float4(acc[ih*4+i][4] + bv, acc[ih*4+i][5] + bv,
                                    acc[ih*4+i][6] + bv, acc[ih*4+i][7] + bv);
            *(float4*)&Y[(size_t)row * N + col0 + tn * 4]      = o0;
            *(float4*)&Y[(size_t)row * N + col0 + 32 + tn * 4] = o1;
        }
}

__device__ __forceinline__ float ex2(float x) {
    float y; asm("ex2.approx.ftz.f32 %0, %1;" : "=f"(y) : "f"(x)); return y;
}
__device__ __forceinline__ unsigned packh2(float hi, float lo) {
    unsigned r; asm("cvt.rn.f16x2.f32 %0, %1, %2;" : "=r"(r) : "f"(hi), "f"(lo)); return r;
}
__device__ __forceinline__ unsigned movm(unsigned x) {
    unsigned r; asm("movmatrix.sync.aligned.m8n8.trans.b16 %0, %1;" : "=r"(r) : "r"(x)); return r;
}
__device__ __forceinline__ void mma_f16(float* d, unsigned a0, unsigned a1,
                                        unsigned a2, unsigned a3, unsigned b0, unsigned b1) {
    asm volatile("mma.sync.aligned.m16n8k16.row.col.f32.f16.f16.f32 "
                 "{%0,%1,%2,%3}, {%4,%5,%6,%7}, {%8,%9}, {%0,%1,%2,%3};"
                 : "+f"(d[0]), "+f"(d[1]), "+f"(d[2]), "+f"(d[3])
                 : "r"(a0), "r"(a1), "r"(a2), "r"(a3), "r"(b0), "r"(b1));
}

// ---------------------------------------------------------------------------
// L2-normalize q,k; q scaled 10*log2(e); fp16 transposed [pix][32d].
// ---------------------------------------------------------------------------
__global__ __launch_bounds__(256) void l2norm_kernel(
    const float* __restrict__ qkv, unsigned* __restrict__ qh, unsigned* __restrict__ kh)
{
    int idx = blockIdx.x * 256 + threadIdx.x;
    int pix = idx & (NPIX - 1);
    int t = idx >> 12;
    int head = t & 3, sel = (t >> 2) & 1, b = t >> 3;
    const float* p = qkv + ((size_t)b * 384 + sel * 128 + head * 32) * NPIX + pix;
    float v[32]; float ss = 0.f;
#pragma unroll
    for (int d = 0; d < 32; d++) { v[d] = p[(size_t)d * NPIX]; ss = fmaf(v[d], v[d], ss); }
    float inv = 1.f / fmaxf(sqrtf(ss), 1e-12f);
    if (sel == 0) inv *= 14.426950408889634f;
    unsigned o[16];
#pragma unroll
    for (int j = 0; j < 16; j++) o[j] = packh2(v[2 * j + 1] * inv, v[2 * j] * inv);
    uint4* dst = (uint4*)((sel ? kh : qh) + ((size_t)(b * 4 + head) * NPIX + pix) * 16);
#pragma unroll
    for (int j = 0; j < 4; j++) dst[j] = make_uint4(o[4*j], o[4*j+1], o[4*j+2], o[4*j+3]);
}

__global__ __launch_bounds__(256) void vcvt_kernel(
    const float* __restrict__ qkv, unsigned* __restrict__ vh)
{
    int idx = blockIdx.x * 256 + threadIdx.x;
    int px8 = idx & 511;
    int t = idx >> 9;
    int d = t & 31, bh = t >> 5, b = bh >> 2, h = bh & 3;
    const float* src = qkv + ((size_t)b * 384 + 256 + h * 32 + d) * NPIX + px8 * 8;
    unsigned o[4];
#pragma unroll
    for (int j = 0; j < 4; j++) o[j] = packh2(src[2 * j + 1], src[2 * j]);
    *(uint4*)(vh + ((size_t)bh * 32 + d) * (NPIX / 2) + px8 * 4) =
        make_uint4(o[0], o[1], o[2], o[3]);
}

// ---------------------------------------------------------------------------
// fp16 flash attention (m16n8k16, movmatrix P-transpose, double-buffered K/V).
// __launch_bounds__(128,4): force regs<=128 -> 4 CTAs/SM -> single wave.
// ---------------------------------------------------------------------------
#define SKH 20
#define SVH 36
#define STAGE (64 * SKH + 32 * SVH)

__global__ __launch_bounds__(128, 4) void flash_h_kernel(
    const unsigned* __restrict__ qh, const unsigned* __restrict__ kh,
    const unsigned* __restrict__ vh, float* __restrict__ out)
{
    __shared__ unsigned sm[2 * STAGE];
    __shared__ float lw[4][32];

    const int tid = threadIdx.x, lane = tid & 31, warp = tid >> 5;
    const int g = lane >> 2, c = lane & 3;
    const int bh = blockIdx.y, b = bh >> 2, h = bh & 3;
    const int qw = blockIdx.x * 128 + warp * 32;

    const unsigned* qbh = qh + (size_t)bh * NPIX * 16;
    const unsigned* kbh = kh + (size_t)bh * NPIX * 16;
    const unsigned* vbh = vh + (size_t)bh * 32 * (NPIX / 2);
    const unsigned sbase = (unsigned)__cvta_generic_to_shared(sm);

    unsigned bq[2][4][2];
#pragma unroll
    for (int n = 0; n < 4; n++) {
        const unsigned* qq = qbh + (size_t)(qw + 8 * n + g) * 16;
#pragma unroll
        for (int ks = 0; ks < 2; ks++) {
            bq[ks][n][0] = qq[8 * ks + c];
            bq[ks][n][1] = qq[8 * ks + c + 4];
        }
    }

    float O[2][4][4];
    float lrun[4][2];
#pragma unroll
    for (int mq = 0; mq < 2; mq++)
#pragma unroll
        for (int nd = 0; nd < 4; nd++)
#pragma unroll
            for (int r = 0; r < 4; r++) O[mq][nd][r] = 0.f;
#pragma unroll
    for (int n = 0; n < 4; n++) { lrun[n][0] = 0.f; lrun[n][1] = 0.f; }

    auto fill = [&](int it, int s) {
        unsigned base = sbase + (unsigned)(s * STAGE) * 4u;
        int j0 = it * 64;
#pragma unroll
        for (int r = 0; r < 2; r++) {
            int id = tid + r * 128;
            int row = id >> 2, j = id & 3;
            cpasync16(base + (unsigned)(row * SKH + 4 * j) * 4u,
                      kbh + (size_t)(j0 + row) * 16 + 4 * j);
            int d = id >> 3, jj = id & 7;
            cpasync16(base + (unsigned)(64 * SKH + d * SVH + 4 * jj) * 4u,
                      vbh + (size_t)d * (NPIX / 2) + j0 / 2 + 4 * jj);
        }
        asm volatile("cp.async.commit_group;");
    };

    fill(0, 0);

    for (int it = 0; it < 64; ++it) {
        if (it < 63) {
            fill(it + 1, (it + 1) & 1);
            asm volatile("cp.async.wait_group 1;");
        } else {
            asm volatile("cp.async.wait_group 0;");
        }
        __syncthreads();

        const unsigned* skh = sm + (it & 1) * STAGE;
        const unsigned* svh = skh + 64 * SKH;

#pragma unroll
        for (int m = 0; m < 4; m++) {
            float acc[4][4];
#pragma unroll
            for (int n = 0; n < 4; n++)
#pragma unroll
                for (int r = 0; r < 4; r++) acc[n][r] = 0.f;
#pragma unroll
            for (int ks = 0; ks < 2; ks++) {
                unsigned a0 = skh[(16 * m + g) * SKH + 8 * ks + c];
                unsigned a1 = skh[(16 * m + 8 + g) * SKH + 8 * ks + c];
                unsigned a2 = skh[(16 * m + g) * SKH + 8 * ks + c + 4];
                unsigned a3 = skh[(16 * m + 8 + g) * SKH + 8 * ks + c + 4];
#pragma unroll
                for (int n = 0; n < 4; n++)
                    mma_f16(acc[n], a0, a1, a2, a3, bq[ks][n][0], bq[ks][n][1]);
            }
            unsigned t0[4], t1[4];
#pragma unroll
            for (int n = 0; n < 4; n++) {
                float e0 = ex2(acc[n][0]), e1 = ex2(acc[n][1]);
                float e2 = ex2(acc[n][2]), e3 = ex2(acc[n][3]);
                lrun[n][0] += e0 + e2;
                lrun[n][1] += e1 + e3;
                t0[n] = movm(packh2(e1, e0));
                t1[n] = movm(packh2(e3, e2));
            }
#pragma unroll
            for (int nd = 0; nd < 4; nd++) {
                unsigned b0 = svh[(8 * nd + g) * SVH + 8 * m + c];
                unsigned b1 = svh[(8 * nd + g) * SVH + 8 * m + c + 4];
                mma_f16(O[0][nd], t0[0], t0[1], t1[0], t1[1], b0, b1);
                mma_f16(O[1][nd], t0[2], t0[3], t1[2], t1[3], b0, b1);
            }
        }
        __syncthreads();
    }

#pragma unroll
    for (int n = 0; n < 4; n++)
#pragma unroll
        for (int p = 0; p < 2; p++) {
            float l = lrun[n][p];
            l += __shfl_xor_sync(0xffffffffu, l, 4);
            l += __shfl_xor_sync(0xffffffffu, l, 8);
            l += __shfl_xor_sync(0xffffffffu, l, 16);
            lrun[n][p] = l;
        }
    if (g == 0) {
#pragma unroll
        for (int n = 0; n < 4; n++) {
            lw[warp][8 * n + 2 * c]     = lrun[n][0];
            lw[warp][8 * n + 2 * c + 1] = lrun[n][1];
        }
    }
    __syncwarp();
    float linv[2][2];
#pragma unroll
    for (int mq = 0; mq < 2; mq++) {
        linv[mq][0] = 1.f / lw[warp][16 * mq + g];
        linv[mq][1] = 1.f / lw[warp][16 * mq + 8 + g];
    }

    float* op = out + ((size_t)b * 128 + h * 32) * NPIX;
#pragma unroll
    for (int mq = 0; mq < 2; mq++)
#pragma unroll
        for (int nd = 0; nd < 4; nd++) {
            int q0 = qw + 16 * mq + g;
            int dd = 8 * nd + 2 * c;
            op[(size_t)dd * NPIX + q0]           = O[mq][nd][0] * linv[mq][0];
            op[(size_t)(dd + 1) * NPIX + q0]     = O[mq][nd][1] * linv[mq][0];
            op[(size_t)dd * NPIX + q0 + 8]       = O[mq][nd][2] * linv[mq][1];
            op[(size_t)(dd + 1) * NPIX + q0 + 8] = O[mq][nd][3] * linv[mq][1];
        }
}

// ---------------------------------------------------------------------------
extern "C" void kernel_launch(void* const* d_in, const int* in_sizes, int n_in,
                              void* d_out, int out_size)
{
    const float* x     = (const float*)d_in[0];
    const float* w_qkv = (const float*)d_in[1];
    const float* w_out = (const float*)d_in[2];
    const float* b_out = (const float*)d_in[3];
    float* out = (float*)d_out;

    static float *qkv = nullptr, *ao = nullptr, *wt1 = nullptr, *wt2 = nullptr;
    static unsigned *qh = nullptr, *kh = nullptr, *vh = nullptr;
    if (!qkv) {
        cudaGetSymbolAddress((void**)&qkv, g_qkv);
        cudaGetSymbolAddress((void**)&ao,  g_ao);
        cudaGetSymbolAddress((void**)&qh,  g_qh);
        cudaGetSymbolAddress((void**)&kh,  g_kh);
        cudaGetSymbolAddress((void**)&vh,  g_vh);
        cudaGetSymbolAddress((void**)&wt1, g_wt1);
        cudaGetSymbolAddress((void**)&wt2, g_wt2);
    }

    // transpose weights: wt[k][m] = w[m][k]
    dim3 tb(32, 8);
    transpose_kernel<<<dim3(256 / 32, 384 / 32), tb>>>(w_qkv, wt1, 384, 256);
    transpose_kernel<<<dim3(128 / 32, 256 / 32), tb>>>(w_out, wt2, 256, 128);

    dim3 g1(NPIX / 64, 384 / 128, NB);
    gemm_tn<<<g1, 128>>>(wt1, x, qkv, nullptr, 384, NPIX, CIN);

    l2norm_kernel<<<(NB * 2 * NHEADS * NPIX) / 256, 256>>>(qkv, qh, kh);
    vcvt_kernel<<<(16 * 32 * 512) / 256, 256>>>(qkv, vh);

    dim3 g3(NPIX / 128, 16);
    flash_h_kernel<<<g3, 128>>>(qh, kh, vh, ao);

    dim3 g4(NPIX / 64, 256 / 128, NB);
    gemm_tn<<<g4, 128>>>(wt2, ao, out, b_out, 256, NPIX, HID);
}

// round 9
// speedup vs baseline: 5.6133x; 1.0063x over previous
#include <cuda_runtime.h>
#include <cuda_fp16.h>
#include <cstdint>
#include <math.h>

#define NPIX 4096
#define NB 4
#define NHEADS 4
#define CIN 256
#define HID 128

__device__ float g_ao[(size_t)NB * HID * NPIX];
__device__ unsigned g_qh[(size_t)16 * NPIX * 16];        // [bh][pix][16 d-pairs]
__device__ unsigned g_kh[(size_t)16 * NPIX * 16];
__device__ unsigned g_vh[(size_t)16 * 32 * (NPIX / 2)];  // [bh][d][pix-pairs]
__device__ float g_wt1[256 * 384];
__device__ float g_wt2[128 * 256];

__device__ __forceinline__ void cpasync16(unsigned dst, const void* src) {
    asm volatile("cp.async.ca.shared.global [%0], [%1], 16;" :: "r"(dst), "l"(src));
}
__device__ __forceinline__ float ex2(float x) {
    float y; asm("ex2.approx.ftz.f32 %0, %1;" : "=f"(y) : "f"(x)); return y;
}
__device__ __forceinline__ unsigned packh2(float hi, float lo) {
    unsigned r; asm("cvt.rn.f16x2.f32 %0, %1, %2;" : "=r"(r) : "f"(hi), "f"(lo)); return r;
}
__device__ __forceinline__ unsigned movm(unsigned x) {
    unsigned r; asm("movmatrix.sync.aligned.m8n8.trans.b16 %0, %1;" : "=r"(r) : "r"(x)); return r;
}
__device__ __forceinline__ void mma_f16(float* d, unsigned a0, unsigned a1,
                                        unsigned a2, unsigned a3, unsigned b0, unsigned b1) {
    asm volatile("mma.sync.aligned.m16n8k16.row.col.f32.f16.f16.f32 "
                 "{%0,%1,%2,%3}, {%4,%5,%6,%7}, {%8,%9}, {%0,%1,%2,%3};"
                 : "+f"(d[0]), "+f"(d[1]), "+f"(d[2]), "+f"(d[3])
                 : "r"(a0), "r"(a1), "r"(a2), "r"(a3), "r"(b0), "r"(b1));
}

// ---------------------------------------------------------------------------
// Tiled transpose: out[k][m] = in[m][k]
// ---------------------------------------------------------------------------
__global__ void transpose_kernel(const float* __restrict__ in, float* __restrict__ out,
                                 int M, int K)
{
    __shared__ float t[32][33];
    int bx = blockIdx.x * 32, by = blockIdx.y * 32;
#pragma unroll
    for (int i = 0; i < 32; i += 8)
        t[threadIdx.y + i][threadIdx.x] = in[(size_t)(by + threadIdx.y + i) * K + bx + threadIdx.x];
    __syncthreads();
#pragma unroll
    for (int i = 0; i < 32; i += 8)
        out[(size_t)(bx + threadIdx.y + i) * M + by + threadIdx.x] = t[threadIdx.x][threadIdx.y + i];
}

// ---------------------------------------------------------------------------
// Fused QKV GEMM + l2norm + fp16 conversion.
// BM=128 (= one of q/k/v via blockIdx.y), BN=64, BK=16, 128 threads, 8x8 tile.
// Epilogue: q/k -> per-pixel-per-head l2norm (block-local), scale 10*log2e on q,
// write fp16 transposed [pix][32d]; v -> fp16 [d][pix].
// ---------------------------------------------------------------------------
__global__ __launch_bounds__(128) void gemm_qkv(
    const float* __restrict__ Wt, const float* __restrict__ X,
    unsigned* __restrict__ qh, unsigned* __restrict__ kh, unsigned* __restrict__ vh)
{
    const int sel = blockIdx.y;                 // 0=q 1=k 2=v
    const int b = blockIdx.z;
    X += (size_t)b * (size_t)CIN * NPIX;

    __shared__ float Ws[2][16][128];
    __shared__ float Xs[2][16][64];
    __shared__ float red[4][64];

    const int tid = threadIdx.x;
    const int tm = tid >> 3, tn = tid & 7;
    const int row0 = sel * 128, col0 = blockIdx.x * 64;
    const unsigned wsb = (unsigned)__cvta_generic_to_shared(&Ws[0][0][0]);
    const unsigned xsb = (unsigned)__cvta_generic_to_shared(&Xs[0][0][0]);

    if (sel < 2)
        for (int i = tid; i < 256; i += 128) ((float*)red)[i] = 0.f;

    float acc[8][8];
#pragma unroll
    for (int i = 0; i < 8; i++)
#pragma unroll
        for (int j = 0; j < 8; j++) acc[i][j] = 0.f;

    auto fill = [&](int kk, int s) {
#pragma unroll
        for (int i = 0; i < 4; i++) {
            int idx = tid + i * 128;
            int k = idx >> 5, m4 = idx & 31;
            cpasync16(wsb + (unsigned)((s * 16 + k) * 128 + m4 * 4) * 4u,
                      Wt + (size_t)(kk + k) * 384 + row0 + m4 * 4);
        }
#pragma unroll
        for (int i = 0; i < 2; i++) {
            int idx = tid + i * 128;
            int k = idx >> 4, n4 = idx & 15;
            cpasync16(xsb + (unsigned)((s * 16 + k) * 64 + n4 * 4) * 4u,
                      X + (size_t)(kk + k) * NPIX + col0 + n4 * 4);
        }
        asm volatile("cp.async.commit_group;");
    };

    fill(0, 0);
    for (int c = 0; c < 16; ++c) {
        if (c + 1 < 16) {
            fill((c + 1) << 4, (c + 1) & 1);
            asm volatile("cp.async.wait_group 1;");
        } else {
            asm volatile("cp.async.wait_group 0;");
        }
        __syncthreads();
        const int s = c & 1;
#pragma unroll
        for (int k = 0; k < 16; k++) {
            float4 w0 = *(const float4*)&Ws[s][k][tm * 4];
            float4 w1 = *(const float4*)&Ws[s][k][64 + tm * 4];
            float4 x0 = *(const float4*)&Xs[s][k][tn * 4];
            float4 x1 = *(const float4*)&Xs[s][k][32 + tn * 4];
            float wr[8] = {w0.x, w0.y, w0.z, w0.w, w1.x, w1.y, w1.z, w1.w};
            float xr[8] = {x0.x, x0.y, x0.z, x0.w, x1.x, x1.y, x1.z, x1.w};
#pragma unroll
            for (int i = 0; i < 8; i++)
#pragma unroll
                for (int j = 0; j < 8; j++)
                    acc[i][j] = fmaf(wr[i], xr[j], acc[i][j]);
        }
        __syncthreads();
    }

    if (sel < 2) {
        // per (head, pixel) sum of squares: rows ih*64+tm*4+i, head = ih*2+(tm>>3)
#pragma unroll
        for (int ih = 0; ih < 2; ih++) {
            int head = ih * 2 + (tm >> 3);
#pragma unroll
            for (int j = 0; j < 8; j++) {
                int col = (j >> 2) * 32 + tn * 4 + (j & 3);
                float s = acc[ih*4+0][j] * acc[ih*4+0][j] + acc[ih*4+1][j] * acc[ih*4+1][j]
                        + acc[ih*4+2][j] * acc[ih*4+2][j] + acc[ih*4+3][j] * acc[ih*4+3][j];
                atomicAdd(&red[head][col], s);
            }
        }
        __syncthreads();

        unsigned* dst = sel ? kh : qh;
        const float scale = (sel == 0) ? 14.426950408889634f : 1.f;  // 10*log2(e)
        const int pairbase = (tm & 7) * 2;      // ((tm*4)&31)/2
#pragma unroll
        for (int ih = 0; ih < 2; ih++) {
            int head = ih * 2 + (tm >> 3);
#pragma unroll
            for (int j = 0; j < 8; j++) {
                int col = (j >> 2) * 32 + tn * 4 + (j & 3);
                float inv = scale / fmaxf(sqrtf(red[head][col]), 1e-12f);
                size_t base = ((size_t)(b * 4 + head) * NPIX + col0 + col) * 16;
                dst[base + pairbase]     = packh2(acc[ih*4+1][j] * inv, acc[ih*4+0][j] * inv);
                dst[base + pairbase + 1] = packh2(acc[ih*4+3][j] * inv, acc[ih*4+2][j] * inv);
            }
        }
    } else {
        // v: fp16 [bh][d][pix-pairs]
#pragma unroll
        for (int ih = 0; ih < 2; ih++)
#pragma unroll
            for (int i = 0; i < 4; i++) {
                int rowl = ih * 64 + tm * 4 + i;
                int head = rowl >> 5, d = rowl & 31;
#pragma unroll
                for (int jh = 0; jh < 2; jh++) {
                    unsigned u0 = packh2(acc[ih*4+i][jh*4+1], acc[ih*4+i][jh*4+0]);
                    unsigned u1 = packh2(acc[ih*4+i][jh*4+3], acc[ih*4+i][jh*4+2]);
                    int pix = col0 + jh * 32 + tn * 4;
                    *(uint2*)&vh[((size_t)(b * 4 + head) * 32 + d) * (NPIX / 2) + pix / 2] =
                        make_uint2(u0, u1);
                }
            }
    }
}

// ---------------------------------------------------------------------------
// fp32 SGEMM for output projection: Y = W @ X (+bias), Wt[K][M].
// ---------------------------------------------------------------------------
__global__ __launch_bounds__(128) void gemm_tn(
    const float* __restrict__ Wt, const float* __restrict__ X,
    float* __restrict__ Y, const float* __restrict__ bias,
    int M, int N, int K)
{
    X += (size_t)blockIdx.z * (size_t)K * N;
    Y += (size_t)blockIdx.z * (size_t)M * N;
    __shared__ float Ws[2][16][128];
    __shared__ float Xs[2][16][64];
    const int tid = threadIdx.x;
    const int tm = tid >> 3, tn = tid & 7;
    const int row0 = blockIdx.y * 128, col0 = blockIdx.x * 64;
    const unsigned wsb = (unsigned)__cvta_generic_to_shared(&Ws[0][0][0]);
    const unsigned xsb = (unsigned)__cvta_generic_to_shared(&Xs[0][0][0]);

    float acc[8][8];
#pragma unroll
    for (int i = 0; i < 8; i++)
#pragma unroll
        for (int j = 0; j < 8; j++) acc[i][j] = 0.f;

    auto fill = [&](int kk, int s) {
#pragma unroll
        for (int i = 0; i < 4; i++) {
            int idx = tid + i * 128;
            int k = idx >> 5, m4 = idx & 31;
            cpasync16(wsb + (unsigned)((s * 16 + k) * 128 + m4 * 4) * 4u,
                      Wt + (size_t)(kk + k) * M + row0 + m4 * 4);
        }
#pragma unroll
        for (int i = 0; i < 2; i++) {
            int idx = tid + i * 128;
            int k = idx >> 4, n4 = idx & 15;
            cpasync16(xsb + (unsigned)((s * 16 + k) * 64 + n4 * 4) * 4u,
                      X + (size_t)(kk + k) * N + col0 + n4 * 4);
        }
        asm volatile("cp.async.commit_group;");
    };

    const int nchunk = K >> 4;
    fill(0, 0);
    for (int c = 0; c < nchunk; ++c) {
        if (c + 1 < nchunk) {
            fill((c + 1) << 4, (c + 1) & 1);
            asm volatile("cp.async.wait_group 1;");
        } else {
            asm volatile("cp.async.wait_group 0;");
        }
        __syncthreads();
        const int s = c & 1;
#pragma unroll
        for (int k = 0; k < 16; k++) {
            float4 w0 = *(const float4*)&Ws[s][k][tm * 4];
            float4 w1 = *(const float4*)&Ws[s][k][64 + tm * 4];
            float4 x0 = *(const float4*)&Xs[s][k][tn * 4];
            float4 x1 = *(const float4*)&Xs[s][k][32 + tn * 4];
            float wr[8] = {w0.x, w0.y, w0.z, w0.w, w1.x, w1.y, w1.z, w1.w};
            float xr[8] = {x0.x, x0.y, x0.z, x0.w, x1.x, x1.y, x1.z, x1.w};
#pragma unroll
            for (int i = 0; i < 8; i++)
#pragma unroll
                for (int j = 0; j < 8; j++)
                    acc[i][j] = fmaf(wr[i], xr[j], acc[i][j]);
        }
        __syncthreads();
    }

#pragma unroll
    for (int ih = 0; ih < 2; ih++)
#pragma unroll
        for (int i = 0; i < 4; i++) {
            int row = row0 + ih * 64 + tm * 4 + i;
            float bv = bias ? bias[row] : 0.f;
            float4 o0 = make_float4(acc[ih*4+i][0] + bv, acc[ih*4+i][1] + bv,
                                    acc[ih*4+i][2] + bv, acc[ih*4+i][3] + bv);
            float4 o1 = make_float4(acc[ih*4+i][4] + bv, acc[ih*4+i][5] + bv,
                                    acc[ih*4+i][6] + bv, acc[ih*4+i][7] + bv);
            *(float4*)&Y[(size_t)row * N + col0 + tn * 4]      = o0;
            *(float4*)&Y[(size_t)row * N + col0 + 32 + tn * 4] = o1;
        }
}

// ---------------------------------------------------------------------------
// fp16 flash attention: 3-stage cp.async ring, ONE __syncthreads per iter.
// ---------------------------------------------------------------------------
#define SKH 20
#define SVH 36
#define STAGE (64 * SKH + 32 * SVH)

__global__ __launch_bounds__(128, 4) void flash_h_kernel(
    const unsigned* __restrict__ qh, const unsigned* __restrict__ kh,
    const unsigned* __restrict__ vh, float* __restrict__ out)
{
    __shared__ unsigned sm[3 * STAGE];
    __shared__ float lw[4][32];

    const int tid = threadIdx.x, lane = tid & 31, warp = tid >> 5;
    const int g = lane >> 2, c = lane & 3;
    const int bh = blockIdx.y, b = bh >> 2, h = bh & 3;
    const int qw = blockIdx.x * 128 + warp * 32;

    const unsigned* qbh = qh + (size_t)bh * NPIX * 16;
    const unsigned* kbh = kh + (size_t)bh * NPIX * 16;
    const unsigned* vbh = vh + (size_t)bh * 32 * (NPIX / 2);
    const unsigned sbase = (unsigned)__cvta_generic_to_shared(sm);

    unsigned bq[2][4][2];
#pragma unroll
    for (int n = 0; n < 4; n++) {
        const unsigned* qq = qbh + (size_t)(qw + 8 * n + g) * 16;
#pragma unroll
        for (int ks = 0; ks < 2; ks++) {
            bq[ks][n][0] = qq[8 * ks + c];
            bq[ks][n][1] = qq[8 * ks + c + 4];
        }
    }

    float O[2][4][4];
    float lrun[4][2];
#pragma unroll
    for (int mq = 0; mq < 2; mq++)
#pragma unroll
        for (int nd = 0; nd < 4; nd++)
#pragma unroll
            for (int r = 0; r < 4; r++) O[mq][nd][r] = 0.f;
#pragma unroll
    for (int n = 0; n < 4; n++) { lrun[n][0] = 0.f; lrun[n][1] = 0.f; }

    auto fill = [&](int it, int s) {
        unsigned base = sbase + (unsigned)(s * STAGE) * 4u;
        int j0 = it * 64;
#pragma unroll
        for (int r = 0; r < 2; r++) {
            int id = tid + r * 128;
            int row = id >> 2, j = id & 3;
            cpasync16(base + (unsigned)(row * SKH + 4 * j) * 4u,
                      kbh + (size_t)(j0 + row) * 16 + 4 * j);
            int d = id >> 3, jj = id & 7;
            cpasync16(base + (unsigned)(64 * SKH + d * SVH + 4 * jj) * 4u,
                      vbh + (size_t)d * (NPIX / 2) + j0 / 2 + 4 * jj);
        }
        asm volatile("cp.async.commit_group;");
    };

    fill(0, 0);
    fill(1, 1);

    int stage = 0;
    for (int it = 0; it < 64; ++it) {
        if (it < 62) asm volatile("cp.async.wait_group 1;");
        else         asm volatile("cp.async.wait_group 0;");
        __syncthreads();
        if (it < 62) {
            int s2 = stage + 2; if (s2 >= 3) s2 -= 3;
            fill(it + 2, s2);
        }

        const unsigned* skh = sm + stage * STAGE;
        const unsigned* svh = skh + 64 * SKH;

#pragma unroll
        for (int m = 0; m < 4; m++) {
            float acc[4][4];
#pragma unroll
            for (int n = 0; n < 4; n++)
#pragma unroll
                for (int r = 0; r < 4; r++) acc[n][r] = 0.f;
#pragma unroll
            for (int ks = 0; ks < 2; ks++) {
                unsigned a0 = skh[(16 * m + g) * SKH + 8 * ks + c];
                unsigned a1 = skh[(16 * m + 8 + g) * SKH + 8 * ks + c];
                unsigned a2 = skh[(16 * m + g) * SKH + 8 * ks + c + 4];
                unsigned a3 = skh[(16 * m + 8 + g) * SKH + 8 * ks + c + 4];
#pragma unroll
                for (int n = 0; n < 4; n++)
                    mma_f16(acc[n], a0, a1, a2, a3, bq[ks][n][0], bq[ks][n][1]);
            }
            unsigned t0[4], t1[4];
#pragma unroll
            for (int n = 0; n < 4; n++) {
                float e0 = ex2(acc[n][0]), e1 = ex2(acc[n][1]);
                float e2 = ex2(acc[n][2]), e3 = ex2(acc[n][3]);
                lrun[n][0] += e0 + e2;
                lrun[n][1] += e1 + e3;
                t0[n] = movm(packh2(e1, e0));
                t1[n] = movm(packh2(e3, e2));
            }
#pragma unroll
            for (int nd = 0; nd < 4; nd++) {
                unsigned b0 = svh[(8 * nd + g) * SVH + 8 * m + c];
                unsigned b1 = svh[(8 * nd + g) * SVH + 8 * m + c + 4];
                mma_f16(O[0][nd], t0[0], t0[1], t1[0], t1[1], b0, b1);
                mma_f16(O[1][nd], t0[2], t0[3], t1[2], t1[3], b0, b1);
            }
        }
        if (++stage == 3) stage = 0;
    }

#pragma unroll
    for (int n = 0; n < 4; n++)
#pragma unroll
        for (int p = 0; p < 2; p++) {
            float l = lrun[n][p];
            l += __shfl_xor_sync(0xffffffffu, l, 4);
            l += __shfl_xor_sync(0xffffffffu, l, 8);
            l += __shfl_xor_sync(0xffffffffu, l, 16);
            lrun[n][p] = l;
        }
    if (g == 0) {
#pragma unroll
        for (int n = 0; n < 4; n++) {
            lw[warp][8 * n + 2 * c]     = lrun[n][0];
            lw[warp][8 * n + 2 * c + 1] = lrun[n][1];
        }
    }
    __syncwarp();
    float linv[2][2];
#pragma unroll
    for (int mq = 0; mq < 2; mq++) {
        linv[mq][0] = 1.f / lw[warp][16 * mq + g];
        linv[mq][1] = 1.f / lw[warp][16 * mq + 8 + g];
    }

    float* op = out + ((size_t)b * 128 + h * 32) * NPIX;
#pragma unroll
    for (int mq = 0; mq < 2; mq++)
#pragma unroll
        for (int nd = 0; nd < 4; nd++) {
            int q0 = qw + 16 * mq + g;
            int dd = 8 * nd + 2 * c;
            op[(size_t)dd * NPIX + q0]           = O[mq][nd][0] * linv[mq][0];
            op[(size_t)(dd + 1) * NPIX + q0]     = O[mq][nd][1] * linv[mq][0];
            op[(size_t)dd * NPIX + q0 + 8]       = O[mq][nd][2] * linv[mq][1];
            op[(size_t)(dd + 1) * NPIX + q0 + 8] = O[mq][nd][3] * linv[mq][1];
        }
}

// ---------------------------------------------------------------------------
extern "C" void kernel_launch(void* const* d_in, const int* in_sizes, int n_in,
                              void* d_out, int out_size)
{
    const float* x     = (const float*)d_in[0];
    const float* w_qkv = (const float*)d_in[1];
    const float* w_out = (const float*)d_in[2];
    const float* b_out = (const float*)d_in[3];
    float* out = (float*)d_out;

    static float *ao = nullptr, *wt1 = nullptr, *wt2 = nullptr;
    static unsigned *qh = nullptr, *kh = nullptr, *vh = nullptr;
    if (!ao) {
        cudaGetSymbolAddress((void**)&ao,  g_ao);
        cudaGetSymbolAddress((void**)&qh,  g_qh);
        cudaGetSymbolAddress((void**)&kh,  g_kh);
        cudaGetSymbolAddress((void**)&vh,  g_vh);
        cudaGetSymbolAddress((void**)&wt1, g_wt1);
        cudaGetSymbolAddress((void**)&wt2, g_wt2);
    }

    dim3 tb(32, 8);
    transpose_kernel<<<dim3(256 / 32, 384 / 32), tb>>>(w_qkv, wt1, 384, 256);
    transpose_kernel<<<dim3(128 / 32, 256 / 32), tb>>>(w_out, wt2, 256, 128);

    dim3 g1(NPIX / 64, 3, NB);
    gemm_qkv<<<g1, 128>>>(wt1, x, qh, kh, vh);

    dim3 g3(NPIX / 128, 16);
    flash_h_kernel<<<g3, 128>>>(qh, kh, vh, ao);

    dim3 g4(NPIX / 64, 256 / 128, NB);
    gemm_tn<<<g4, 128>>>(wt2, ao, out, b_out, 256, NPIX, HID);
}

// round 10
// speedup vs baseline: 7.3104x; 1.3023x over previous
#include <cuda_runtime.h>
#include <cuda_fp16.h>
#include <cstdint>
#include <math.h>

#define NPIX 4096
#define NB 4
#define NHEADS 4
#define CIN 256
#define HID 128

__device__ float g_ao[(size_t)NB * HID * NPIX];
__device__ unsigned g_qh[(size_t)16 * NPIX * 16];        // [bh][pix][16 d-pairs]
__device__ unsigned g_kh[(size_t)16 * NPIX * 16];
__device__ unsigned g_vh[(size_t)16 * 32 * (NPIX / 2)];  // [bh][d][pix-pairs]
__device__ unsigned g_wh[384 * 128];                     // w_qkv fp16 [m][k-pairs]
__device__ unsigned g_xh[(size_t)NB * NPIX * 128];       // x fp16 transposed [b][pix][k-pairs]
__device__ float g_wt2[128 * 256];

__device__ __forceinline__ void cpasync16(unsigned dst, const void* src) {
    asm volatile("cp.async.ca.shared.global [%0], [%1], 16;" :: "r"(dst), "l"(src));
}
__device__ __forceinline__ unsigned packh2(float hi, float lo) {
    unsigned r; asm("cvt.rn.f16x2.f32 %0, %1, %2;" : "=r"(r) : "f"(hi), "f"(lo)); return r;
}
__device__ __forceinline__ unsigned h2exp2(unsigned x) {
    unsigned r; asm("ex2.approx.f16x2 %0, %1;" : "=r"(r) : "r"(x)); return r;
}
__device__ __forceinline__ unsigned movm(unsigned x) {
    unsigned r; asm("movmatrix.sync.aligned.m8n8.trans.b16 %0, %1;" : "=r"(r) : "r"(x)); return r;
}
__device__ __forceinline__ void mma_f16(float* d, unsigned a0, unsigned a1,
                                        unsigned a2, unsigned a3, unsigned b0, unsigned b1) {
    asm volatile("mma.sync.aligned.m16n8k16.row.col.f32.f16.f16.f32 "
                 "{%0,%1,%2,%3}, {%4,%5,%6,%7}, {%8,%9}, {%0,%1,%2,%3};"
                 : "+f"(d[0]), "+f"(d[1]), "+f"(d[2]), "+f"(d[3])
                 : "r"(a0), "r"(a1), "r"(a2), "r"(a3), "r"(b0), "r"(b1));
}

// ---------------- converters ----------------
__global__ void wcvt_kernel(const float* __restrict__ w, unsigned* __restrict__ wh)
{
    int i = blockIdx.x * 256 + threadIdx.x;      // 49152 u32
    wh[i] = packh2(w[2 * i + 1], w[2 * i]);
}

__global__ void transpose_kernel(const float* __restrict__ in, float* __restrict__ out,
                                 int M, int K)
{
    __shared__ float t[32][33];
    int bx = blockIdx.x * 32, by = blockIdx.y * 32;
#pragma unroll
    for (int i = 0; i < 32; i += 8)
        t[threadIdx.y + i][threadIdx.x] = in[(size_t)(by + threadIdx.y + i) * K + bx + threadIdx.x];
    __syncthreads();
#pragma unroll
    for (int i = 0; i < 32; i += 8)
        out[(size_t)(bx + threadIdx.y + i) * M + by + threadIdx.x] = t[threadIdx.x][threadIdx.y + i];
}

// x fp32 [b][k][pix] -> fp16 transposed [b][pix][k-pairs]
__global__ __launch_bounds__(256) void xcvt_kernel(const float* __restrict__ x,
                                                   unsigned* __restrict__ xh)
{
    __shared__ float t[64][65];
    const int pix0 = blockIdx.x * 64, k0 = blockIdx.y * 64, b = blockIdx.z;
    const int tid = threadIdx.x;
#pragma unroll
    for (int j = 0; j < 16; j++) {
        int row = j * 4 + (tid >> 6), col = tid & 63;
        t[row][col] = x[((size_t)b * 256 + k0 + row) * NPIX + pix0 + col];
    }
    __syncthreads();
    int p = tid >> 2, seg = tid & 3;
    unsigned u[8];
#pragma unroll
    for (int j = 0; j < 8; j++)
        u[j] = packh2(t[seg * 16 + 2 * j + 1][p], t[seg * 16 + 2 * j][p]);
    unsigned* dst = xh + ((size_t)b * NPIX + pix0 + p) * 128 + k0 / 2 + seg * 8;
    *(uint4*)dst       = make_uint4(u[0], u[1], u[2], u[3]);
    *(uint4*)(dst + 4) = make_uint4(u[4], u[5], u[6], u[7]);
}

// ---------------------------------------------------------------------------
// fp16 tensor-core QKV GEMM + fused l2norm + flash-layout outputs.
// BM=128 (sel in {q,k,v}), BN=64 pixels, K=256, 128 threads; warp w == head w.
// ---------------------------------------------------------------------------
#define GS 12   // smem row stride in u32 (12 % 32 == 12; 12g+c distinct banks)

__global__ __launch_bounds__(128) void gemm_qkv_h(
    const unsigned* __restrict__ wh, const unsigned* __restrict__ xh,
    unsigned* __restrict__ qh, unsigned* __restrict__ kh, unsigned* __restrict__ vh)
{
    __shared__ unsigned sW[2][128 * GS];
    __shared__ unsigned sX[2][64 * GS];

    const int sel = blockIdx.y, b = blockIdx.z;
    const int pix0 = blockIdx.x * 64;
    const int tid = threadIdx.x, lane = tid & 31, warp = tid >> 5;
    const int g = lane >> 2, c = lane & 3;
    const unsigned wsb = (unsigned)__cvta_generic_to_shared(&sW[0][0]);
    const unsigned xsb = (unsigned)__cvta_generic_to_shared(&sX[0][0]);

    float acc[2][8][4];
#pragma unroll
    for (int mt = 0; mt < 2; mt++)
#pragma unroll
        for (int nt = 0; nt < 8; nt++)
#pragma unroll
            for (int r = 0; r < 4; r++) acc[mt][nt][r] = 0.f;

    auto fill = [&](int kk, int s) {
        const unsigned* wsrc = wh + (size_t)(sel * 128 + tid) * 128 + kk / 2;
#pragma unroll
        for (int j = 0; j < 2; j++)
            cpasync16(wsb + (unsigned)(s * 128 * GS + tid * GS + j * 4) * 4u, wsrc + j * 4);
        int row = tid >> 1, hf = tid & 1;
        cpasync16(xsb + (unsigned)(s * 64 * GS + row * GS + hf * 4) * 4u,
                  xh + ((size_t)b * NPIX + pix0 + row) * 128 + kk / 2 + hf * 4);
        asm volatile("cp.async.commit_group;");
    };

    fill(0, 0);
    for (int ch = 0; ch < 16; ++ch) {
        if (ch < 15) {
            fill((ch + 1) * 16, (ch + 1) & 1);
            asm volatile("cp.async.wait_group 1;");
        } else {
            asm volatile("cp.async.wait_group 0;");
        }
        __syncthreads();
        const unsigned* w0 = &sW[ch & 1][0];
        const unsigned* x0 = &sX[ch & 1][0];
        unsigned bb[8][2];
#pragma unroll
        for (int nt = 0; nt < 8; nt++) {
            bb[nt][0] = x0[(8 * nt + g) * GS + c];
            bb[nt][1] = x0[(8 * nt + g) * GS + c + 4];
        }
#pragma unroll
        for (int mt = 0; mt < 2; mt++) {
            int mrow = 32 * warp + 16 * mt;
            unsigned a0 = w0[(mrow + g) * GS + c];
            unsigned a1 = w0[(mrow + 8 + g) * GS + c];
            unsigned a2 = w0[(mrow + g) * GS + c + 4];
            unsigned a3 = w0[(mrow + 8 + g) * GS + c + 4];
#pragma unroll
            for (int nt = 0; nt < 8; nt++)
                mma_f16(acc[mt][nt], a0, a1, a2, a3, bb[nt][0], bb[nt][1]);
        }
        __syncthreads();
    }

    // ---- epilogue: warp w == head w ----
    if (sel < 2) {
        unsigned* dst = sel ? kh : qh;
        const float scale = (sel == 0) ? 14.426950408889634f : 1.f;   // 10*log2(e)
#pragma unroll
        for (int nt = 0; nt < 8; nt++) {
#pragma unroll
            for (int par = 0; par < 2; par++) {
                float ss = acc[0][nt][par] * acc[0][nt][par]
                         + acc[0][nt][par + 2] * acc[0][nt][par + 2]
                         + acc[1][nt][par] * acc[1][nt][par]
                         + acc[1][nt][par + 2] * acc[1][nt][par + 2];
                ss += __shfl_xor_sync(0xffffffffu, ss, 4);
                ss += __shfl_xor_sync(0xffffffffu, ss, 8);
                ss += __shfl_xor_sync(0xffffffffu, ss, 16);
                float inv = scale / fmaxf(sqrtf(ss), 1e-12f);
                size_t base = ((size_t)(b * 4 + warp) * NPIX + pix0 + 8 * nt + 2 * c + par) * 16;
#pragma unroll
                for (int mt = 0; mt < 2; mt++) {
                    float v0 = acc[mt][nt][par] * inv;        // d = 16mt+g
                    float v1 = acc[mt][nt][par + 2] * inv;    // d = 16mt+8+g
                    float w0 = __shfl_xor_sync(0xffffffffu, v0, 4);
                    float w1 = __shfl_xor_sync(0xffffffffu, v1, 4);
                    if (!(g & 1)) {
                        dst[base + 8 * mt + (g >> 1)]     = packh2(w0, v0);
                        dst[base + 8 * mt + 4 + (g >> 1)] = packh2(w1, v1);
                    }
                }
            }
        }
    } else {
#pragma unroll
        for (int mt = 0; mt < 2; mt++)
#pragma unroll
            for (int dh = 0; dh < 2; dh++) {
                int d = 16 * mt + 8 * dh + g;
#pragma unroll
                for (int nt = 0; nt < 8; nt++) {
                    unsigned pv = packh2(acc[mt][nt][2 * dh + 1], acc[mt][nt][2 * dh]);
                    vh[((size_t)(b * 4 + warp) * 32 + d) * (NPIX / 2) + (pix0 + 8 * nt) / 2 + c] = pv;
                }
            }
    }
}

// ---------------------------------------------------------------------------
// fp32 SGEMM for output projection (Wt[K][M]).
// ---------------------------------------------------------------------------
__global__ __launch_bounds__(128) void gemm_tn(
    const float* __restrict__ Wt, const float* __restrict__ X,
    float* __restrict__ Y, const float* __restrict__ bias,
    int M, int N, int K)
{
    X += (size_t)blockIdx.z * (size_t)K * N;
    Y += (size_t)blockIdx.z * (size_t)M * N;
    __shared__ float Ws[2][16][128];
    __shared__ float Xs[2][16][64];
    const int tid = threadIdx.x;
    const int tm = tid >> 3, tn = tid & 7;
    const int row0 = blockIdx.y * 128, col0 = blockIdx.x * 64;
    const unsigned wsb = (unsigned)__cvta_generic_to_shared(&Ws[0][0][0]);
    const unsigned xsb = (unsigned)__cvta_generic_to_shared(&Xs[0][0][0]);

    float acc[8][8];
#pragma unroll
    for (int i = 0; i < 8; i++)
#pragma unroll
        for (int j = 0; j < 8; j++) acc[i][j] = 0.f;

    auto fill = [&](int kk, int s) {
#pragma unroll
        for (int i = 0; i < 4; i++) {
            int idx = tid + i * 128;
            int k = idx >> 5, m4 = idx & 31;
            cpasync16(wsb + (unsigned)((s * 16 + k) * 128 + m4 * 4) * 4u,
                      Wt + (size_t)(kk + k) * M + row0 + m4 * 4);
        }
#pragma unroll
        for (int i = 0; i < 2; i++) {
            int idx = tid + i * 128;
            int k = idx >> 4, n4 = idx & 15;
            cpasync16(xsb + (unsigned)((s * 16 + k) * 64 + n4 * 4) * 4u,
                      X + (size_t)(kk + k) * N + col0 + n4 * 4);
        }
        asm volatile("cp.async.commit_group;");
    };

    const int nchunk = K >> 4;
    fill(0, 0);
    for (int ch = 0; ch < nchunk; ++ch) {
        if (ch + 1 < nchunk) {
            fill((ch + 1) << 4, (ch + 1) & 1);
            asm volatile("cp.async.wait_group 1;");
        } else {
            asm volatile("cp.async.wait_group 0;");
        }
        __syncthreads();
        const int s = ch & 1;
#pragma unroll
        for (int k = 0; k < 16; k++) {
            float4 w0 = *(const float4*)&Ws[s][k][tm * 4];
            float4 w1 = *(const float4*)&Ws[s][k][64 + tm * 4];
            float4 x0 = *(const float4*)&Xs[s][k][tn * 4];
            float4 x1 = *(const float4*)&Xs[s][k][32 + tn * 4];
            float wr[8] = {w0.x, w0.y, w0.z, w0.w, w1.x, w1.y, w1.z, w1.w};
            float xr[8] = {x0.x, x0.y, x0.z, x0.w, x1.x, x1.y, x1.z, x1.w};
#pragma unroll
            for (int i = 0; i < 8; i++)
#pragma unroll
                for (int j = 0; j < 8; j++)
                    acc[i][j] = fmaf(wr[i], xr[j], acc[i][j]);
        }
        __syncthreads();
    }

#pragma unroll
    for (int ih = 0; ih < 2; ih++)
#pragma unroll
        for (int i = 0; i < 4; i++) {
            int row = row0 + ih * 64 + tm * 4 + i;
            float bv = bias ? bias[row] : 0.f;
            float4 o0 = make_float4(acc[ih*4+i][0] + bv, acc[ih*4+i][1] + bv,
                                    acc[ih*4+i][2] + bv, acc[ih*4+i][3] + bv);
            float4 o1 = make_float4(acc[ih*4+i][4] + bv, acc[ih*4+i][5] + bv,
                                    acc[ih*4+i][6] + bv, acc[ih*4+i][7] + bv);
            *(float4*)&Y[(size_t)row * N + col0 + tn * 4]      = o0;
            *(float4*)&Y[(size_t)row * N + col0 + 32 + tn * 4] = o1;
        }
}

// ---------------------------------------------------------------------------
// fp16 flash attention: h2exp2 softmax (MUFU halved), 3-stage cp.async ring.
// ---------------------------------------------------------------------------
#define SKH 20
#define SVH 36
#define STAGE (64 * SKH + 32 * SVH)

__global__ __launch_bounds__(128, 4) void flash_h_kernel(
    const unsigned* __restrict__ qh, const unsigned* __restrict__ kh,
    const unsigned* __restrict__ vh, float* __restrict__ out)
{
    __shared__ unsigned sm[3 * STAGE];
    __shared__ float lw[4][32];

    const int tid = threadIdx.x, lane = tid & 31, warp = tid >> 5;
    const int g = lane >> 2, c = lane & 3;
    const int bh = blockIdx.y, b = bh >> 2, h = bh & 3;
    const int qw = blockIdx.x * 128 + warp * 32;

    const unsigned* qbh = qh + (size_t)bh * NPIX * 16;
    const unsigned* kbh = kh + (size_t)bh * NPIX * 16;
    const unsigned* vbh = vh + (size_t)bh * 32 * (NPIX / 2);
    const unsigned sbase = (unsigned)__cvta_generic_to_shared(sm);

    unsigned bq[2][4][2];
#pragma unroll
    for (int n = 0; n < 4; n++) {
        const unsigned* qq = qbh + (size_t)(qw + 8 * n + g) * 16;
#pragma unroll
        for (int ks = 0; ks < 2; ks++) {
            bq[ks][n][0] = qq[8 * ks + c];
            bq[ks][n][1] = qq[8 * ks + c + 4];
        }
    }

    float O[2][4][4];
    float lrun[4][2];
#pragma unroll
    for (int mq = 0; mq < 2; mq++)
#pragma unroll
        for (int nd = 0; nd < 4; nd++)
#pragma unroll
            for (int r = 0; r < 4; r++) O[mq][nd][r] = 0.f;
#pragma unroll
    for (int n = 0; n < 4; n++) { lrun[n][0] = 0.f; lrun[n][1] = 0.f; }

    auto fill = [&](int it, int s) {
        unsigned base = sbase + (unsigned)(s * STAGE) * 4u;
        int j0 = it * 64;
#pragma unroll
        for (int r = 0; r < 2; r++) {
            int id = tid + r * 128;
            int row = id >> 2, j = id & 3;
            cpasync16(base + (unsigned)(row * SKH + 4 * j) * 4u,
                      kbh + (size_t)(j0 + row) * 16 + 4 * j);
            int d = id >> 3, jj = id & 7;
            cpasync16(base + (unsigned)(64 * SKH + d * SVH + 4 * jj) * 4u,
                      vbh + (size_t)d * (NPIX / 2) + j0 / 2 + 4 * jj);
        }
        asm volatile("cp.async.commit_group;");
    };

    fill(0, 0);
    fill(1, 1);

    int stage = 0;
    for (int it = 0; it < 64; ++it) {
        if (it < 62) asm volatile("cp.async.wait_group 1;");
        else         asm volatile("cp.async.wait_group 0;");
        __syncthreads();
        if (it < 62) {
            int s2 = stage + 2; if (s2 >= 3) s2 -= 3;
            fill(it + 2, s2);
        }

        const unsigned* skh = sm + stage * STAGE;
        const unsigned* svh = skh + 64 * SKH;

#pragma unroll
        for (int m = 0; m < 4; m++) {
            float acc[4][4];
#pragma unroll
            for (int n = 0; n < 4; n++)
#pragma unroll
                for (int r = 0; r < 4; r++) acc[n][r] = 0.f;
#pragma unroll
            for (int ks = 0; ks < 2; ks++) {
                unsigned a0 = skh[(16 * m + g) * SKH + 8 * ks + c];
                unsigned a1 = skh[(16 * m + 8 + g) * SKH + 8 * ks + c];
                unsigned a2 = skh[(16 * m + g) * SKH + 8 * ks + c + 4];
                unsigned a3 = skh[(16 * m + 8 + g) * SKH + 8 * ks + c + 4];
#pragma unroll
                for (int n = 0; n < 4; n++)
                    mma_f16(acc[n], a0, a1, a2, a3, bq[ks][n][0], bq[ks][n][1]);
            }
            unsigned t0[4], t1[4];
#pragma unroll
            for (int n = 0; n < 4; n++) {
                unsigned e01 = h2exp2(packh2(acc[n][1], acc[n][0]));
                unsigned e23 = h2exp2(packh2(acc[n][3], acc[n][2]));
                __half2 hs = __hadd2(*(__half2*)&e01, *(__half2*)&e23);
                lrun[n][0] += __low2float(hs);
                lrun[n][1] += __high2float(hs);
                t0[n] = movm(e01);
                t1[n] = movm(e23);
            }
#pragma unroll
            for (int nd = 0; nd < 4; nd++) {
                unsigned b0 = svh[(8 * nd + g) * SVH + 8 * m + c];
                unsigned b1 = svh[(8 * nd + g) * SVH + 8 * m + c + 4];
                mma_f16(O[0][nd], t0[0], t0[1], t1[0], t1[1], b0, b1);
                mma_f16(O[1][nd], t0[2], t0[3], t1[2], t1[3], b0, b1);
            }
        }
        if (++stage == 3) stage = 0;
    }

#pragma unroll
    for (int n = 0; n < 4; n++)
#pragma unroll
        for (int p = 0; p < 2; p++) {
            float l = lrun[n][p];
            l += __shfl_xor_sync(0xffffffffu, l, 4);
            l += __shfl_xor_sync(0xffffffffu, l, 8);
            l += __shfl_xor_sync(0xffffffffu, l, 16);
            lrun[n][p] = l;
        }
    if (g == 0) {
#pragma unroll
        for (int n = 0; n < 4; n++) {
            lw[warp][8 * n + 2 * c]     = lrun[n][0];
            lw[warp][8 * n + 2 * c + 1] = lrun[n][1];
        }
    }
    __syncwarp();
    float linv[2][2];
#pragma unroll
    for (int mq = 0; mq < 2; mq++) {
        linv[mq][0] = 1.f / lw[warp][16 * mq + g];
        linv[mq][1] = 1.f / lw[warp][16 * mq + 8 + g];
    }

    float* op = out + ((size_t)b * 128 + h * 32) * NPIX;
#pragma unroll
    for (int mq = 0; mq < 2; mq++)
#pragma unroll
        for (int nd = 0; nd < 4; nd++) {
            int q0 = qw + 16 * mq + g;
            int dd = 8 * nd + 2 * c;
            op[(size_t)dd * NPIX + q0]           = O[mq][nd][0] * linv[mq][0];
            op[(size_t)(dd + 1) * NPIX + q0]     = O[mq][nd][1] * linv[mq][0];
            op[(size_t)dd * NPIX + q0 + 8]       = O[mq][nd][2] * linv[mq][1];
            op[(size_t)(dd + 1) * NPIX + q0 + 8] = O[mq][nd][3] * linv[mq][1];
        }
}

// ---------------------------------------------------------------------------
extern "C" void kernel_launch(void* const* d_in, const int* in_sizes, int n_in,
                              void* d_out, int out_size)
{
    const float* x     = (const float*)d_in[0];
    const float* w_qkv = (const float*)d_in[1];
    const float* w_out = (const float*)d_in[2];
    const float* b_out = (const float*)d_in[3];
    float* out = (float*)d_out;

    static float *ao = nullptr, *wt2 = nullptr;
    static unsigned *qh = nullptr, *kh = nullptr, *vh = nullptr, *wh = nullptr, *xh = nullptr;
    if (!ao) {
        cudaGetSymbolAddress((void**)&ao,  g_ao);
        cudaGetSymbolAddress((void**)&qh,  g_qh);
        cudaGetSymbolAddress((void**)&kh,  g_kh);
        cudaGetSymbolAddress((void**)&vh,  g_vh);
        cudaGetSymbolAddress((void**)&wh,  g_wh);
        cudaGetSymbolAddress((void**)&xh,  g_xh);
        cudaGetSymbolAddress((void**)&wt2, g_wt2);
    }

    wcvt_kernel<<<192, 256>>>(w_qkv, wh);
    transpose_kernel<<<dim3(128 / 32, 256 / 32), dim3(32, 8)>>>(w_out, wt2, 256, 128);
    xcvt_kernel<<<dim3(NPIX / 64, 256 / 64, NB), 256>>>(x, xh);

    dim3 g1(NPIX / 64, 3, NB);
    gemm_qkv_h<<<g1, 128>>>(wh, xh, qh, kh, vh);

    dim3 g3(NPIX / 128, 16);
    flash_h_kernel<<<g3, 128>>>(qh, kh, vh, ao);

    dim3 g4(NPIX / 64, 256 / 128, NB);
    gemm_tn<<<g4, 128>>>(wt2, ao, out, b_out, 256, NPIX, HID);
}

// round 11
// speedup vs baseline: 7.7368x; 1.0583x over previous
#include <cuda_runtime.h>
#include <cuda_fp16.h>
#include <cstdint>
#include <math.h>

#define NPIX 4096
#define NB 4
#define NHEADS 4
#define CIN 256
#define HID 128

__device__ unsigned g_qh[(size_t)16 * NPIX * 16];
__device__ unsigned g_kh[(size_t)16 * NPIX * 16];
__device__ unsigned g_vh[(size_t)16 * 32 * (NPIX / 2)];
__device__ unsigned g_wh[384 * 128];
__device__ unsigned g_xh[(size_t)NB * NPIX * 128];
__device__ unsigned g_w2hi[256 * 64], g_w2lo[256 * 64];          // w_out split [m][k-pairs]
__device__ unsigned g_aohi[(size_t)NB * NPIX * 64];              // attn out split [pix][k-pairs]
__device__ unsigned g_aolo[(size_t)NB * NPIX * 64];

__device__ __forceinline__ void cpasync16(unsigned dst, const void* src) {
    asm volatile("cp.async.ca.shared.global [%0], [%1], 16;" :: "r"(dst), "l"(src));
}
__device__ __forceinline__ unsigned packh2(float hi, float lo) {
    unsigned r; asm("cvt.rn.f16x2.f32 %0, %1, %2;" : "=r"(r) : "f"(hi), "f"(lo)); return r;
}
__device__ __forceinline__ unsigned h2exp2(unsigned x) {
    unsigned r; asm("ex2.approx.f16x2 %0, %1;" : "=r"(r) : "r"(x)); return r;
}
__device__ __forceinline__ unsigned movm(unsigned x) {
    unsigned r; asm("movmatrix.sync.aligned.m8n8.trans.b16 %0, %1;" : "=r"(r) : "r"(x)); return r;
}
__device__ __forceinline__ void mma_f16(float* d, unsigned a0, unsigned a1,
                                        unsigned a2, unsigned a3, unsigned b0, unsigned b1) {
    asm volatile("mma.sync.aligned.m16n8k16.row.col.f32.f16.f16.f32 "
                 "{%0,%1,%2,%3}, {%4,%5,%6,%7}, {%8,%9}, {%0,%1,%2,%3};"
                 : "+f"(d[0]), "+f"(d[1]), "+f"(d[2]), "+f"(d[3])
                 : "r"(a0), "r"(a1), "r"(a2), "r"(a3), "r"(b0), "r"(b1));
}

// ---------------- converters ----------------
__global__ void wcvt_kernel(const float* __restrict__ w, unsigned* __restrict__ wh)
{
    int i = blockIdx.x * 256 + threadIdx.x;
    wh[i] = packh2(w[2 * i + 1], w[2 * i]);
}
__global__ void wsplit_kernel(const float* __restrict__ w,
                              unsigned* __restrict__ whi, unsigned* __restrict__ wlo)
{
    int i = blockIdx.x * 256 + threadIdx.x;       // 16384 u32
    float a = w[2 * i], bb = w[2 * i + 1];
    __half ha = __float2half_rn(a), hb = __float2half_rn(bb);
    whi[i] = (unsigned)__half_as_ushort(ha) | ((unsigned)__half_as_ushort(hb) << 16);
    wlo[i] = packh2(bb - __half2float(hb), a - __half2float(ha));
}
__global__ __launch_bounds__(256) void xcvt_kernel(const float* __restrict__ x,
                                                   unsigned* __restrict__ xh)
{
    __shared__ float t[64][65];
    const int pix0 = blockIdx.x * 64, k0 = blockIdx.y * 64, b = blockIdx.z;
    const int tid = threadIdx.x;
#pragma unroll
    for (int j = 0; j < 16; j++) {
        int row = j * 4 + (tid >> 6), col = tid & 63;
        t[row][col] = x[((size_t)b * 256 + k0 + row) * NPIX + pix0 + col];
    }
    __syncthreads();
    int p = tid >> 2, seg = tid & 3;
    unsigned u[8];
#pragma unroll
    for (int j = 0; j < 8; j++)
        u[j] = packh2(t[seg * 16 + 2 * j + 1][p], t[seg * 16 + 2 * j][p]);
    unsigned* dst = xh + ((size_t)b * NPIX + pix0 + p) * 128 + k0 / 2 + seg * 8;
    *(uint4*)dst       = make_uint4(u[0], u[1], u[2], u[3]);
    *(uint4*)(dst + 4) = make_uint4(u[4], u[5], u[6], u[7]);
}

// ---------------------------------------------------------------------------
// fp16 QKV GEMM + fused l2norm. 256 thr (4 head-warps x 2 pixel-halves),
// BM=128(sel), BN=128 pixels, BK=32 (8 chunks), double-buffered.
// ---------------------------------------------------------------------------
#define GS 20
__global__ __launch_bounds__(256) void gemm_qkv_h(
    const unsigned* __restrict__ wh, const unsigned* __restrict__ xh,
    unsigned* __restrict__ qh, unsigned* __restrict__ kh, unsigned* __restrict__ vh)
{
    __shared__ unsigned sW[2][128 * GS];
    __shared__ unsigned sX[2][128 * GS];

    const int sel = blockIdx.y, b = blockIdx.z;
    const int pixB = blockIdx.x * 128;
    const int tid = threadIdx.x, lane = tid & 31, warp = tid >> 5;
    const int g = lane >> 2, c = lane & 3;
    const int head = warp & 3, nh = warp >> 2;
    const int pix0 = pixB + nh * 64;
    const unsigned wsb = (unsigned)__cvta_generic_to_shared(&sW[0][0]);
    const unsigned xsb = (unsigned)__cvta_generic_to_shared(&sX[0][0]);

    float acc[2][8][4];
#pragma unroll
    for (int mt = 0; mt < 2; mt++)
#pragma unroll
        for (int nt = 0; nt < 8; nt++)
#pragma unroll
            for (int r = 0; r < 4; r++) acc[mt][nt][r] = 0.f;

    auto fill = [&](int kk, int s) {
        int row = tid >> 1, sg = tid & 1;
        const unsigned* ws = wh + (size_t)(sel * 128 + row) * 128 + kk / 2 + sg * 8;
        cpasync16(wsb + (unsigned)(s * 128 * GS + row * GS + sg * 8) * 4u, ws);
        cpasync16(wsb + (unsigned)(s * 128 * GS + row * GS + sg * 8 + 4) * 4u, ws + 4);
        const unsigned* xs = xh + ((size_t)b * NPIX + pixB + row) * 128 + kk / 2 + sg * 8;
        cpasync16(xsb + (unsigned)(s * 128 * GS + row * GS + sg * 8) * 4u, xs);
        cpasync16(xsb + (unsigned)(s * 128 * GS + row * GS + sg * 8 + 4) * 4u, xs + 4);
        asm volatile("cp.async.commit_group;");
    };

    fill(0, 0);
    for (int ch = 0; ch < 8; ++ch) {
        if (ch < 7) {
            fill((ch + 1) * 32, (ch + 1) & 1);
            asm volatile("cp.async.wait_group 1;");
        } else {
            asm volatile("cp.async.wait_group 0;");
        }
        __syncthreads();
        const unsigned* w0 = &sW[ch & 1][0];
        const unsigned* x0 = &sX[ch & 1][0];
#pragma unroll
        for (int ks = 0; ks < 2; ks++) {
            unsigned bb[8][2];
#pragma unroll
            for (int nt = 0; nt < 8; nt++) {
                bb[nt][0] = x0[(64 * nh + 8 * nt + g) * GS + 8 * ks + c];
                bb[nt][1] = x0[(64 * nh + 8 * nt + g) * GS + 8 * ks + c + 4];
            }
#pragma unroll
            for (int mt = 0; mt < 2; mt++) {
                int mrow = 32 * head + 16 * mt;
                unsigned a0 = w0[(mrow + g) * GS + 8 * ks + c];
                unsigned a1 = w0[(mrow + 8 + g) * GS + 8 * ks + c];
                unsigned a2 = w0[(mrow + g) * GS + 8 * ks + c + 4];
                unsigned a3 = w0[(mrow + 8 + g) * GS + 8 * ks + c + 4];
#pragma unroll
                for (int nt = 0; nt < 8; nt++)
                    mma_f16(acc[mt][nt], a0, a1, a2, a3, bb[nt][0], bb[nt][1]);
            }
        }
        __syncthreads();
    }

    if (sel < 2) {
        unsigned* dst = sel ? kh : qh;
        const float scale = (sel == 0) ? 14.426950408889634f : 1.f;
#pragma unroll
        for (int nt = 0; nt < 8; nt++) {
#pragma unroll
            for (int par = 0; par < 2; par++) {
                float ss = acc[0][nt][par] * acc[0][nt][par]
                         + acc[0][nt][par + 2] * acc[0][nt][par + 2]
                         + acc[1][nt][par] * acc[1][nt][par]
                         + acc[1][nt][par + 2] * acc[1][nt][par + 2];
                ss += __shfl_xor_sync(0xffffffffu, ss, 4);
                ss += __shfl_xor_sync(0xffffffffu, ss, 8);
                ss += __shfl_xor_sync(0xffffffffu, ss, 16);
                float inv = scale / fmaxf(sqrtf(ss), 1e-12f);
                size_t base = ((size_t)(b * 4 + head) * NPIX + pix0 + 8 * nt + 2 * c + par) * 16;
#pragma unroll
                for (int mt = 0; mt < 2; mt++) {
                    float v0 = acc[mt][nt][par] * inv;
                    float v1 = acc[mt][nt][par + 2] * inv;
                    float w0 = __shfl_xor_sync(0xffffffffu, v0, 4);
                    float w1 = __shfl_xor_sync(0xffffffffu, v1, 4);
                    if (!(g & 1)) {
                        dst[base + 8 * mt + (g >> 1)]     = packh2(w0, v0);
                        dst[base + 8 * mt + 4 + (g >> 1)] = packh2(w1, v1);
                    }
                }
            }
        }
    } else {
#pragma unroll
        for (int mt = 0; mt < 2; mt++)
#pragma unroll
            for (int dh = 0; dh < 2; dh++) {
                int d = 16 * mt + 8 * dh + g;
#pragma unroll
                for (int nt = 0; nt < 8; nt++) {
                    unsigned pv = packh2(acc[mt][nt][2 * dh + 1], acc[mt][nt][2 * dh]);
                    vh[((size_t)(b * 4 + head) * 32 + d) * (NPIX / 2) + (pix0 + 8 * nt) / 2 + c] = pv;
                }
            }
    }
}

// ---------------------------------------------------------------------------
// Split-fp16 output projection: y = whi@xhi + whi@xlo + wlo@xhi (+bias), fp32 acc.
// BM=128, BN=64 pixels, K=128 (8 chunks of 16), 128 threads.
// ---------------------------------------------------------------------------
#define GO 12
__global__ __launch_bounds__(128) void gemm_out_h(
    const unsigned* __restrict__ whi, const unsigned* __restrict__ wlo,
    const unsigned* __restrict__ xhi, const unsigned* __restrict__ xlo,
    float* __restrict__ out, const float* __restrict__ bias)
{
    __shared__ unsigned sWh[2][128 * GO], sWl[2][128 * GO];
    __shared__ unsigned sXh[2][64 * GO],  sXl[2][64 * GO];

    const int b = blockIdx.z;
    const int row0 = blockIdx.y * 128, pix0 = blockIdx.x * 64;
    const int tid = threadIdx.x, lane = tid & 31, warp = tid >> 5;
    const int g = lane >> 2, c = lane & 3;
    const unsigned whb = (unsigned)__cvta_generic_to_shared(&sWh[0][0]);
    const unsigned wlb = (unsigned)__cvta_generic_to_shared(&sWl[0][0]);
    const unsigned xhb = (unsigned)__cvta_generic_to_shared(&sXh[0][0]);
    const unsigned xlb = (unsigned)__cvta_generic_to_shared(&sXl[0][0]);
    const unsigned* xhs = xhi + (size_t)b * NPIX * 64;
    const unsigned* xls = xlo + (size_t)b * NPIX * 64;
    float* outb = out + (size_t)b * 256 * NPIX;

    float acc[2][8][4];
#pragma unroll
    for (int mt = 0; mt < 2; mt++)
#pragma unroll
        for (int nt = 0; nt < 8; nt++)
#pragma unroll
            for (int r = 0; r < 4; r++) acc[mt][nt][r] = 0.f;

    auto fill = [&](int kk, int s) {
        const unsigned* wh_ = whi + (size_t)(row0 + tid) * 64 + kk / 2;
        const unsigned* wl_ = wlo + (size_t)(row0 + tid) * 64 + kk / 2;
        cpasync16(whb + (unsigned)(s * 128 * GO + tid * GO) * 4u, wh_);
        cpasync16(whb + (unsigned)(s * 128 * GO + tid * GO + 4) * 4u, wh_ + 4);
        cpasync16(wlb + (unsigned)(s * 128 * GO + tid * GO) * 4u, wl_);
        cpasync16(wlb + (unsigned)(s * 128 * GO + tid * GO + 4) * 4u, wl_ + 4);
        int row = tid >> 1, sg = tid & 1;
        cpasync16(xhb + (unsigned)(s * 64 * GO + row * GO + sg * 4) * 4u,
                  xhs + (size_t)(pix0 + row) * 64 + kk / 2 + sg * 4);
        cpasync16(xlb + (unsigned)(s * 64 * GO + row * GO + sg * 4) * 4u,
                  xls + (size_t)(pix0 + row) * 64 + kk / 2 + sg * 4);
        asm volatile("cp.async.commit_group;");
    };

    fill(0, 0);
    for (int ch = 0; ch < 8; ++ch) {
        if (ch < 7) {
            fill((ch + 1) * 16, (ch + 1) & 1);
            asm volatile("cp.async.wait_group 1;");
        } else {
            asm volatile("cp.async.wait_group 0;");
        }
        __syncthreads();
        const int s = ch & 1;
        const unsigned* wh0 = &sWh[s][0];
        const unsigned* wl0 = &sWl[s][0];
        const unsigned* xh0 = &sXh[s][0];
        const unsigned* xl0 = &sXl[s][0];
        unsigned bh[8][2], bl[8][2];
#pragma unroll
        for (int nt = 0; nt < 8; nt++) {
            bh[nt][0] = xh0[(8 * nt + g) * GO + c];
            bh[nt][1] = xh0[(8 * nt + g) * GO + c + 4];
            bl[nt][0] = xl0[(8 * nt + g) * GO + c];
            bl[nt][1] = xl0[(8 * nt + g) * GO + c + 4];
        }
#pragma unroll
        for (int mt = 0; mt < 2; mt++) {
            int mrow = 32 * warp + 16 * mt;
            unsigned ah0 = wh0[(mrow + g) * GO + c],     ah1 = wh0[(mrow + 8 + g) * GO + c];
            unsigned ah2 = wh0[(mrow + g) * GO + c + 4], ah3 = wh0[(mrow + 8 + g) * GO + c + 4];
            unsigned al0 = wl0[(mrow + g) * GO + c],     al1 = wl0[(mrow + 8 + g) * GO + c];
            unsigned al2 = wl0[(mrow + g) * GO + c + 4], al3 = wl0[(mrow + 8 + g) * GO + c + 4];
#pragma unroll
            for (int nt = 0; nt < 8; nt++) {
                mma_f16(acc[mt][nt], ah0, ah1, ah2, ah3, bh[nt][0], bh[nt][1]);
                mma_f16(acc[mt][nt], ah0, ah1, ah2, ah3, bl[nt][0], bl[nt][1]);
                mma_f16(acc[mt][nt], al0, al1, al2, al3, bh[nt][0], bh[nt][1]);
            }
        }
        __syncthreads();
    }

#pragma unroll
    for (int mt = 0; mt < 2; mt++) {
        int r0 = row0 + 32 * warp + 16 * mt + g;
        float b0 = bias[r0], b1 = bias[r0 + 8];
#pragma unroll
        for (int nt = 0; nt < 8; nt++) {
            int col = pix0 + 8 * nt + 2 * c;
            *(float2*)&outb[(size_t)r0 * NPIX + col] =
                make_float2(acc[mt][nt][0] + b0, acc[mt][nt][1] + b0);
            *(float2*)&outb[(size_t)(r0 + 8) * NPIX + col] =
                make_float2(acc[mt][nt][2] + b1, acc[mt][nt][3] + b1);
        }
    }
}

// ---------------------------------------------------------------------------
// fp16 flash attention (unchanged core); epilogue emits split hi/lo fp16
// transposed [pix][k-pairs] for the out-projection.
// ---------------------------------------------------------------------------
#define SKH 20
#define SVH 36
#define STAGE (64 * SKH + 32 * SVH)

__global__ __launch_bounds__(128, 4) void flash_h_kernel(
    const unsigned* __restrict__ qh, const unsigned* __restrict__ kh,
    const unsigned* __restrict__ vh, unsigned* __restrict__ aohi,
    unsigned* __restrict__ aolo)
{
    __shared__ unsigned sm[3 * STAGE];
    __shared__ float lw[4][32];

    const int tid = threadIdx.x, lane = tid & 31, warp = tid >> 5;
    const int g = lane >> 2, c = lane & 3;
    const int bh = blockIdx.y, b = bh >> 2, h = bh & 3;
    const int qw = blockIdx.x * 128 + warp * 32;

    const unsigned* qbh = qh + (size_t)bh * NPIX * 16;
    const unsigned* kbh = kh + (size_t)bh * NPIX * 16;
    const unsigned* vbh = vh + (size_t)bh * 32 * (NPIX / 2);
    const unsigned sbase = (unsigned)__cvta_generic_to_shared(sm);

    unsigned bq[2][4][2];
#pragma unroll
    for (int n = 0; n < 4; n++) {
        const unsigned* qq = qbh + (size_t)(qw + 8 * n + g) * 16;
#pragma unroll
        for (int ks = 0; ks < 2; ks++) {
            bq[ks][n][0] = qq[8 * ks + c];
            bq[ks][n][1] = qq[8 * ks + c + 4];
        }
    }

    float O[2][4][4];
    float lrun[4][2];
#pragma unroll
    for (int mq = 0; mq < 2; mq++)
#pragma unroll
        for (int nd = 0; nd < 4; nd++)
#pragma unroll
            for (int r = 0; r < 4; r++) O[mq][nd][r] = 0.f;
#pragma unroll
    for (int n = 0; n < 4; n++) { lrun[n][0] = 0.f; lrun[n][1] = 0.f; }

    auto fill = [&](int it, int s) {
        unsigned base = sbase + (unsigned)(s * STAGE) * 4u;
        int j0 = it * 64;
#pragma unroll
        for (int r = 0; r < 2; r++) {
            int id = tid + r * 128;
            int row = id >> 2, j = id & 3;
            cpasync16(base + (unsigned)(row * SKH + 4 * j) * 4u,
                      kbh + (size_t)(j0 + row) * 16 + 4 * j);
            int d = id >> 3, jj = id & 7;
            cpasync16(base + (unsigned)(64 * SKH + d * SVH + 4 * jj) * 4u,
                      vbh + (size_t)d * (NPIX / 2) + j0 / 2 + 4 * jj);
        }
        asm volatile("cp.async.commit_group;");
    };

    fill(0, 0);
    fill(1, 1);

    int stage = 0;
    for (int it = 0; it < 64; ++it) {
        if (it < 62) asm volatile("cp.async.wait_group 1;");
        else         asm volatile("cp.async.wait_group 0;");
        __syncthreads();
        if (it < 62) {
            int s2 = stage + 2; if (s2 >= 3) s2 -= 3;
            fill(it + 2, s2);
        }

        const unsigned* skh = sm + stage * STAGE;
        const unsigned* svh = skh + 64 * SKH;

#pragma unroll
        for (int m = 0; m < 4; m++) {
            float acc[4][4];
#pragma unroll
            for (int n = 0; n < 4; n++)
#pragma unroll
                for (int r = 0; r < 4; r++) acc[n][r] = 0.f;
#pragma unroll
            for (int ks = 0; ks < 2; ks++) {
                unsigned a0 = skh[(16 * m + g) * SKH + 8 * ks + c];
                unsigned a1 = skh[(16 * m + 8 + g) * SKH + 8 * ks + c];
                unsigned a2 = skh[(16 * m + g) * SKH + 8 * ks + c + 4];
                unsigned a3 = skh[(16 * m + 8 + g) * SKH + 8 * ks + c + 4];
#pragma unroll
                for (int n = 0; n < 4; n++)
                    mma_f16(acc[n], a0, a1, a2, a3, bq[ks][n][0], bq[ks][n][1]);
            }
            unsigned t0[4], t1[4];
#pragma unroll
            for (int n = 0; n < 4; n++) {
                unsigned e01 = h2exp2(packh2(acc[n][1], acc[n][0]));
                unsigned e23 = h2exp2(packh2(acc[n][3], acc[n][2]));
                __half2 hs = __hadd2(*(__half2*)&e01, *(__half2*)&e23);
                lrun[n][0] += __low2float(hs);
                lrun[n][1] += __high2float(hs);
                t0[n] = movm(e01);
                t1[n] = movm(e23);
            }
#pragma unroll
            for (int nd = 0; nd < 4; nd++) {
                unsigned b0 = svh[(8 * nd + g) * SVH + 8 * m + c];
                unsigned b1 = svh[(8 * nd + g) * SVH + 8 * m + c + 4];
                mma_f16(O[0][nd], t0[0], t0[1], t1[0], t1[1], b0, b1);
                mma_f16(O[1][nd], t0[2], t0[3], t1[2], t1[3], b0, b1);
            }
        }
        if (++stage == 3) stage = 0;
    }

#pragma unroll
    for (int n = 0; n < 4; n++)
#pragma unroll
        for (int p = 0; p < 2; p++) {
            float l = lrun[n][p];
            l += __shfl_xor_sync(0xffffffffu, l, 4);
            l += __shfl_xor_sync(0xffffffffu, l, 8);
            l += __shfl_xor_sync(0xffffffffu, l, 16);
            lrun[n][p] = l;
        }
    if (g == 0) {
#pragma unroll
        for (int n = 0; n < 4; n++) {
            lw[warp][8 * n + 2 * c]     = lrun[n][0];
            lw[warp][8 * n + 2 * c + 1] = lrun[n][1];
        }
    }
    __syncwarp();
    float linv[2][2];
#pragma unroll
    for (int mq = 0; mq < 2; mq++) {
        linv[mq][0] = 1.f / lw[warp][16 * mq + g];
        linv[mq][1] = 1.f / lw[warp][16 * mq + 8 + g];
    }

    unsigned* aoh = aohi + (size_t)b * NPIX * 64;
    unsigned* aol = aolo + (size_t)b * NPIX * 64;
#pragma unroll
    for (int mq = 0; mq < 2; mq++)
#pragma unroll
        for (int nd = 0; nd < 4; nd++) {
            int q0 = qw + 16 * mq + g;
            int pr = h * 16 + 4 * nd + c;
            float o0 = O[mq][nd][0] * linv[mq][0];
            float o1 = O[mq][nd][1] * linv[mq][0];
            __half h0 = __float2half_rn(o0), h1 = __float2half_rn(o1);
            aoh[(size_t)q0 * 64 + pr] =
                (unsigned)__half_as_ushort(h0) | ((unsigned)__half_as_ushort(h1) << 16);
            aol[(size_t)q0 * 64 + pr] =
                packh2(o1 - __half2float(h1), o0 - __half2float(h0));
            float o2 = O[mq][nd][2] * linv[mq][1];
            float o3 = O[mq][nd][3] * linv[mq][1];
            __half h2 = __float2half_rn(o2), h3 = __float2half_rn(o3);
            aoh[(size_t)(q0 + 8) * 64 + pr] =
                (unsigned)__half_as_ushort(h2) | ((unsigned)__half_as_ushort(h3) << 16);
            aol[(size_t)(q0 + 8) * 64 + pr] =
                packh2(o3 - __half2float(h3), o2 - __half2float(h2));
        }
}

// ---------------------------------------------------------------------------
extern "C" void kernel_launch(void* const* d_in, const int* in_sizes, int n_in,
                              void* d_out, int out_size)
{
    const float* x     = (const float*)d_in[0];
    const float* w_qkv = (const float*)d_in[1];
    const float* w_out = (const float*)d_in[2];
    const float* b_out = (const float*)d_in[3];
    float* out = (float*)d_out;

    static unsigned *qh = nullptr, *kh = nullptr, *vh = nullptr, *wh = nullptr, *xh = nullptr;
    static unsigned *w2hi = nullptr, *w2lo = nullptr, *aohi = nullptr, *aolo = nullptr;
    if (!qh) {
        cudaGetSymbolAddress((void**)&qh,   g_qh);
        cudaGetSymbolAddress((void**)&kh,   g_kh);
        cudaGetSymbolAddress((void**)&vh,   g_vh);
        cudaGetSymbolAddress((void**)&wh,   g_wh);
        cudaGetSymbolAddress((void**)&xh,   g_xh);
        cudaGetSymbolAddress((void**)&w2hi, g_w2hi);
        cudaGetSymbolAddress((void**)&w2lo, g_w2lo);
        cudaGetSymbolAddress((void**)&aohi, g_aohi);
        cudaGetSymbolAddress((void**)&aolo, g_aolo);
    }

    wcvt_kernel<<<192, 256>>>(w_qkv, wh);
    wsplit_kernel<<<64, 256>>>(w_out, w2hi, w2lo);
    xcvt_kernel<<<dim3(NPIX / 64, 256 / 64, NB), 256>>>(x, xh);

    dim3 g1(NPIX / 128, 3, NB);
    gemm_qkv_h<<<g1, 256>>>(wh, xh, qh, kh, vh);

    dim3 g3(NPIX / 128, 16);
    flash_h_kernel<<<g3, 128>>>(qh, kh, vh, aohi, aolo);

    dim3 g4(NPIX / 64, 2, NB);
    gemm_out_h<<<g4, 128>>>(w2hi, w2lo, aohi, aolo, out, b_out);
}

// round 13
// speedup vs baseline: 8.4357x; 1.0903x over previous
#include <cuda_runtime.h>
#include <cuda_fp16.h>
#include <cstdint>
#include <math.h>

#define NPIX 4096
#define NB 4
#define NHEADS 4
#define CIN 256
#define HID 128

__device__ unsigned g_qh[(size_t)16 * NPIX * 16];
__device__ unsigned g_kh[(size_t)16 * NPIX * 16];
__device__ unsigned g_vh[(size_t)16 * 32 * (NPIX / 2)];
__device__ unsigned g_wh[384 * 128];
__device__ unsigned g_xh[(size_t)NB * NPIX * 128];
__device__ unsigned g_w2hi[256 * 64], g_w2lo[256 * 64];
__device__ unsigned g_aohi[(size_t)NB * NPIX * 64];
__device__ unsigned g_aolo[(size_t)NB * NPIX * 64];

__device__ __forceinline__ void cpasync16(unsigned dst, const void* src) {
    asm volatile("cp.async.ca.shared.global [%0], [%1], 16;" :: "r"(dst), "l"(src));
}
__device__ __forceinline__ unsigned packh2(float hi, float lo) {
    unsigned r; asm("cvt.rn.f16x2.f32 %0, %1, %2;" : "=r"(r) : "f"(hi), "f"(lo)); return r;
}
__device__ __forceinline__ unsigned h2exp2(unsigned x) {
    unsigned r; asm("ex2.approx.f16x2 %0, %1;" : "=r"(r) : "r"(x)); return r;
}
__device__ __forceinline__ unsigned movm(unsigned x) {
    unsigned r; asm("movmatrix.sync.aligned.m8n8.trans.b16 %0, %1;" : "=r"(r) : "r"(x)); return r;
}
__device__ __forceinline__ void ldm4(unsigned* r, unsigned a) {
    asm volatile("ldmatrix.sync.aligned.m8n8.x4.shared.b16 {%0,%1,%2,%3}, [%4];"
                 : "=r"(r[0]), "=r"(r[1]), "=r"(r[2]), "=r"(r[3]) : "r"(a));
}
__device__ __forceinline__ void ldm2(unsigned* r, unsigned a) {
    asm volatile("ldmatrix.sync.aligned.m8n8.x2.shared.b16 {%0,%1}, [%2];"
                 : "=r"(r[0]), "=r"(r[1]) : "r"(a));
}
__device__ __forceinline__ void mma_f16(float* d, unsigned a0, unsigned a1,
                                        unsigned a2, unsigned a3, unsigned b0, unsigned b1) {
    asm volatile("mma.sync.aligned.m16n8k16.row.col.f32.f16.f16.f32 "
                 "{%0,%1,%2,%3}, {%4,%5,%6,%7}, {%8,%9}, {%0,%1,%2,%3};"
                 : "+f"(d[0]), "+f"(d[1]), "+f"(d[2]), "+f"(d[3])
                 : "r"(a0), "r"(a1), "r"(a2), "r"(a3), "r"(b0), "r"(b1));
}

// ---------------- converters ----------------
__global__ void wcvt_kernel(const float* __restrict__ w, unsigned* __restrict__ wh)
{
    int i = blockIdx.x * 256 + threadIdx.x;
    wh[i] = packh2(w[2 * i + 1], w[2 * i]);
}
__global__ void wsplit_kernel(const float* __restrict__ w,
                              unsigned* __restrict__ whi, unsigned* __restrict__ wlo)
{
    int i = blockIdx.x * 256 + threadIdx.x;
    float a = w[2 * i], bb = w[2 * i + 1];
    __half ha = __float2half_rn(a), hb = __float2half_rn(bb);
    whi[i] = (unsigned)__half_as_ushort(ha) | ((unsigned)__half_as_ushort(hb) << 16);
    wlo[i] = packh2(bb - __half2float(hb), a - __half2float(ha));
}
__global__ __launch_bounds__(256) void xcvt_kernel(const float* __restrict__ x,
                                                   unsigned* __restrict__ xh)
{
    __shared__ float t[64][65];
    const int pix0 = blockIdx.x * 64, k0 = blockIdx.y * 64, b = blockIdx.z;
    const int tid = threadIdx.x;
#pragma unroll
    for (int j = 0; j < 16; j++) {
        int row = j * 4 + (tid >> 6), col = tid & 63;
        t[row][col] = x[((size_t)b * 256 + k0 + row) * NPIX + pix0 + col];
    }
    __syncthreads();
    int p = tid >> 2, seg = tid & 3;
    unsigned u[8];
#pragma unroll
    for (int j = 0; j < 8; j++)
        u[j] = packh2(t[seg * 16 + 2 * j + 1][p], t[seg * 16 + 2 * j][p]);
    unsigned* dst = xh + ((size_t)b * NPIX + pix0 + p) * 128 + k0 / 2 + seg * 8;
    *(uint4*)dst       = make_uint4(u[0], u[1], u[2], u[3]);
    *(uint4*)(dst + 4) = make_uint4(u[4], u[5], u[6], u[7]);
}

// ---------------------------------------------------------------------------
// fp16 QKV GEMM + fused l2norm, ldmatrix fragment loads.
// ---------------------------------------------------------------------------
#define GS 20
__global__ __launch_bounds__(256) void gemm_qkv_h(
    const unsigned* __restrict__ wh, const unsigned* __restrict__ xh,
    unsigned* __restrict__ qh, unsigned* __restrict__ kh, unsigned* __restrict__ vh)
{
    __shared__ unsigned sW[2][128 * GS];
    __shared__ unsigned sX[2][128 * GS];

    const int sel = blockIdx.y, b = blockIdx.z;
    const int pixB = blockIdx.x * 128;
    const int tid = threadIdx.x, lane = tid & 31, warp = tid >> 5;
    const int g = lane >> 2, c = lane & 3;
    const int head = warp & 3, nh = warp >> 2;
    const int pix0 = pixB + nh * 64;
    const unsigned wsb = (unsigned)__cvta_generic_to_shared(&sW[0][0]);
    const unsigned xsb = (unsigned)__cvta_generic_to_shared(&sX[0][0]);
    const unsigned aRow = (unsigned)((lane & 15) * GS + ((lane >> 4) & 1) * 4);
    const unsigned bRow = (unsigned)(((lane & 7) + ((lane >> 4) & 1) * 8) * GS + ((lane >> 3) & 1) * 4);

    float acc[2][8][4];
#pragma unroll
    for (int mt = 0; mt < 2; mt++)
#pragma unroll
        for (int nt = 0; nt < 8; nt++)
#pragma unroll
            for (int r = 0; r < 4; r++) acc[mt][nt][r] = 0.f;

    auto fill = [&](int kk, int s) {
        int row = tid >> 1, sg = tid & 1;
        const unsigned* ws = wh + (size_t)(sel * 128 + row) * 128 + kk / 2 + sg * 8;
        cpasync16(wsb + (unsigned)(s * 128 * GS + row * GS + sg * 8) * 4u, ws);
        cpasync16(wsb + (unsigned)(s * 128 * GS + row * GS + sg * 8 + 4) * 4u, ws + 4);
        const unsigned* xs = xh + ((size_t)b * NPIX + pixB + row) * 128 + kk / 2 + sg * 8;
        cpasync16(xsb + (unsigned)(s * 128 * GS + row * GS + sg * 8) * 4u, xs);
        cpasync16(xsb + (unsigned)(s * 128 * GS + row * GS + sg * 8 + 4) * 4u, xs + 4);
        asm volatile("cp.async.commit_group;");
    };

    fill(0, 0);
    for (int ch = 0; ch < 8; ++ch) {
        if (ch < 7) {
            fill((ch + 1) * 32, (ch + 1) & 1);
            asm volatile("cp.async.wait_group 1;");
        } else {
            asm volatile("cp.async.wait_group 0;");
        }
        __syncthreads();
        unsigned wbase = wsb + (unsigned)((ch & 1) * 128 * GS) * 4u;
        unsigned xbase = xsb + (unsigned)((ch & 1) * 128 * GS) * 4u;
#pragma unroll
        for (int ks = 0; ks < 2; ks++) {
            unsigned bb[8][2];
#pragma unroll
            for (int np = 0; np < 4; np++) {
                unsigned r[4];
                ldm4(r, xbase + ((unsigned)((64 * nh + 16 * np) * GS + 8 * ks) + bRow) * 4u);
                bb[2*np][0] = r[0]; bb[2*np][1] = r[1];
                bb[2*np+1][0] = r[2]; bb[2*np+1][1] = r[3];
            }
#pragma unroll
            for (int mt = 0; mt < 2; mt++) {
                unsigned a[4];
                ldm4(a, wbase + ((unsigned)((32 * head + 16 * mt) * GS + 8 * ks) + aRow) * 4u);
#pragma unroll
                for (int nt = 0; nt < 8; nt++)
                    mma_f16(acc[mt][nt], a[0], a[1], a[2], a[3], bb[nt][0], bb[nt][1]);
            }
        }
        __syncthreads();
    }

    if (sel < 2) {
        unsigned* dst = sel ? kh : qh;
        const float scale = (sel == 0) ? 14.426950408889634f : 1.f;
#pragma unroll
        for (int nt = 0; nt < 8; nt++) {
#pragma unroll
            for (int par = 0; par < 2; par++) {
                float ss = acc[0][nt][par] * acc[0][nt][par]
                         + acc[0][nt][par + 2] * acc[0][nt][par + 2]
                         + acc[1][nt][par] * acc[1][nt][par]
                         + acc[1][nt][par + 2] * acc[1][nt][par + 2];
                ss += __shfl_xor_sync(0xffffffffu, ss, 4);
                ss += __shfl_xor_sync(0xffffffffu, ss, 8);
                ss += __shfl_xor_sync(0xffffffffu, ss, 16);
                float inv = scale / fmaxf(sqrtf(ss), 1e-12f);
                size_t base = ((size_t)(b * 4 + head) * NPIX + pix0 + 8 * nt + 2 * c + par) * 16;
#pragma unroll
                for (int mt = 0; mt < 2; mt++) {
                    float v0 = acc[mt][nt][par] * inv;
                    float v1 = acc[mt][nt][par + 2] * inv;
                    float w0 = __shfl_xor_sync(0xffffffffu, v0, 4);
                    float w1 = __shfl_xor_sync(0xffffffffu, v1, 4);
                    if (!(g & 1)) {
                        dst[base + 8 * mt + (g >> 1)]     = packh2(w0, v0);
                        dst[base + 8 * mt + 4 + (g >> 1)] = packh2(w1, v1);
                    }
                }
            }
        }
    } else {
        // V: fp16 [bh][d][pix-pairs]  (head, NOT warp — round-12 bug)
#pragma unroll
        for (int mt = 0; mt < 2; mt++)
#pragma unroll
            for (int dh = 0; dh < 2; dh++) {
                int d = 16 * mt + 8 * dh + g;
#pragma unroll
                for (int nt = 0; nt < 8; nt++) {
                    unsigned pv = packh2(acc[mt][nt][2 * dh + 1], acc[mt][nt][2 * dh]);
                    vh[((size_t)(b * 4 + head) * 32 + d) * (NPIX / 2) + (pix0 + 8 * nt) / 2 + c] = pv;
                }
            }
    }
}

// ---------------------------------------------------------------------------
// Split-fp16 output projection.
// ---------------------------------------------------------------------------
#define GO 12
__global__ __launch_bounds__(128) void gemm_out_h(
    const unsigned* __restrict__ whi, const unsigned* __restrict__ wlo,
    const unsigned* __restrict__ xhi, const unsigned* __restrict__ xlo,
    float* __restrict__ out, const float* __restrict__ bias)
{
    __shared__ unsigned sWh[2][128 * GO], sWl[2][128 * GO];
    __shared__ unsigned sXh[2][64 * GO],  sXl[2][64 * GO];

    const int b = blockIdx.z;
    const int row0 = blockIdx.y * 128, pix0 = blockIdx.x * 64;
    const int tid = threadIdx.x, lane = tid & 31, warp = tid >> 5;
    const int g = lane >> 2, c = lane & 3;
    const unsigned whb = (unsigned)__cvta_generic_to_shared(&sWh[0][0]);
    const unsigned wlb = (unsigned)__cvta_generic_to_shared(&sWl[0][0]);
    const unsigned xhb = (unsigned)__cvta_generic_to_shared(&sXh[0][0]);
    const unsigned xlb = (unsigned)__cvta_generic_to_shared(&sXl[0][0]);
    const unsigned* xhs = xhi + (size_t)b * NPIX * 64;
    const unsigned* xls = xlo + (size_t)b * NPIX * 64;
    float* outb = out + (size_t)b * 256 * NPIX;

    float acc[2][8][4];
#pragma unroll
    for (int mt = 0; mt < 2; mt++)
#pragma unroll
        for (int nt = 0; nt < 8; nt++)
#pragma unroll
            for (int r = 0; r < 4; r++) acc[mt][nt][r] = 0.f;

    auto fill = [&](int kk, int s) {
        const unsigned* wh_ = whi + (size_t)(row0 + tid) * 64 + kk / 2;
        const unsigned* wl_ = wlo + (size_t)(row0 + tid) * 64 + kk / 2;
        cpasync16(whb + (unsigned)(s * 128 * GO + tid * GO) * 4u, wh_);
        cpasync16(whb + (unsigned)(s * 128 * GO + tid * GO + 4) * 4u, wh_ + 4);
        cpasync16(wlb + (unsigned)(s * 128 * GO + tid * GO) * 4u, wl_);
        cpasync16(wlb + (unsigned)(s * 128 * GO + tid * GO + 4) * 4u, wl_ + 4);
        int row = tid >> 1, sg = tid & 1;
        cpasync16(xhb + (unsigned)(s * 64 * GO + row * GO + sg * 4) * 4u,
                  xhs + (size_t)(pix0 + row) * 64 + kk / 2 + sg * 4);
        cpasync16(xlb + (unsigned)(s * 64 * GO + row * GO + sg * 4) * 4u,
                  xls + (size_t)(pix0 + row) * 64 + kk / 2 + sg * 4);
        asm volatile("cp.async.commit_group;");
    };

    fill(0, 0);
    for (int ch = 0; ch < 8; ++ch) {
        if (ch < 7) {
            fill((ch + 1) * 16, (ch + 1) & 1);
            asm volatile("cp.async.wait_group 1;");
        } else {
            asm volatile("cp.async.wait_group 0;");
        }
        __syncthreads();
        const int s = ch & 1;
        const unsigned* wh0 = &sWh[s][0];
        const unsigned* wl0 = &sWl[s][0];
        const unsigned* xh0 = &sXh[s][0];
        const unsigned* xl0 = &sXl[s][0];
        unsigned bh[8][2], bl[8][2];
#pragma unroll
        for (int nt = 0; nt < 8; nt++) {
            bh[nt][0] = xh0[(8 * nt + g) * GO + c];
            bh[nt][1] = xh0[(8 * nt + g) * GO + c + 4];
            bl[nt][0] = xl0[(8 * nt + g) * GO + c];
            bl[nt][1] = xl0[(8 * nt + g) * GO + c + 4];
        }
#pragma unroll
        for (int mt = 0; mt < 2; mt++) {
            int mrow = 32 * warp + 16 * mt;
            unsigned ah0 = wh0[(mrow + g) * GO + c],     ah1 = wh0[(mrow + 8 + g) * GO + c];
            unsigned ah2 = wh0[(mrow + g) * GO + c + 4], ah3 = wh0[(mrow + 8 + g) * GO + c + 4];
            unsigned al0 = wl0[(mrow + g) * GO + c],     al1 = wl0[(mrow + 8 + g) * GO + c];
            unsigned al2 = wl0[(mrow + g) * GO + c + 4], al3 = wl0[(mrow + 8 + g) * GO + c + 4];
#pragma unroll
            for (int nt = 0; nt < 8; nt++) {
                mma_f16(acc[mt][nt], ah0, ah1, ah2, ah3, bh[nt][0], bh[nt][1]);
                mma_f16(acc[mt][nt], ah0, ah1, ah2, ah3, bl[nt][0], bl[nt][1]);
                mma_f16(acc[mt][nt], al0, al1, al2, al3, bh[nt][0], bh[nt][1]);
            }
        }
        __syncthreads();
    }

#pragma unroll
    for (int mt = 0; mt < 2; mt++) {
        int r0 = row0 + 32 * warp + 16 * mt + g;
        float b0 = bias[r0], b1 = bias[r0 + 8];
#pragma unroll
        for (int nt = 0; nt < 8; nt++) {
            int col = pix0 + 8 * nt + 2 * c;
            *(float2*)&outb[(size_t)r0 * NPIX + col] =
                make_float2(acc[mt][nt][0] + b0, acc[mt][nt][1] + b0);
            *(float2*)&outb[(size_t)(r0 + 8) * NPIX + col] =
                make_float2(acc[mt][nt][2] + b1, acc[mt][nt][3] + b1);
        }
    }
}

// ---------------------------------------------------------------------------
// fp16 flash: ldmatrix K/V fragments; l accumulated via ones-row in V (MMA).
// ---------------------------------------------------------------------------
#define SKH 20
#define SVH 36
#define STAGE (64 * SKH + 40 * SVH)

__global__ __launch_bounds__(128, 4) void flash_h_kernel(
    const unsigned* __restrict__ qh, const unsigned* __restrict__ kh,
    const unsigned* __restrict__ vh, unsigned* __restrict__ aohi,
    unsigned* __restrict__ aolo)
{
    __shared__ unsigned sm[3 * STAGE];

    const int tid = threadIdx.x, lane = tid & 31, warp = tid >> 5;
    const int g = lane >> 2, c = lane & 3;
    const int bh = blockIdx.y, b = bh >> 2, h = bh & 3;
    const int qw = blockIdx.x * 128 + warp * 32;

    const unsigned* qbh = qh + (size_t)bh * NPIX * 16;
    const unsigned* kbh = kh + (size_t)bh * NPIX * 16;
    const unsigned* vbh = vh + (size_t)bh * 32 * (NPIX / 2);
    const unsigned sbase = (unsigned)__cvta_generic_to_shared(sm);
    const unsigned kRow = (unsigned)((lane & 15) * SKH + ((lane >> 4) & 1) * 4);
    const unsigned vRow = (unsigned)(((lane & 7) + ((lane >> 4) & 1) * 8) * SVH + ((lane >> 3) & 1) * 4);
    const unsigned vRow5 = (unsigned)((32 + (lane & 7)) * SVH + ((lane >> 3) & 1) * 4);

    unsigned bq[2][4][2];
#pragma unroll
    for (int n = 0; n < 4; n++) {
        const unsigned* qq = qbh + (size_t)(qw + 8 * n + g) * 16;
#pragma unroll
        for (int ks = 0; ks < 2; ks++) {
            bq[ks][n][0] = qq[8 * ks + c];
            bq[ks][n][1] = qq[8 * ks + c + 4];
        }
    }

    float O[2][4][4];
    float Oex[2][4];
#pragma unroll
    for (int mq = 0; mq < 2; mq++) {
#pragma unroll
        for (int nd = 0; nd < 4; nd++)
#pragma unroll
            for (int r = 0; r < 4; r++) O[mq][nd][r] = 0.f;
#pragma unroll
        for (int r = 0; r < 4; r++) Oex[mq][r] = 0.f;
    }

    auto fill = [&](int it, int s) {
        unsigned base = sbase + (unsigned)(s * STAGE) * 4u;
        int j0 = it * 64;
#pragma unroll
        for (int r = 0; r < 2; r++) {
            int id = tid + r * 128;
            int row = id >> 2, j = id & 3;
            cpasync16(base + (unsigned)(row * SKH + 4 * j) * 4u,
                      kbh + (size_t)(j0 + row) * 16 + 4 * j);
            int d = id >> 3, jj = id & 7;
            cpasync16(base + (unsigned)(64 * SKH + d * SVH + 4 * jj) * 4u,
                      vbh + (size_t)d * (NPIX / 2) + j0 / 2 + 4 * jj);
        }
        asm volatile("cp.async.commit_group;");
    };

    fill(0, 0);
    fill(1, 1);
    // const V rows 32..39 (row 32 = ones) for all 3 stages
    for (int i = tid; i < 3 * 8 * 32; i += 128) {
        int st = i >> 8, rem = i & 255, row = 32 + (rem >> 5), col = rem & 31;
        sm[st * STAGE + 64 * SKH + row * SVH + col] = (row == 32) ? 0x3C003C00u : 0u;
    }

    int stage = 0;
    for (int it = 0; it < 64; ++it) {
        if (it < 62) asm volatile("cp.async.wait_group 1;");
        else         asm volatile("cp.async.wait_group 0;");
        __syncthreads();
        if (it < 62) {
            int s2 = stage + 2; if (s2 >= 3) s2 -= 3;
            fill(it + 2, s2);
        }

        const unsigned kb = sbase + (unsigned)(stage * STAGE) * 4u;
        const unsigned vb = kb + (unsigned)(64 * SKH) * 4u;

#pragma unroll
        for (int m = 0; m < 4; m++) {
            float acc[4][4];
#pragma unroll
            for (int n = 0; n < 4; n++)
#pragma unroll
                for (int r = 0; r < 4; r++) acc[n][r] = 0.f;
#pragma unroll
            for (int ks = 0; ks < 2; ks++) {
                unsigned a[4];
                ldm4(a, kb + ((unsigned)(16 * m * SKH + 8 * ks) + kRow) * 4u);
#pragma unroll
                for (int n = 0; n < 4; n++)
                    mma_f16(acc[n], a[0], a[1], a[2], a[3], bq[ks][n][0], bq[ks][n][1]);
            }
            unsigned t0[4], t1[4];
#pragma unroll
            for (int n = 0; n < 4; n++) {
                t0[n] = movm(h2exp2(packh2(acc[n][1], acc[n][0])));
                t1[n] = movm(h2exp2(packh2(acc[n][3], acc[n][2])));
            }
#pragma unroll
            for (int np = 0; np < 2; np++) {
                unsigned v[4];
                ldm4(v, vb + ((unsigned)(16 * np * SVH + 8 * m) + vRow) * 4u);
                mma_f16(O[0][2*np],   t0[0], t0[1], t1[0], t1[1], v[0], v[1]);
                mma_f16(O[1][2*np],   t0[2], t0[3], t1[2], t1[3], v[0], v[1]);
                mma_f16(O[0][2*np+1], t0[0], t0[1], t1[0], t1[1], v[2], v[3]);
                mma_f16(O[1][2*np+1], t0[2], t0[3], t1[2], t1[3], v[2], v[3]);
            }
            unsigned vx[2];
            ldm2(vx, vb + ((unsigned)(8 * m) + vRow5) * 4u);
            mma_f16(Oex[0], t0[0], t0[1], t1[0], t1[1], vx[0], vx[1]);
            mma_f16(Oex[1], t0[2], t0[3], t1[2], t1[3], vx[0], vx[1]);
        }
        if (++stage == 3) stage = 0;
    }

    // l lives at output column n=0 -> c==0 lane of each g (r0: q row g, r2: q+8)
    float linvq[2], linvq8[2];
#pragma unroll
    for (int mq = 0; mq < 2; mq++) {
        linvq[mq]  = 1.f / __shfl_sync(0xffffffffu, Oex[mq][0], lane & 28);
        linvq8[mq] = 1.f / __shfl_sync(0xffffffffu, Oex[mq][2], lane & 28);
    }

    unsigned* aoh = aohi + (size_t)b * NPIX * 64;
    unsigned* aol = aolo + (size_t)b * NPIX * 64;
#pragma unroll
    for (int mq = 0; mq < 2; mq++)
#pragma unroll
        for (int nd = 0; nd < 4; nd++) {
            int q0 = qw + 16 * mq + g;
            int pr = h * 16 + 4 * nd + c;
            float o0 = O[mq][nd][0] * linvq[mq];
            float o1 = O[mq][nd][1] * linvq[mq];
            __half h0 = __float2half_rn(o0), h1 = __float2half_rn(o1);
            aoh[(size_t)q0 * 64 + pr] =
                (unsigned)__half_as_ushort(h0) | ((unsigned)__half_as_ushort(h1) << 16);
            aol[(size_t)q0 * 64 + pr] =
                packh2(o1 - __half2float(h1), o0 - __half2float(h0));
            float o2 = O[mq][nd][2] * linvq8[mq];
            float o3 = O[mq][nd][3] * linvq8[mq];
            __half h2 = __float2half_rn(o2), h3 = __float2half_rn(o3);
            aoh[(size_t)(q0 + 8) * 64 + pr] =
                (unsigned)__half_as_ushort(h2) | ((unsigned)__half_as_ushort(h3) << 16);
            aol[(size_t)(q0 + 8) * 64 + pr] =
                packh2(o3 - __half2float(h3), o2 - __half2float(h2));
        }
}

// ---------------------------------------------------------------------------
extern "C" void kernel_launch(void* const* d_in, const int* in_sizes, int n_in,
                              void* d_out, int out_size)
{
    const float* x     = (const float*)d_in[0];
    const float* w_qkv = (const float*)d_in[1];
    const float* w_out = (const float*)d_in[2];
    const float* b_out = (const float*)d_in[3];
    float* out = (float*)d_out;

    static unsigned *qh = nullptr, *kh = nullptr, *vh = nullptr, *wh = nullptr, *xh = nullptr;
    static unsigned *w2hi = nullptr, *w2lo = nullptr, *aohi = nullptr, *aolo = nullptr;
    if (!qh) {
        cudaGetSymbolAddress((void**)&qh,   g_qh);
        cudaGetSymbolAddress((void**)&kh,   g_kh);
        cudaGetSymbolAddress((void**)&vh,   g_vh);
        cudaGetSymbolAddress((void**)&wh,   g_wh);
        cudaGetSymbolAddress((void**)&xh,   g_xh);
        cudaGetSymbolAddress((void**)&w2hi, g_w2hi);
        cudaGetSymbolAddress((void**)&w2lo, g_w2lo);
        cudaGetSymbolAddress((void**)&aohi, g_aohi);
        cudaGetSymbolAddress((void**)&aolo, g_aolo);
    }

    wcvt_kernel<<<192, 256>>>(w_qkv, wh);
    wsplit_kernel<<<64, 256>>>(w_out, w2hi, w2lo);
    xcvt_kernel<<<dim3(NPIX / 64, 256 / 64, NB), 256>>>(x, xh);

    dim3 g1(NPIX / 128, 3, NB);
    gemm_qkv_h<<<g1, 256>>>(wh, xh, qh, kh, vh);

    dim3 g3(NPIX / 128, 16);
    flash_h_kernel<<<g3, 128>>>(qh, kh, vh, aohi, aolo);

    dim3 g4(NPIX / 64, 2, NB);
    gemm_out_h<<<g4, 128>>>(w2hi, w2lo, aohi, aolo, out, b_out);
}

// round 14
// speedup vs baseline: 8.6269x; 1.0227x over previous
#include <cuda_runtime.h>
#include <cuda_fp16.h>
#include <cstdint>
#include <math.h>

#define NPIX 4096
#define NB 4
#define NHEADS 4
#define CIN 256
#define HID 128

__device__ unsigned g_qh[(size_t)16 * NPIX * 16];
__device__ unsigned g_kh[(size_t)16 * NPIX * 16];
__device__ unsigned g_vh[(size_t)16 * 32 * (NPIX / 2)];
__device__ unsigned g_wh[384 * 128];
__device__ unsigned g_xh[(size_t)NB * NPIX * 128];
__device__ unsigned g_w2hi[256 * 64], g_w2lo[256 * 64];
__device__ unsigned g_aohi[(size_t)NB * NPIX * 64];
__device__ unsigned g_aolo[(size_t)NB * NPIX * 64];

__device__ __forceinline__ void cpasync16(unsigned dst, const void* src) {
    asm volatile("cp.async.ca.shared.global [%0], [%1], 16;" :: "r"(dst), "l"(src));
}
__device__ __forceinline__ unsigned packh2(float hi, float lo) {
    unsigned r; asm("cvt.rn.f16x2.f32 %0, %1, %2;" : "=r"(r) : "f"(hi), "f"(lo)); return r;
}
__device__ __forceinline__ unsigned h2exp2(unsigned x) {
    unsigned r; asm("ex2.approx.f16x2 %0, %1;" : "=r"(r) : "r"(x)); return r;
}
__device__ __forceinline__ void ldm4(unsigned* r, unsigned a) {
    asm volatile("ldmatrix.sync.aligned.m8n8.x4.shared.b16 {%0,%1,%2,%3}, [%4];"
                 : "=r"(r[0]), "=r"(r[1]), "=r"(r[2]), "=r"(r[3]) : "r"(a));
}
__device__ __forceinline__ void mma_f16(float* d, unsigned a0, unsigned a1,
                                        unsigned a2, unsigned a3, unsigned b0, unsigned b1) {
    asm volatile("mma.sync.aligned.m16n8k16.row.col.f32.f16.f16.f32 "
                 "{%0,%1,%2,%3}, {%4,%5,%6,%7}, {%8,%9}, {%0,%1,%2,%3};"
                 : "+f"(d[0]), "+f"(d[1]), "+f"(d[2]), "+f"(d[3])
                 : "r"(a0), "r"(a1), "r"(a2), "r"(a3), "r"(b0), "r"(b1));
}

// ---------------- converters ----------------
__global__ void wcvt_kernel(const float* __restrict__ w, unsigned* __restrict__ wh)
{
    int i = blockIdx.x * 256 + threadIdx.x;
    wh[i] = packh2(w[2 * i + 1], w[2 * i]);
}
__global__ void wsplit_kernel(const float* __restrict__ w,
                              unsigned* __restrict__ whi, unsigned* __restrict__ wlo)
{
    int i = blockIdx.x * 256 + threadIdx.x;
    float a = w[2 * i], bb = w[2 * i + 1];
    __half ha = __float2half_rn(a), hb = __float2half_rn(bb);
    whi[i] = (unsigned)__half_as_ushort(ha) | ((unsigned)__half_as_ushort(hb) << 16);
    wlo[i] = packh2(bb - __half2float(hb), a - __half2float(ha));
}
__global__ __launch_bounds__(256) void xcvt_kernel(const float* __restrict__ x,
                                                   unsigned* __restrict__ xh)
{
    __shared__ float t[64][65];
    const int pix0 = blockIdx.x * 64, k0 = blockIdx.y * 64, b = blockIdx.z;
    const int tid = threadIdx.x;
#pragma unroll
    for (int j = 0; j < 16; j++) {
        int row = j * 4 + (tid >> 6), col = tid & 63;
        t[row][col] = x[((size_t)b * 256 + k0 + row) * NPIX + pix0 + col];
    }
    __syncthreads();
    int p = tid >> 2, seg = tid & 3;
    unsigned u[8];
#pragma unroll
    for (int j = 0; j < 8; j++)
        u[j] = packh2(t[seg * 16 + 2 * j + 1][p], t[seg * 16 + 2 * j][p]);
    unsigned* dst = xh + ((size_t)b * NPIX + pix0 + p) * 128 + k0 / 2 + seg * 8;
    *(uint4*)dst       = make_uint4(u[0], u[1], u[2], u[3]);
    *(uint4*)(dst + 4) = make_uint4(u[4], u[5], u[6], u[7]);
}

// ---------------------------------------------------------------------------
// fp16 QKV GEMM + fused l2norm (unchanged from round 13).
// ---------------------------------------------------------------------------
#define GS 20
__global__ __launch_bounds__(256) void gemm_qkv_h(
    const unsigned* __restrict__ wh, const unsigned* __restrict__ xh,
    unsigned* __restrict__ qh, unsigned* __restrict__ kh, unsigned* __restrict__ vh)
{
    __shared__ unsigned sW[2][128 * GS];
    __shared__ unsigned sX[2][128 * GS];

    const int sel = blockIdx.y, b = blockIdx.z;
    const int pixB = blockIdx.x * 128;
    const int tid = threadIdx.x, lane = tid & 31, warp = tid >> 5;
    const int g = lane >> 2, c = lane & 3;
    const int head = warp & 3, nh = warp >> 2;
    const int pix0 = pixB + nh * 64;
    const unsigned wsb = (unsigned)__cvta_generic_to_shared(&sW[0][0]);
    const unsigned xsb = (unsigned)__cvta_generic_to_shared(&sX[0][0]);
    const unsigned aRow = (unsigned)((lane & 15) * GS + ((lane >> 4) & 1) * 4);
    const unsigned bRow = (unsigned)(((lane & 7) + ((lane >> 4) & 1) * 8) * GS + ((lane >> 3) & 1) * 4);

    float acc[2][8][4];
#pragma unroll
    for (int mt = 0; mt < 2; mt++)
#pragma unroll
        for (int nt = 0; nt < 8; nt++)
#pragma unroll
            for (int r = 0; r < 4; r++) acc[mt][nt][r] = 0.f;

    auto fill = [&](int kk, int s) {
        int row = tid >> 1, sg = tid & 1;
        const unsigned* ws = wh + (size_t)(sel * 128 + row) * 128 + kk / 2 + sg * 8;
        cpasync16(wsb + (unsigned)(s * 128 * GS + row * GS + sg * 8) * 4u, ws);
        cpasync16(wsb + (unsigned)(s * 128 * GS + row * GS + sg * 8 + 4) * 4u, ws + 4);
        const unsigned* xs = xh + ((size_t)b * NPIX + pixB + row) * 128 + kk / 2 + sg * 8;
        cpasync16(xsb + (unsigned)(s * 128 * GS + row * GS + sg * 8) * 4u, xs);
        cpasync16(xsb + (unsigned)(s * 128 * GS + row * GS + sg * 8 + 4) * 4u, xs + 4);
        asm volatile("cp.async.commit_group;");
    };

    fill(0, 0);
    for (int ch = 0; ch < 8; ++ch) {
        if (ch < 7) {
            fill((ch + 1) * 32, (ch + 1) & 1);
            asm volatile("cp.async.wait_group 1;");
        } else {
            asm volatile("cp.async.wait_group 0;");
        }
        __syncthreads();
        unsigned wbase = wsb + (unsigned)((ch & 1) * 128 * GS) * 4u;
        unsigned xbase = xsb + (unsigned)((ch & 1) * 128 * GS) * 4u;
#pragma unroll
        for (int ks = 0; ks < 2; ks++) {
            unsigned bb[8][2];
#pragma unroll
            for (int np = 0; np < 4; np++) {
                unsigned r[4];
                ldm4(r, xbase + ((unsigned)((64 * nh + 16 * np) * GS + 8 * ks) + bRow) * 4u);
                bb[2*np][0] = r[0]; bb[2*np][1] = r[1];
                bb[2*np+1][0] = r[2]; bb[2*np+1][1] = r[3];
            }
#pragma unroll
            for (int mt = 0; mt < 2; mt++) {
                unsigned a[4];
                ldm4(a, wbase + ((unsigned)((32 * head + 16 * mt) * GS + 8 * ks) + aRow) * 4u);
#pragma unroll
                for (int nt = 0; nt < 8; nt++)
                    mma_f16(acc[mt][nt], a[0], a[1], a[2], a[3], bb[nt][0], bb[nt][1]);
            }
        }
        __syncthreads();
    }

    if (sel < 2) {
        unsigned* dst = sel ? kh : qh;
        const float scale = (sel == 0) ? 14.426950408889634f : 1.f;
#pragma unroll
        for (int nt = 0; nt < 8; nt++) {
#pragma unroll
            for (int par = 0; par < 2; par++) {
                float ss = acc[0][nt][par] * acc[0][nt][par]
                         + acc[0][nt][par + 2] * acc[0][nt][par + 2]
                         + acc[1][nt][par] * acc[1][nt][par]
                         + acc[1][nt][par + 2] * acc[1][nt][par + 2];
                ss += __shfl_xor_sync(0xffffffffu, ss, 4);
                ss += __shfl_xor_sync(0xffffffffu, ss, 8);
                ss += __shfl_xor_sync(0xffffffffu, ss, 16);
                float inv = scale / fmaxf(sqrtf(ss), 1e-12f);
                size_t base = ((size_t)(b * 4 + head) * NPIX + pix0 + 8 * nt + 2 * c + par) * 16;
#pragma unroll
                for (int mt = 0; mt < 2; mt++) {
                    float v0 = acc[mt][nt][par] * inv;
                    float v1 = acc[mt][nt][par + 2] * inv;
                    float w0 = __shfl_xor_sync(0xffffffffu, v0, 4);
                    float w1 = __shfl_xor_sync(0xffffffffu, v1, 4);
                    if (!(g & 1)) {
                        dst[base + 8 * mt + (g >> 1)]     = packh2(w0, v0);
                        dst[base + 8 * mt + 4 + (g >> 1)] = packh2(w1, v1);
                    }
                }
            }
        }
    } else {
#pragma unroll
        for (int mt = 0; mt < 2; mt++)
#pragma unroll
            for (int dh = 0; dh < 2; dh++) {
                int d = 16 * mt + 8 * dh + g;
#pragma unroll
                for (int nt = 0; nt < 8; nt++) {
                    unsigned pv = packh2(acc[mt][nt][2 * dh + 1], acc[mt][nt][2 * dh]);
                    vh[((size_t)(b * 4 + head) * 32 + d) * (NPIX / 2) + (pix0 + 8 * nt) / 2 + c] = pv;
                }
            }
    }
}

// ---------------------------------------------------------------------------
// Split-fp16 output projection (unchanged).
// ---------------------------------------------------------------------------
#define GO 12
__global__ __launch_bounds__(128) void gemm_out_h(
    const unsigned* __restrict__ whi, const unsigned* __restrict__ wlo,
    const unsigned* __restrict__ xhi, const unsigned* __restrict__ xlo,
    float* __restrict__ out, const float* __restrict__ bias)
{
    __shared__ unsigned sWh[2][128 * GO], sWl[2][128 * GO];
    __shared__ unsigned sXh[2][64 * GO],  sXl[2][64 * GO];

    const int b = blockIdx.z;
    const int row0 = blockIdx.y * 128, pix0 = blockIdx.x * 64;
    const int tid = threadIdx.x, lane = tid & 31, warp = tid >> 5;
    const int g = lane >> 2, c = lane & 3;
    const unsigned whb = (unsigned)__cvta_generic_to_shared(&sWh[0][0]);
    const unsigned wlb = (unsigned)__cvta_generic_to_shared(&sWl[0][0]);
    const unsigned xhb = (unsigned)__cvta_generic_to_shared(&sXh[0][0]);
    const unsigned xlb = (unsigned)__cvta_generic_to_shared(&sXl[0][0]);
    const unsigned* xhs = xhi + (size_t)b * NPIX * 64;
    const unsigned* xls = xlo + (size_t)b * NPIX * 64;
    float* outb = out + (size_t)b * 256 * NPIX;

    float acc[2][8][4];
#pragma unroll
    for (int mt = 0; mt < 2; mt++)
#pragma unroll
        for (int nt = 0; nt < 8; nt++)
#pragma unroll
            for (int r = 0; r < 4; r++) acc[mt][nt][r] = 0.f;

    auto fill = [&](int kk, int s) {
        const unsigned* wh_ = whi + (size_t)(row0 + tid) * 64 + kk / 2;
        const unsigned* wl_ = wlo + (size_t)(row0 + tid) * 64 + kk / 2;
        cpasync16(whb + (unsigned)(s * 128 * GO + tid * GO) * 4u, wh_);
        cpasync16(whb + (unsigned)(s * 128 * GO + tid * GO + 4) * 4u, wh_ + 4);
        cpasync16(wlb + (unsigned)(s * 128 * GO + tid * GO) * 4u, wl_);
        cpasync16(wlb + (unsigned)(s * 128 * GO + tid * GO + 4) * 4u, wl_ + 4);
        int row = tid >> 1, sg = tid & 1;
        cpasync16(xhb + (unsigned)(s * 64 * GO + row * GO + sg * 4) * 4u,
                  xhs + (size_t)(pix0 + row) * 64 + kk / 2 + sg * 4);
        cpasync16(xlb + (unsigned)(s * 64 * GO + row * GO + sg * 4) * 4u,
                  xls + (size_t)(pix0 + row) * 64 + kk / 2 + sg * 4);
        asm volatile("cp.async.commit_group;");
    };

    fill(0, 0);
    for (int ch = 0; ch < 8; ++ch) {
        if (ch < 7) {
            fill((ch + 1) * 16, (ch + 1) & 1);
            asm volatile("cp.async.wait_group 1;");
        } else {
            asm volatile("cp.async.wait_group 0;");
        }
        __syncthreads();
        const int s = ch & 1;
        const unsigned* wh0 = &sWh[s][0];
        const unsigned* wl0 = &sWl[s][0];
        const unsigned* xh0 = &sXh[s][0];
        const unsigned* xl0 = &sXl[s][0];
        unsigned bh[8][2], bl[8][2];
#pragma unroll
        for (int nt = 0; nt < 8; nt++) {
            bh[nt][0] = xh0[(8 * nt + g) * GO + c];
            bh[nt][1] = xh0[(8 * nt + g) * GO + c + 4];
            bl[nt][0] = xl0[(8 * nt + g) * GO + c];
            bl[nt][1] = xl0[(8 * nt + g) * GO + c + 4];
        }
#pragma unroll
        for (int mt = 0; mt < 2; mt++) {
            int mrow = 32 * warp + 16 * mt;
            unsigned ah0 = wh0[(mrow + g) * GO + c],     ah1 = wh0[(mrow + 8 + g) * GO + c];
            unsigned ah2 = wh0[(mrow + g) * GO + c + 4], ah3 = wh0[(mrow + 8 + g) * GO + c + 4];
            unsigned al0 = wl0[(mrow + g) * GO + c],     al1 = wl0[(mrow + 8 + g) * GO + c];
            unsigned al2 = wl0[(mrow + g) * GO + c + 4], al3 = wl0[(mrow + 8 + g) * GO + c + 4];
#pragma unroll
            for (int nt = 0; nt < 8; nt++) {
                mma_f16(acc[mt][nt], ah0, ah1, ah2, ah3, bh[nt][0], bh[nt][1]);
                mma_f16(acc[mt][nt], ah0, ah1, ah2, ah3, bl[nt][0], bl[nt][1]);
                mma_f16(acc[mt][nt], al0, al1, al2, al3, bh[nt][0], bh[nt][1]);
            }
        }
        __syncthreads();
    }

#pragma unroll
    for (int mt = 0; mt < 2; mt++) {
        int r0 = row0 + 32 * warp + 16 * mt + g;
        float b0 = bias[r0], b1 = bias[r0 + 8];
#pragma unroll
        for (int nt = 0; nt < 8; nt++) {
            int col = pix0 + 8 * nt + 2 * c;
            *(float2*)&outb[(size_t)r0 * NPIX + col] =
                make_float2(acc[mt][nt][0] + b0, acc[mt][nt][1] + b0);
            *(float2*)&outb[(size_t)(r0 + 8) * NPIX + col] =
                make_float2(acc[mt][nt][2] + b1, acc[mt][nt][3] + b1);
        }
    }
}

// ---------------------------------------------------------------------------
// fp16 flash, q-major S (FA-2 style): S acc fragments ARE the P A-fragments
// after exp — no movmatrix. l via ones-constant B MMA (no smem ones row).
// ---------------------------------------------------------------------------
#define SKH 20
#define SVH 36
#define STAGE (64 * SKH + 32 * SVH)
#define H2ONES 0x3C003C00u

__global__ __launch_bounds__(128, 4) void flash_h_kernel(
    const unsigned* __restrict__ qh, const unsigned* __restrict__ kh,
    const unsigned* __restrict__ vh, unsigned* __restrict__ aohi,
    unsigned* __restrict__ aolo)
{
    __shared__ unsigned sm[3 * STAGE];

    const int tid = threadIdx.x, lane = tid & 31, warp = tid >> 5;
    const int g = lane >> 2, c = lane & 3;
    const int bh = blockIdx.y, b = bh >> 2, h = bh & 3;
    const int qw = blockIdx.x * 128 + warp * 32;

    const unsigned* qbh = qh + (size_t)bh * NPIX * 16;
    const unsigned* kbh = kh + (size_t)bh * NPIX * 16;
    const unsigned* vbh = vh + (size_t)bh * 32 * (NPIX / 2);
    const unsigned sbase = (unsigned)__cvta_generic_to_shared(sm);
    // ldm4 per-lane offsets: matrices [rows 0-7|8-15] x [u32 chunk 0|4]
    const unsigned kOff = (unsigned)(((lane & 7) + 8 * ((lane >> 4) & 1)) * SKH + 4 * ((lane >> 3) & 1));
    const unsigned vOff = (unsigned)(((lane & 7) + 8 * ((lane >> 4) & 1)) * SVH + 4 * ((lane >> 3) & 1));

    // Persistent Q A-fragments: aq[mq][ks] = {(g,2c),(g+8,2c),(g,8+2c),(g+8,8+2c)} of d-chunk ks
    unsigned aq[2][2][4];
#pragma unroll
    for (int mq = 0; mq < 2; mq++) {
        const unsigned* q0 = qbh + (size_t)(qw + 16 * mq + g) * 16;
        const unsigned* q1 = qbh + (size_t)(qw + 16 * mq + 8 + g) * 16;
#pragma unroll
        for (int ks = 0; ks < 2; ks++) {
            aq[mq][ks][0] = q0[8 * ks + c];
            aq[mq][ks][1] = q1[8 * ks + c];
            aq[mq][ks][2] = q0[8 * ks + c + 4];
            aq[mq][ks][3] = q1[8 * ks + c + 4];
        }
    }

    float O[2][4][4];
    float Oex[2][4];
#pragma unroll
    for (int mq = 0; mq < 2; mq++) {
#pragma unroll
        for (int nd = 0; nd < 4; nd++)
#pragma unroll
            for (int r = 0; r < 4; r++) O[mq][nd][r] = 0.f;
#pragma unroll
        for (int r = 0; r < 4; r++) Oex[mq][r] = 0.f;
    }

    auto fill = [&](int it, int s) {
        unsigned base = sbase + (unsigned)(s * STAGE) * 4u;
        int j0 = it * 64;
#pragma unroll
        for (int r = 0; r < 2; r++) {
            int id = tid + r * 128;
            int row = id >> 2, j = id & 3;
            cpasync16(base + (unsigned)(row * SKH + 4 * j) * 4u,
                      kbh + (size_t)(j0 + row) * 16 + 4 * j);
            int d = id >> 3, jj = id & 7;
            cpasync16(base + (unsigned)(64 * SKH + d * SVH + 4 * jj) * 4u,
                      vbh + (size_t)d * (NPIX / 2) + j0 / 2 + 4 * jj);
        }
        asm volatile("cp.async.commit_group;");
    };

    fill(0, 0);
    fill(1, 1);

    int stage = 0;
    for (int it = 0; it < 64; ++it) {
        if (it < 62) asm volatile("cp.async.wait_group 1;");
        else         asm volatile("cp.async.wait_group 0;");
        __syncthreads();
        if (it < 62) {
            int s2 = stage + 2; if (s2 >= 3) s2 -= 3;
            fill(it + 2, s2);
        }

        const unsigned kb = sbase + (unsigned)(stage * STAGE) * 4u;
        const unsigned vb = kb + (unsigned)(64 * SKH) * 4u;

#pragma unroll
        for (int kc = 0; kc < 4; kc++) {        // 16-key chunks
            // K B-fragments: kf0 = d0-15 (ks0), kf1 = d16-31 (ks1);
            // [0,1] = keys 0-7 (b0,b1), [2,3] = keys 8-15
            unsigned kf0[4], kf1[4];
            ldm4(kf0, kb + ((unsigned)(16 * kc * SKH) + kOff) * 4u);
            ldm4(kf1, kb + ((unsigned)(16 * kc * SKH + 8) + kOff) * 4u);

            float acc[2][2][4];
#pragma unroll
            for (int mq = 0; mq < 2; mq++)
#pragma unroll
                for (int nt = 0; nt < 2; nt++) {
#pragma unroll
                    for (int r = 0; r < 4; r++) acc[mq][nt][r] = 0.f;
                    mma_f16(acc[mq][nt], aq[mq][0][0], aq[mq][0][1], aq[mq][0][2], aq[mq][0][3],
                            kf0[2 * nt], kf0[2 * nt + 1]);
                    mma_f16(acc[mq][nt], aq[mq][1][0], aq[mq][1][1], aq[mq][1][2], aq[mq][1][3],
                            kf1[2 * nt], kf1[2 * nt + 1]);
                }

            // exp: S acc -> P A-fragments directly (no transpose needed)
            unsigned pa[2][4];
#pragma unroll
            for (int mq = 0; mq < 2; mq++) {
                pa[mq][0] = h2exp2(packh2(acc[mq][0][1], acc[mq][0][0]));  // (g,   k 2c)
                pa[mq][1] = h2exp2(packh2(acc[mq][0][3], acc[mq][0][2]));  // (g+8, k 2c)
                pa[mq][2] = h2exp2(packh2(acc[mq][1][1], acc[mq][1][0]));  // (g,   k 8+2c)
                pa[mq][3] = h2exp2(packh2(acc[mq][1][3], acc[mq][1][2]));  // (g+8, k 8+2c)
            }

            // V B-fragments: vf0 = d0-15, vf1 = d16-31
            unsigned vf0[4], vf1[4];
            ldm4(vf0, vb + ((unsigned)(8 * kc) + vOff) * 4u);
            ldm4(vf1, vb + ((unsigned)(16 * SVH + 8 * kc) + vOff) * 4u);

#pragma unroll
            for (int mq = 0; mq < 2; mq++) {
                mma_f16(O[mq][0], pa[mq][0], pa[mq][1], pa[mq][2], pa[mq][3], vf0[0], vf0[1]);
                mma_f16(O[mq][1], pa[mq][0], pa[mq][1], pa[mq][2], pa[mq][3], vf0[2], vf0[3]);
                mma_f16(O[mq][2], pa[mq][0], pa[mq][1], pa[mq][2], pa[mq][3], vf1[0], vf1[1]);
                mma_f16(O[mq][3], pa[mq][0], pa[mq][1], pa[mq][2], pa[mq][3], vf1[2], vf1[3]);
                mma_f16(Oex[mq], pa[mq][0], pa[mq][1], pa[mq][2], pa[mq][3], H2ONES, H2ONES);
            }
        }
        if (++stage == 3) stage = 0;
    }

    // l: every column of Oex equals the row sum -> this thread's own rows
    float linvq[2], linvq8[2];
#pragma unroll
    for (int mq = 0; mq < 2; mq++) {
        linvq[mq]  = 1.f / Oex[mq][0];
        linvq8[mq] = 1.f / Oex[mq][2];
    }

    unsigned* aoh = aohi + (size_t)b * NPIX * 64;
    unsigned* aol = aolo + (size_t)b * NPIX * 64;
#pragma unroll
    for (int mq = 0; mq < 2; mq++)
#pragma unroll
        for (int nd = 0; nd < 4; nd++) {
            int q0 = qw + 16 * mq + g;
            int pr = h * 16 + 4 * nd + c;
            float o0 = O[mq][nd][0] * linvq[mq];
            float o1 = O[mq][nd][1] * linvq[mq];
            __half h0 = __float2half_rn(o0), h1 = __float2half_rn(o1);
            aoh[(size_t)q0 * 64 + pr] =
                (unsigned)__half_as_ushort(h0) | ((unsigned)__half_as_ushort(h1) << 16);
            aol[(size_t)q0 * 64 + pr] =
                packh2(o1 - __half2float(h1), o0 - __half2float(h0));
            float o2 = O[mq][nd][2] * linvq8[mq];
            float o3 = O[mq][nd][3] * linvq8[mq];
            __half h2 = __float2half_rn(o2), h3 = __float2half_rn(o3);
            aoh[(size_t)(q0 + 8) * 64 + pr] =
                (unsigned)__half_as_ushort(h2) | ((unsigned)__half_as_ushort(h3) << 16);
            aol[(size_t)(q0 + 8) * 64 + pr] =
                packh2(o3 - __half2float(h3), o2 - __half2float(h2));
        }
}

// ---------------------------------------------------------------------------
extern "C" void kernel_launch(void* const* d_in, const int* in_sizes, int n_in,
                              void* d_out, int out_size)
{
    const float* x     = (const float*)d_in[0];
    const float* w_qkv = (const float*)d_in[1];
    const float* w_out = (const float*)d_in[2];
    const float* b_out = (const float*)d_in[3];
    float* out = (float*)d_out;

    static unsigned *qh = nullptr, *kh = nullptr, *vh = nullptr, *wh = nullptr, *xh = nullptr;
    static unsigned *w2hi = nullptr, *w2lo = nullptr, *aohi = nullptr, *aolo = nullptr;
    if (!qh) {
        cudaGetSymbolAddress((void**)&qh,   g_qh);
        cudaGetSymbolAddress((void**)&kh,   g_kh);
        cudaGetSymbolAddress((void**)&vh,   g_vh);
        cudaGetSymbolAddress((void**)&wh,   g_wh);
        cudaGetSymbolAddress((void**)&xh,   g_xh);
        cudaGetSymbolAddress((void**)&w2hi, g_w2hi);
        cudaGetSymbolAddress((void**)&w2lo, g_w2lo);
        cudaGetSymbolAddress((void**)&aohi, g_aohi);
        cudaGetSymbolAddress((void**)&aolo, g_aolo);
    }

    wcvt_kernel<<<192, 256>>>(w_qkv, wh);
    wsplit_kernel<<<64, 256>>>(w_out, w2hi, w2lo);
    xcvt_kernel<<<dim3(NPIX / 64, 256 / 64, NB), 256>>>(x, xh);

    dim3 g1(NPIX / 128, 3, NB);
    gemm_qkv_h<<<g1, 256>>>(wh, xh, qh, kh, vh);

    dim3 g3(NPIX / 128, 16);
    flash_h_kernel<<<g3, 128>>>(qh, kh, vh, aohi, aolo);

    dim3 g4(NPIX / 64, 2, NB);
    gemm_out_h<<<g4, 128>>>(w2hi, w2lo, aohi, aolo, out, b_out);
}

// round 15
// speedup vs baseline: 8.7927x; 1.0192x over previous
#include <cuda_runtime.h>
#include <cuda_fp16.h>
#include <cstdint>

#define NPIX 4096
#define NB 4
#define CIN 256

__device__ unsigned g_qh[(size_t)16 * NPIX * 16];
__device__ unsigned g_kh[(size_t)16 * NPIX * 16];
__device__ unsigned g_vh[(size_t)16 * 32 * (NPIX / 2)];
__device__ unsigned g_wh[384 * 128];
__device__ unsigned g_xh[(size_t)NB * NPIX * 128];
__device__ unsigned g_w2hi[256 * 64], g_w2lo[256 * 64];
__device__ unsigned g_aohi[(size_t)NB * NPIX * 64];
__device__ unsigned g_aolo[(size_t)NB * NPIX * 64];

__device__ __forceinline__ void cpasync16(unsigned dst, const void* src) {
    asm volatile("cp.async.ca.shared.global [%0], [%1], 16;" :: "r"(dst), "l"(src));
}
__device__ __forceinline__ unsigned packh2(float hi, float lo) {
    unsigned r; asm("cvt.rn.f16x2.f32 %0, %1, %2;" : "=r"(r) : "f"(hi), "f"(lo)); return r;
}
__device__ __forceinline__ unsigned h2exp2(unsigned x) {
    unsigned r; asm("ex2.approx.f16x2 %0, %1;" : "=r"(r) : "r"(x)); return r;
}
__device__ __forceinline__ void ldm4(unsigned* r, unsigned a) {
    asm volatile("ldmatrix.sync.aligned.m8n8.x4.shared.b16 {%0,%1,%2,%3}, [%4];"
                 : "=r"(r[0]), "=r"(r[1]), "=r"(r[2]), "=r"(r[3]) : "r"(a));
}
__device__ __forceinline__ void mma_f16(float* d, unsigned a0, unsigned a1,
                                        unsigned a2, unsigned a3, unsigned b0, unsigned b1) {
    asm volatile("mma.sync.aligned.m16n8k16.row.col.f32.f16.f16.f32 "
                 "{%0,%1,%2,%3}, {%4,%5,%6,%7}, {%8,%9}, {%0,%1,%2,%3};"
                 : "+f"(d[0]), "+f"(d[1]), "+f"(d[2]), "+f"(d[3])
                 : "r"(a0), "r"(a1), "r"(a2), "r"(a3), "r"(b0), "r"(b1));
}

// ---------------- converters (weights merged into one launch) ----------------
__global__ void cvtw_kernel(const float* __restrict__ w_qkv, unsigned* __restrict__ wh,
                            const float* __restrict__ w_out,
                            unsigned* __restrict__ whi, unsigned* __restrict__ wlo)
{
    int i = blockIdx.x * 256 + threadIdx.x;        // 49152
    wh[i] = packh2(w_qkv[2 * i + 1], w_qkv[2 * i]);
    if (i < 16384) {
        float a = w_out[2 * i], bb = w_out[2 * i + 1];
        __half ha = __float2half_rn(a), hb = __float2half_rn(bb);
        whi[i] = (unsigned)__half_as_ushort(ha) | ((unsigned)__half_as_ushort(hb) << 16);
        wlo[i] = packh2(bb - __half2float(hb), a - __half2float(ha));
    }
}
__global__ __launch_bounds__(256) void xcvt_kernel(const float* __restrict__ x,
                                                   unsigned* __restrict__ xh)
{
    __shared__ float t[64][65];
    const int pix0 = blockIdx.x * 64, k0 = blockIdx.y * 64, b = blockIdx.z;
    const int tid = threadIdx.x;
#pragma unroll
    for (int j = 0; j < 16; j++) {
        int row = j * 4 + (tid >> 6), col = tid & 63;
        t[row][col] = x[((size_t)b * 256 + k0 + row) * NPIX + pix0 + col];
    }
    __syncthreads();
    int p = tid >> 2, seg = tid & 3;
    unsigned u[8];
#pragma unroll
    for (int j = 0; j < 8; j++)
        u[j] = packh2(t[seg * 16 + 2 * j + 1][p], t[seg * 16 + 2 * j][p]);
    unsigned* dst = xh + ((size_t)b * NPIX + pix0 + p) * 128 + k0 / 2 + seg * 8;
    *(uint4*)dst       = make_uint4(u[0], u[1], u[2], u[3]);
    *(uint4*)(dst + 4) = make_uint4(u[4], u[5], u[6], u[7]);
}

// ---------------------------------------------------------------------------
// fp16 QKV GEMM + fused l2norm: 3-stage cp.async ring, ONE sync per chunk.
// ---------------------------------------------------------------------------
#define GS 20
#define QKVSM (6 * 128 * GS * 4)   // 61440 B dynamic

__global__ __launch_bounds__(256) void gemm_qkv_h(
    const unsigned* __restrict__ wh, const unsigned* __restrict__ xh,
    unsigned* __restrict__ qh, unsigned* __restrict__ kh, unsigned* __restrict__ vh)
{
    extern __shared__ unsigned gsm[];
    unsigned* sXoff = gsm + 3 * 128 * GS;

    const int sel = blockIdx.y, b = blockIdx.z;
    const int pixB = blockIdx.x * 128;
    const int tid = threadIdx.x, lane = tid & 31, warp = tid >> 5;
    const int g = lane >> 2, c = lane & 3;
    const int head = warp & 3, nh = warp >> 2;
    const int pix0 = pixB + nh * 64;
    const unsigned wsb = (unsigned)__cvta_generic_to_shared(gsm);
    const unsigned xsb = (unsigned)__cvta_generic_to_shared(sXoff);
    const unsigned aRow = (unsigned)((lane & 15) * GS + ((lane >> 4) & 1) * 4);
    const unsigned bRow = (unsigned)(((lane & 7) + ((lane >> 4) & 1) * 8) * GS + ((lane >> 3) & 1) * 4);

    float acc[2][8][4];
#pragma unroll
    for (int mt = 0; mt < 2; mt++)
#pragma unroll
        for (int nt = 0; nt < 8; nt++)
#pragma unroll
            for (int r = 0; r < 4; r++) acc[mt][nt][r] = 0.f;

    auto fill = [&](int kk, int s) {
        int row = tid >> 1, sg = tid & 1;
        const unsigned* ws = wh + (size_t)(sel * 128 + row) * 128 + kk / 2 + sg * 8;
        cpasync16(wsb + (unsigned)(s * 128 * GS + row * GS + sg * 8) * 4u, ws);
        cpasync16(wsb + (unsigned)(s * 128 * GS + row * GS + sg * 8 + 4) * 4u, ws + 4);
        const unsigned* xs = xh + ((size_t)b * NPIX + pixB + row) * 128 + kk / 2 + sg * 8;
        cpasync16(xsb + (unsigned)(s * 128 * GS + row * GS + sg * 8) * 4u, xs);
        cpasync16(xsb + (unsigned)(s * 128 * GS + row * GS + sg * 8 + 4) * 4u, xs + 4);
        asm volatile("cp.async.commit_group;");
    };

    fill(0, 0);
    fill(32, 1);
    for (int ch = 0; ch < 8; ++ch) {
        if (ch < 7) asm volatile("cp.async.wait_group 1;");
        else        asm volatile("cp.async.wait_group 0;");
        __syncthreads();
        if (ch < 6) {
            int s2 = ch + 2; while (s2 >= 3) s2 -= 3;
            fill((ch + 2) * 32, s2);
        }
        int st = ch; while (st >= 3) st -= 3;
        unsigned wbase = wsb + (unsigned)(st * 128 * GS) * 4u;
        unsigned xbase = xsb + (unsigned)(st * 128 * GS) * 4u;
#pragma unroll
        for (int ks = 0; ks < 2; ks++) {
            unsigned bb[8][2];
#pragma unroll
            for (int np = 0; np < 4; np++) {
                unsigned r[4];
                ldm4(r, xbase + ((unsigned)((64 * nh + 16 * np) * GS + 8 * ks) + bRow) * 4u);
                bb[2*np][0] = r[0]; bb[2*np][1] = r[1];
                bb[2*np+1][0] = r[2]; bb[2*np+1][1] = r[3];
            }
#pragma unroll
            for (int mt = 0; mt < 2; mt++) {
                unsigned a[4];
                ldm4(a, wbase + ((unsigned)((32 * head + 16 * mt) * GS + 8 * ks) + aRow) * 4u);
#pragma unroll
                for (int nt = 0; nt < 8; nt++)
                    mma_f16(acc[mt][nt], a[0], a[1], a[2], a[3], bb[nt][0], bb[nt][1]);
            }
        }
    }

    if (sel < 2) {
        unsigned* dst = sel ? kh : qh;
        const float scale = (sel == 0) ? 14.426950408889634f : 1.f;
#pragma unroll
        for (int nt = 0; nt < 8; nt++) {
#pragma unroll
            for (int par = 0; par < 2; par++) {
                float ss = acc[0][nt][par] * acc[0][nt][par]
                         + acc[0][nt][par + 2] * acc[0][nt][par + 2]
                         + acc[1][nt][par] * acc[1][nt][par]
                         + acc[1][nt][par + 2] * acc[1][nt][par + 2];
                ss += __shfl_xor_sync(0xffffffffu, ss, 4);
                ss += __shfl_xor_sync(0xffffffffu, ss, 8);
                ss += __shfl_xor_sync(0xffffffffu, ss, 16);
                float inv = scale / fmaxf(sqrtf(ss), 1e-12f);
                size_t base = ((size_t)(b * 4 + head) * NPIX + pix0 + 8 * nt + 2 * c + par) * 16;
#pragma unroll
                for (int mt = 0; mt < 2; mt++) {
                    float v0 = acc[mt][nt][par] * inv;
                    float v1 = acc[mt][nt][par + 2] * inv;
                    float w0 = __shfl_xor_sync(0xffffffffu, v0, 4);
                    float w1 = __shfl_xor_sync(0xffffffffu, v1, 4);
                    if (!(g & 1)) {
                        dst[base + 8 * mt + (g >> 1)]     = packh2(w0, v0);
                        dst[base + 8 * mt + 4 + (g >> 1)] = packh2(w1, v1);
                    }
                }
            }
        }
    } else {
#pragma unroll
        for (int mt = 0; mt < 2; mt++)
#pragma unroll
            for (int dh = 0; dh < 2; dh++) {
                int d = 16 * mt + 8 * dh + g;
#pragma unroll
                for (int nt = 0; nt < 8; nt++) {
                    unsigned pv = packh2(acc[mt][nt][2 * dh + 1], acc[mt][nt][2 * dh]);
                    vh[((size_t)(b * 4 + head) * 32 + d) * (NPIX / 2) + (pix0 + 8 * nt) / 2 + c] = pv;
                }
            }
    }
}

// ---------------------------------------------------------------------------
// Split-fp16 output projection (unchanged).
// ---------------------------------------------------------------------------
#define GO 12
__global__ __launch_bounds__(128) void gemm_out_h(
    const unsigned* __restrict__ whi, const unsigned* __restrict__ wlo,
    const unsigned* __restrict__ xhi, const unsigned* __restrict__ xlo,
    float* __restrict__ out, const float* __restrict__ bias)
{
    __shared__ unsigned sWh[2][128 * GO], sWl[2][128 * GO];
    __shared__ unsigned sXh[2][64 * GO],  sXl[2][64 * GO];

    const int b = blockIdx.z;
    const int row0 = blockIdx.y * 128, pix0 = blockIdx.x * 64;
    const int tid = threadIdx.x, lane = tid & 31, warp = tid >> 5;
    const int g = lane >> 2, c = lane & 3;
    const unsigned whb = (unsigned)__cvta_generic_to_shared(&sWh[0][0]);
    const unsigned wlb = (unsigned)__cvta_generic_to_shared(&sWl[0][0]);
    const unsigned xhb = (unsigned)__cvta_generic_to_shared(&sXh[0][0]);
    const unsigned xlb = (unsigned)__cvta_generic_to_shared(&sXl[0][0]);
    const unsigned* xhs = xhi + (size_t)b * NPIX * 64;
    const unsigned* xls = xlo + (size_t)b * NPIX * 64;
    float* outb = out + (size_t)b * 256 * NPIX;

    float acc[2][8][4];
#pragma unroll
    for (int mt = 0; mt < 2; mt++)
#pragma unroll
        for (int nt = 0; nt < 8; nt++)
#pragma unroll
            for (int r = 0; r < 4; r++) acc[mt][nt][r] = 0.f;

    auto fill = [&](int kk, int s) {
        const unsigned* wh_ = whi + (size_t)(row0 + tid) * 64 + kk / 2;
        const unsigned* wl_ = wlo + (size_t)(row0 + tid) * 64 + kk / 2;
        cpasync16(whb + (unsigned)(s * 128 * GO + tid * GO) * 4u, wh_);
        cpasync16(whb + (unsigned)(s * 128 * GO + tid * GO + 4) * 4u, wh_ + 4);
        cpasync16(wlb + (unsigned)(s * 128 * GO + tid * GO) * 4u, wl_);
        cpasync16(wlb + (unsigned)(s * 128 * GO + tid * GO + 4) * 4u, wl_ + 4);
        int row = tid >> 1, sg = tid & 1;
        cpasync16(xhb + (unsigned)(s * 64 * GO + row * GO + sg * 4) * 4u,
                  xhs + (size_t)(pix0 + row) * 64 + kk / 2 + sg * 4);
        cpasync16(xlb + (unsigned)(s * 64 * GO + row * GO + sg * 4) * 4u,
                  xls + (size_t)(pix0 + row) * 64 + kk / 2 + sg * 4);
        asm volatile("cp.async.commit_group;");
    };

    fill(0, 0);
    for (int ch = 0; ch < 8; ++ch) {
        if (ch < 7) {
            fill((ch + 1) * 16, (ch + 1) & 1);
            asm volatile("cp.async.wait_group 1;");
        } else {
            asm volatile("cp.async.wait_group 0;");
        }
        __syncthreads();
        const int s = ch & 1;
        const unsigned* wh0 = &sWh[s][0];
        const unsigned* wl0 = &sWl[s][0];
        const unsigned* xh0 = &sXh[s][0];
        const unsigned* xl0 = &sXl[s][0];
        unsigned bh[8][2], bl[8][2];
#pragma unroll
        for (int nt = 0; nt < 8; nt++) {
            bh[nt][0] = xh0[(8 * nt + g) * GO + c];
            bh[nt][1] = xh0[(8 * nt + g) * GO + c + 4];
            bl[nt][0] = xl0[(8 * nt + g) * GO + c];
            bl[nt][1] = xl0[(8 * nt + g) * GO + c + 4];
        }
#pragma unroll
        for (int mt = 0; mt < 2; mt++) {
            int mrow = 32 * warp + 16 * mt;
            unsigned ah0 = wh0[(mrow + g) * GO + c],     ah1 = wh0[(mrow + 8 + g) * GO + c];
            unsigned ah2 = wh0[(mrow + g) * GO + c + 4], ah3 = wh0[(mrow + 8 + g) * GO + c + 4];
            unsigned al0 = wl0[(mrow + g) * GO + c],     al1 = wl0[(mrow + 8 + g) * GO + c];
            unsigned al2 = wl0[(mrow + g) * GO + c + 4], al3 = wl0[(mrow + 8 + g) * GO + c + 4];
#pragma unroll
            for (int nt = 0; nt < 8; nt++) {
                mma_f16(acc[mt][nt], ah0, ah1, ah2, ah3, bh[nt][0], bh[nt][1]);
                mma_f16(acc[mt][nt], ah0, ah1, ah2, ah3, bl[nt][0], bl[nt][1]);
                mma_f16(acc[mt][nt], al0, al1, al2, al3, bh[nt][0], bh[nt][1]);
            }
        }
        __syncthreads();
    }

#pragma unroll
    for (int mt = 0; mt < 2; mt++) {
        int r0 = row0 + 32 * warp + 16 * mt + g;
        float b0 = bias[r0], b1 = bias[r0 + 8];
#pragma unroll
        for (int nt = 0; nt < 8; nt++) {
            int col = pix0 + 8 * nt + 2 * c;
            *(float2*)&outb[(size_t)r0 * NPIX + col] =
                make_float2(acc[mt][nt][0] + b0, acc[mt][nt][1] + b0);
            *(float2*)&outb[(size_t)(r0 + 8) * NPIX + col] =
                make_float2(acc[mt][nt][2] + b1, acc[mt][nt][3] + b1);
        }
    }
}

// ---------------------------------------------------------------------------
// fp16 flash, q-major S, NO movmatrix; 128-key tiles, 2-stage, 32 iters
// (half the barriers of round 14).
// ---------------------------------------------------------------------------
#define SKH 20
#define SVH 68
#define FSTAGE (128 * SKH + 32 * SVH)   // 4736 u32
#define H2ONES 0x3C003C00u

__global__ __launch_bounds__(128, 4) void flash_h_kernel(
    const unsigned* __restrict__ qh, const unsigned* __restrict__ kh,
    const unsigned* __restrict__ vh, unsigned* __restrict__ aohi,
    unsigned* __restrict__ aolo)
{
    __shared__ unsigned sm[2 * FSTAGE];

    const int tid = threadIdx.x, lane = tid & 31, warp = tid >> 5;
    const int g = lane >> 2, c = lane & 3;
    const int bh = blockIdx.y, b = bh >> 2, h = bh & 3;
    const int qw = blockIdx.x * 128 + warp * 32;

    const unsigned* qbh = qh + (size_t)bh * NPIX * 16;
    const unsigned* kbh = kh + (size_t)bh * NPIX * 16;
    const unsigned* vbh = vh + (size_t)bh * 32 * (NPIX / 2);
    const unsigned sbase = (unsigned)__cvta_generic_to_shared(sm);
    const unsigned kOff = (unsigned)(((lane & 7) + 8 * ((lane >> 4) & 1)) * SKH + 4 * ((lane >> 3) & 1));
    const unsigned vOff = (unsigned)(((lane & 7) + 8 * ((lane >> 4) & 1)) * SVH + 4 * ((lane >> 3) & 1));

    unsigned aq[2][2][4];
#pragma unroll
    for (int mq = 0; mq < 2; mq++) {
        const unsigned* q0 = qbh + (size_t)(qw + 16 * mq + g) * 16;
        const unsigned* q1 = qbh + (size_t)(qw + 16 * mq + 8 + g) * 16;
#pragma unroll
        for (int ks = 0; ks < 2; ks++) {
            aq[mq][ks][0] = q0[8 * ks + c];
            aq[mq][ks][1] = q1[8 * ks + c];
            aq[mq][ks][2] = q0[8 * ks + c + 4];
            aq[mq][ks][3] = q1[8 * ks + c + 4];
        }
    }

    float O[2][4][4];
    float Oex[2][4];
#pragma unroll
    for (int mq = 0; mq < 2; mq++) {
#pragma unroll
        for (int nd = 0; nd < 4; nd++)
#pragma unroll
            for (int r = 0; r < 4; r++) O[mq][nd][r] = 0.f;
#pragma unroll
        for (int r = 0; r < 4; r++) Oex[mq][r] = 0.f;
    }

    auto fill = [&](int it, int s) {
        unsigned base = sbase + (unsigned)(s * FSTAGE) * 4u;
        int j0 = it * 128;
#pragma unroll
        for (int r = 0; r < 4; r++) {
            int id = tid + r * 128;              // 0..511
            int row = id >> 2, j = id & 3;
            cpasync16(base + (unsigned)(row * SKH + 4 * j) * 4u,
                      kbh + (size_t)(j0 + row) * 16 + 4 * j);
            int d = id >> 4, jj = id & 15;
            cpasync16(base + (unsigned)(128 * SKH + d * SVH + 4 * jj) * 4u,
                      vbh + (size_t)d * (NPIX / 2) + j0 / 2 + 4 * jj);
        }
        asm volatile("cp.async.commit_group;");
    };

    fill(0, 0);

    for (int it = 0; it < 32; ++it) {
        asm volatile("cp.async.wait_group 0;");
        __syncthreads();
        if (it < 31) fill(it + 1, (it + 1) & 1);

        const unsigned kb = sbase + (unsigned)((it & 1) * FSTAGE) * 4u;
        const unsigned vb = kb + (unsigned)(128 * SKH) * 4u;

#pragma unroll
        for (int kc = 0; kc < 8; kc++) {
            unsigned kf0[4], kf1[4];
            ldm4(kf0, kb + ((unsigned)(16 * kc * SKH) + kOff) * 4u);
            ldm4(kf1, kb + ((unsigned)(16 * kc * SKH + 8) + kOff) * 4u);

            float acc[2][2][4];
#pragma unroll
            for (int mq = 0; mq < 2; mq++)
#pragma unroll
                for (int nt = 0; nt < 2; nt++) {
#pragma unroll
                    for (int r = 0; r < 4; r++) acc[mq][nt][r] = 0.f;
                    mma_f16(acc[mq][nt], aq[mq][0][0], aq[mq][0][1], aq[mq][0][2], aq[mq][0][3],
                            kf0[2 * nt], kf0[2 * nt + 1]);
                    mma_f16(acc[mq][nt], aq[mq][1][0], aq[mq][1][1], aq[mq][1][2], aq[mq][1][3],
                            kf1[2 * nt], kf1[2 * nt + 1]);
                }

            unsigned pa[2][4];
#pragma unroll
            for (int mq = 0; mq < 2; mq++) {
                pa[mq][0] = h2exp2(packh2(acc[mq][0][1], acc[mq][0][0]));
                pa[mq][1] = h2exp2(packh2(acc[mq][0][3], acc[mq][0][2]));
                pa[mq][2] = h2exp2(packh2(acc[mq][1][1], acc[mq][1][0]));
                pa[mq][3] = h2exp2(packh2(acc[mq][1][3], acc[mq][1][2]));
            }

            unsigned vf0[4], vf1[4];
            ldm4(vf0, vb + ((unsigned)(8 * kc) + vOff) * 4u);
            ldm4(vf1, vb + ((unsigned)(16 * SVH + 8 * kc) + vOff) * 4u);

#pragma unroll
            for (int mq = 0; mq < 2; mq++) {
                mma_f16(O[mq][0], pa[mq][0], pa[mq][1], pa[mq][2], pa[mq][3], vf0[0], vf0[1]);
                mma_f16(O[mq][1], pa[mq][0], pa[mq][1], pa[mq][2], pa[mq][3], vf0[2], vf0[3]);
                mma_f16(O[mq][2], pa[mq][0], pa[mq][1], pa[mq][2], pa[mq][3], vf1[0], vf1[1]);
                mma_f16(O[mq][3], pa[mq][0], pa[mq][1], pa[mq][2], pa[mq][3], vf1[2], vf1[3]);
                mma_f16(Oex[mq], pa[mq][0], pa[mq][1], pa[mq][2], pa[mq][3], H2ONES, H2ONES);
            }
        }
    }

    float linvq[2], linvq8[2];
#pragma unroll
    for (int mq = 0; mq < 2; mq++) {
        linvq[mq]  = 1.f / Oex[mq][0];
        linvq8[mq] = 1.f / Oex[mq][2];
    }

    unsigned* aoh = aohi + (size_t)b * NPIX * 64;
    unsigned* aol = aolo + (size_t)b * NPIX * 64;
#pragma unroll
    for (int mq = 0; mq < 2; mq++)
#pragma unroll
        for (int nd = 0; nd < 4; nd++) {
            int q0 = qw + 16 * mq + g;
            int pr = h * 16 + 4 * nd + c;
            float o0 = O[mq][nd][0] * linvq[mq];
            float o1 = O[mq][nd][1] * linvq[mq];
            __half h0 = __float2half_rn(o0), h1 = __float2half_rn(o1);
            aoh[(size_t)q0 * 64 + pr] =
                (unsigned)__half_as_ushort(h0) | ((unsigned)__half_as_ushort(h1) << 16);
            aol[(size_t)q0 * 64 + pr] =
                packh2(o1 - __half2float(h1), o0 - __half2float(h0));
            float o2 = O[mq][nd][2] * linvq8[mq];
            float o3 = O[mq][nd][3] * linvq8[mq];
            __half h2 = __float2half_rn(o2), h3 = __float2half_rn(o3);
            aoh[(size_t)(q0 + 8) * 64 + pr] =
                (unsigned)__half_as_ushort(h2) | ((unsigned)__half_as_ushort(h3) << 16);
            aol[(size_t)(q0 + 8) * 64 + pr] =
                packh2(o3 - __half2float(h3), o2 - __half2float(h2));
        }
}

// ---------------------------------------------------------------------------
extern "C" void kernel_launch(void* const* d_in, const int* in_sizes, int n_in,
                              void* d_out, int out_size)
{
    const float* x     = (const float*)d_in[0];
    const float* w_qkv = (const float*)d_in[1];
    const float* w_out = (const float*)d_in[2];
    const float* b_out = (const float*)d_in[3];
    float* out = (float*)d_out;

    static unsigned *qh = nullptr, *kh = nullptr, *vh = nullptr, *wh = nullptr, *xh = nullptr;
    static unsigned *w2hi = nullptr, *w2lo = nullptr, *aohi = nullptr, *aolo = nullptr;
    if (!qh) {
        cudaGetSymbolAddress((void**)&qh,   g_qh);
        cudaGetSymbolAddress((void**)&kh,   g_kh);
        cudaGetSymbolAddress((void**)&vh,   g_vh);
        cudaGetSymbolAddress((void**)&wh,   g_wh);
        cudaGetSymbolAddress((void**)&xh,   g_xh);
        cudaGetSymbolAddress((void**)&w2hi, g_w2hi);
        cudaGetSymbolAddress((void**)&w2lo, g_w2lo);
        cudaGetSymbolAddress((void**)&aohi, g_aohi);
        cudaGetSymbolAddress((void**)&aolo, g_aolo);
        cudaFuncSetAttribute(gemm_qkv_h, cudaFuncAttributeMaxDynamicSharedMemorySize, QKVSM);
    }

    cvtw_kernel<<<192, 256>>>(w_qkv, wh, w_out, w2hi, w2lo);
    xcvt_kernel<<<dim3(NPIX / 64, 256 / 64, NB), 256>>>(x, xh);

    dim3 g1(NPIX / 128, 3, NB);
    gemm_qkv_h<<<g1, 256, QKVSM>>>(wh, xh, qh, kh, vh);

    dim3 g3(NPIX / 128, 16);
    flash_h_kernel<<<g3, 128>>>(qh, kh, vh, aohi, aolo);

    dim3 g4(NPIX / 64, 2, NB);
    gemm_out_h<<<g4, 128>>>(w2hi, w2lo, aohi, aolo, out, b_out);
}

// round 16
// speedup vs baseline: 8.8060x; 1.0015x over previous
#include <cuda_runtime.h>
#include <cuda_fp16.h>
#include <cstdint>

#define NPIX 4096
#define NB 4
#define CIN 256

__device__ unsigned g_qh[(size_t)16 * NPIX * 16];
__device__ unsigned g_kh[(size_t)16 * NPIX * 16];
__device__ unsigned g_vh[(size_t)16 * 32 * (NPIX / 2)];
__device__ unsigned g_wh[384 * 128];
__device__ unsigned g_xh[(size_t)NB * NPIX * 128];
__device__ unsigned g_w2hi[256 * 64], g_w2lo[256 * 64];
__device__ unsigned g_aohi[(size_t)NB * NPIX * 64];
__device__ unsigned g_aolo[(size_t)NB * NPIX * 64];

__device__ __forceinline__ void cpasync16(unsigned dst, const void* src) {
    asm volatile("cp.async.ca.shared.global [%0], [%1], 16;" :: "r"(dst), "l"(src));
}
__device__ __forceinline__ unsigned packh2(float hi, float lo) {
    unsigned r; asm("cvt.rn.f16x2.f32 %0, %1, %2;" : "=r"(r) : "f"(hi), "f"(lo)); return r;
}
__device__ __forceinline__ unsigned h2exp2(unsigned x) {
    unsigned r; asm("ex2.approx.f16x2 %0, %1;" : "=r"(r) : "r"(x)); return r;
}
__device__ __forceinline__ void ldm4(unsigned* r, unsigned a) {
    asm volatile("ldmatrix.sync.aligned.m8n8.x4.shared.b16 {%0,%1,%2,%3}, [%4];"
                 : "=r"(r[0]), "=r"(r[1]), "=r"(r[2]), "=r"(r[3]) : "r"(a));
}
__device__ __forceinline__ void mma_f16(float* d, unsigned a0, unsigned a1,
                                        unsigned a2, unsigned a3, unsigned b0, unsigned b1) {
    asm volatile("mma.sync.aligned.m16n8k16.row.col.f32.f16.f16.f32 "
                 "{%0,%1,%2,%3}, {%4,%5,%6,%7}, {%8,%9}, {%0,%1,%2,%3};"
                 : "+f"(d[0]), "+f"(d[1]), "+f"(d[2]), "+f"(d[3])
                 : "r"(a0), "r"(a1), "r"(a2), "r"(a3), "r"(b0), "r"(b1));
}

// ---------------- converters ----------------
__global__ void cvtw_kernel(const float* __restrict__ w_qkv, unsigned* __restrict__ wh,
                            const float* __restrict__ w_out,
                            unsigned* __restrict__ whi, unsigned* __restrict__ wlo)
{
    int i = blockIdx.x * 256 + threadIdx.x;
    wh[i] = packh2(w_qkv[2 * i + 1], w_qkv[2 * i]);
    if (i < 16384) {
        float a = w_out[2 * i], bb = w_out[2 * i + 1];
        __half ha = __float2half_rn(a), hb = __float2half_rn(bb);
        whi[i] = (unsigned)__half_as_ushort(ha) | ((unsigned)__half_as_ushort(hb) << 16);
        wlo[i] = packh2(bb - __half2float(hb), a - __half2float(ha));
    }
}
__global__ __launch_bounds__(256) void xcvt_kernel(const float* __restrict__ x,
                                                   unsigned* __restrict__ xh)
{
    __shared__ float t[64][65];
    const int pix0 = blockIdx.x * 64, k0 = blockIdx.y * 64, b = blockIdx.z;
    const int tid = threadIdx.x;
#pragma unroll
    for (int j = 0; j < 16; j++) {
        int row = j * 4 + (tid >> 6), col = tid & 63;
        t[row][col] = x[((size_t)b * 256 + k0 + row) * NPIX + pix0 + col];
    }
    __syncthreads();
    int p = tid >> 2, seg = tid & 3;
    unsigned u[8];
#pragma unroll
    for (int j = 0; j < 8; j++)
        u[j] = packh2(t[seg * 16 + 2 * j + 1][p], t[seg * 16 + 2 * j][p]);
    unsigned* dst = xh + ((size_t)b * NPIX + pix0 + p) * 128 + k0 / 2 + seg * 8;
    *(uint4*)dst       = make_uint4(u[0], u[1], u[2], u[3]);
    *(uint4*)(dst + 4) = make_uint4(u[4], u[5], u[6], u[7]);
}

// ---------------------------------------------------------------------------
// fp16 QKV GEMM + fused l2norm: BK=64, 2-stage, 4 chunks (half the barriers).
// ---------------------------------------------------------------------------
#define GQ 36
#define QKVSM (4 * 128 * GQ * 4)   // 73728 B dynamic

__global__ __launch_bounds__(256) void gemm_qkv_h(
    const unsigned* __restrict__ wh, const unsigned* __restrict__ xh,
    unsigned* __restrict__ qh, unsigned* __restrict__ kh, unsigned* __restrict__ vh)
{
    extern __shared__ unsigned gsm[];
    unsigned* sXoff = gsm + 2 * 128 * GQ;

    const int sel = blockIdx.y, b = blockIdx.z;
    const int pixB = blockIdx.x * 128;
    const int tid = threadIdx.x, lane = tid & 31, warp = tid >> 5;
    const int g = lane >> 2, c = lane & 3;
    const int head = warp & 3, nh = warp >> 2;
    const int pix0 = pixB + nh * 64;
    const unsigned wsb = (unsigned)__cvta_generic_to_shared(gsm);
    const unsigned xsb = (unsigned)__cvta_generic_to_shared(sXoff);
    const unsigned aRow = (unsigned)((lane & 15) * GQ + ((lane >> 4) & 1) * 4);
    const unsigned bRow = (unsigned)(((lane & 7) + ((lane >> 4) & 1) * 8) * GQ + ((lane >> 3) & 1) * 4);

    float acc[2][8][4];
#pragma unroll
    for (int mt = 0; mt < 2; mt++)
#pragma unroll
        for (int nt = 0; nt < 8; nt++)
#pragma unroll
            for (int r = 0; r < 4; r++) acc[mt][nt][r] = 0.f;

    auto fill = [&](int kk, int s) {        // kk in k-elems; 64 per chunk = 32 u32
        int row = tid >> 1, sg = tid & 1;
        const unsigned* ws = wh + (size_t)(sel * 128 + row) * 128 + kk / 2 + sg * 16;
        const unsigned* xs = xh + ((size_t)b * NPIX + pixB + row) * 128 + kk / 2 + sg * 16;
#pragma unroll
        for (int j = 0; j < 4; j++) {
            cpasync16(wsb + (unsigned)(s * 128 * GQ + row * GQ + sg * 16 + 4 * j) * 4u, ws + 4 * j);
            cpasync16(xsb + (unsigned)(s * 128 * GQ + row * GQ + sg * 16 + 4 * j) * 4u, xs + 4 * j);
        }
        asm volatile("cp.async.commit_group;");
    };

    fill(0, 0);
    for (int ch = 0; ch < 4; ++ch) {
        if (ch < 3) {
            fill((ch + 1) * 64, (ch + 1) & 1);
            asm volatile("cp.async.wait_group 1;");
        } else {
            asm volatile("cp.async.wait_group 0;");
        }
        __syncthreads();
        unsigned wbase = wsb + (unsigned)((ch & 1) * 128 * GQ) * 4u;
        unsigned xbase = xsb + (unsigned)((ch & 1) * 128 * GQ) * 4u;
#pragma unroll
        for (int ks = 0; ks < 4; ks++) {
            unsigned bb[8][2];
#pragma unroll
            for (int np = 0; np < 4; np++) {
                unsigned r[4];
                ldm4(r, xbase + ((unsigned)((64 * nh + 16 * np) * GQ + 8 * ks) + bRow) * 4u);
                bb[2*np][0] = r[0]; bb[2*np][1] = r[1];
                bb[2*np+1][0] = r[2]; bb[2*np+1][1] = r[3];
            }
#pragma unroll
            for (int mt = 0; mt < 2; mt++) {
                unsigned a[4];
                ldm4(a, wbase + ((unsigned)((32 * head + 16 * mt) * GQ + 8 * ks) + aRow) * 4u);
#pragma unroll
                for (int nt = 0; nt < 8; nt++)
                    mma_f16(acc[mt][nt], a[0], a[1], a[2], a[3], bb[nt][0], bb[nt][1]);
            }
        }
        __syncthreads();
    }

    if (sel < 2) {
        unsigned* dst = sel ? kh : qh;
        const float scale = (sel == 0) ? 14.426950408889634f : 1.f;
#pragma unroll
        for (int nt = 0; nt < 8; nt++) {
#pragma unroll
            for (int par = 0; par < 2; par++) {
                float ss = acc[0][nt][par] * acc[0][nt][par]
                         + acc[0][nt][par + 2] * acc[0][nt][par + 2]
                         + acc[1][nt][par] * acc[1][nt][par]
                         + acc[1][nt][par + 2] * acc[1][nt][par + 2];
                ss += __shfl_xor_sync(0xffffffffu, ss, 4);
                ss += __shfl_xor_sync(0xffffffffu, ss, 8);
                ss += __shfl_xor_sync(0xffffffffu, ss, 16);
                float inv = scale / fmaxf(sqrtf(ss), 1e-12f);
                size_t base = ((size_t)(b * 4 + head) * NPIX + pix0 + 8 * nt + 2 * c + par) * 16;
#pragma unroll
                for (int mt = 0; mt < 2; mt++) {
                    float v0 = acc[mt][nt][par] * inv;
                    float v1 = acc[mt][nt][par + 2] * inv;
                    float w0 = __shfl_xor_sync(0xffffffffu, v0, 4);
                    float w1 = __shfl_xor_sync(0xffffffffu, v1, 4);
                    if (!(g & 1)) {
                        dst[base + 8 * mt + (g >> 1)]     = packh2(w0, v0);
                        dst[base + 8 * mt + 4 + (g >> 1)] = packh2(w1, v1);
                    }
                }
            }
        }
    } else {
#pragma unroll
        for (int mt = 0; mt < 2; mt++)
#pragma unroll
            for (int dh = 0; dh < 2; dh++) {
                int d = 16 * mt + 8 * dh + g;
#pragma unroll
                for (int nt = 0; nt < 8; nt++) {
                    unsigned pv = packh2(acc[mt][nt][2 * dh + 1], acc[mt][nt][2 * dh]);
                    vh[((size_t)(b * 4 + head) * 32 + d) * (NPIX / 2) + (pix0 + 8 * nt) / 2 + c] = pv;
                }
            }
    }
}

// ---------------------------------------------------------------------------
// Split-fp16 output projection (unchanged).
// ---------------------------------------------------------------------------
#define GO 12
__global__ __launch_bounds__(128) void gemm_out_h(
    const unsigned* __restrict__ whi, const unsigned* __restrict__ wlo,
    const unsigned* __restrict__ xhi, const unsigned* __restrict__ xlo,
    float* __restrict__ out, const float* __restrict__ bias)
{
    __shared__ unsigned sWh[2][128 * GO], sWl[2][128 * GO];
    __shared__ unsigned sXh[2][64 * GO],  sXl[2][64 * GO];

    const int b = blockIdx.z;
    const int row0 = blockIdx.y * 128, pix0 = blockIdx.x * 64;
    const int tid = threadIdx.x, lane = tid & 31, warp = tid >> 5;
    const int g = lane >> 2, c = lane & 3;
    const unsigned whb = (unsigned)__cvta_generic_to_shared(&sWh[0][0]);
    const unsigned wlb = (unsigned)__cvta_generic_to_shared(&sWl[0][0]);
    const unsigned xhb = (unsigned)__cvta_generic_to_shared(&sXh[0][0]);
    const unsigned xlb = (unsigned)__cvta_generic_to_shared(&sXl[0][0]);
    const unsigned* xhs = xhi + (size_t)b * NPIX * 64;
    const unsigned* xls = xlo + (size_t)b * NPIX * 64;
    float* outb = out + (size_t)b * 256 * NPIX;

    float acc[2][8][4];
#pragma unroll
    for (int mt = 0; mt < 2; mt++)
#pragma unroll
        for (int nt = 0; nt < 8; nt++)
#pragma unroll
            for (int r = 0; r < 4; r++) acc[mt][nt][r] = 0.f;

    auto fill = [&](int kk, int s) {
        const unsigned* wh_ = whi + (size_t)(row0 + tid) * 64 + kk / 2;
        const unsigned* wl_ = wlo + (size_t)(row0 + tid) * 64 + kk / 2;
        cpasync16(whb + (unsigned)(s * 128 * GO + tid * GO) * 4u, wh_);
        cpasync16(whb + (unsigned)(s * 128 * GO + tid * GO + 4) * 4u, wh_ + 4);
        cpasync16(wlb + (unsigned)(s * 128 * GO + tid * GO) * 4u, wl_);
        cpasync16(wlb + (unsigned)(s * 128 * GO + tid * GO + 4) * 4u, wl_ + 4);
        int row = tid >> 1, sg = tid & 1;
        cpasync16(xhb + (unsigned)(s * 64 * GO + row * GO + sg * 4) * 4u,
                  xhs + (size_t)(pix0 + row) * 64 + kk / 2 + sg * 4);
        cpasync16(xlb + (unsigned)(s * 64 * GO + row * GO + sg * 4) * 4u,
                  xls + (size_t)(pix0 + row) * 64 + kk / 2 + sg * 4);
        asm volatile("cp.async.commit_group;");
    };

    fill(0, 0);
    for (int ch = 0; ch < 8; ++ch) {
        if (ch < 7) {
            fill((ch + 1) * 16, (ch + 1) & 1);
            asm volatile("cp.async.wait_group 1;");
        } else {
            asm volatile("cp.async.wait_group 0;");
        }
        __syncthreads();
        const int s = ch & 1;
        const unsigned* wh0 = &sWh[s][0];
        const unsigned* wl0 = &sWl[s][0];
        const unsigned* xh0 = &sXh[s][0];
        const unsigned* xl0 = &sXl[s][0];
        unsigned bh[8][2], bl[8][2];
#pragma unroll
        for (int nt = 0; nt < 8; nt++) {
            bh[nt][0] = xh0[(8 * nt + g) * GO + c];
            bh[nt][1] = xh0[(8 * nt + g) * GO + c + 4];
            bl[nt][0] = xl0[(8 * nt + g) * GO + c];
            bl[nt][1] = xl0[(8 * nt + g) * GO + c + 4];
        }
#pragma unroll
        for (int mt = 0; mt < 2; mt++) {
            int mrow = 32 * warp + 16 * mt;
            unsigned ah0 = wh0[(mrow + g) * GO + c],     ah1 = wh0[(mrow + 8 + g) * GO + c];
            unsigned ah2 = wh0[(mrow + g) * GO + c + 4], ah3 = wh0[(mrow + 8 + g) * GO + c + 4];
            unsigned al0 = wl0[(mrow + g) * GO + c],     al1 = wl0[(mrow + 8 + g) * GO + c];
            unsigned al2 = wl0[(mrow + g) * GO + c + 4], al3 = wl0[(mrow + 8 + g) * GO + c + 4];
#pragma unroll
            for (int nt = 0; nt < 8; nt++) {
                mma_f16(acc[mt][nt], ah0, ah1, ah2, ah3, bh[nt][0], bh[nt][1]);
                mma_f16(acc[mt][nt], ah0, ah1, ah2, ah3, bl[nt][0], bl[nt][1]);
                mma_f16(acc[mt][nt], al0, al1, al2, al3, bh[nt][0], bh[nt][1]);
            }
        }
        __syncthreads();
    }

#pragma unroll
    for (int mt = 0; mt < 2; mt++) {
        int r0 = row0 + 32 * warp + 16 * mt + g;
        float b0 = bias[r0], b1 = bias[r0 + 8];
#pragma unroll
        for (int nt = 0; nt < 8; nt++) {
            int col = pix0 + 8 * nt + 2 * c;
            *(float2*)&outb[(size_t)r0 * NPIX + col] =
                make_float2(acc[mt][nt][0] + b0, acc[mt][nt][1] + b0);
            *(float2*)&outb[(size_t)(r0 + 8) * NPIX + col] =
                make_float2(acc[mt][nt][2] + b1, acc[mt][nt][3] + b1);
        }
    }
}

// ---------------------------------------------------------------------------
// fp16 flash, q-major S; V ldmatrix hoisted to overlap exp latency.
// ---------------------------------------------------------------------------
#define SKH 20
#define SVH 68
#define FSTAGE (128 * SKH + 32 * SVH)
#define H2ONES 0x3C003C00u

__global__ __launch_bounds__(128, 4) void flash_h_kernel(
    const unsigned* __restrict__ qh, const unsigned* __restrict__ kh,
    const unsigned* __restrict__ vh, unsigned* __restrict__ aohi,
    unsigned* __restrict__ aolo)
{
    __shared__ unsigned sm[2 * FSTAGE];

    const int tid = threadIdx.x, lane = tid & 31, warp = tid >> 5;
    const int g = lane >> 2, c = lane & 3;
    const int bh = blockIdx.y, b = bh >> 2, h = bh & 3;
    const int qw = blockIdx.x * 128 + warp * 32;

    const unsigned* qbh = qh + (size_t)bh * NPIX * 16;
    const unsigned* kbh = kh + (size_t)bh * NPIX * 16;
    const unsigned* vbh = vh + (size_t)bh * 32 * (NPIX / 2);
    const unsigned sbase = (unsigned)__cvta_generic_to_shared(sm);
    const unsigned kOff = (unsigned)(((lane & 7) + 8 * ((lane >> 4) & 1)) * SKH + 4 * ((lane >> 3) & 1));
    const unsigned vOff = (unsigned)(((lane & 7) + 8 * ((lane >> 4) & 1)) * SVH + 4 * ((lane >> 3) & 1));

    unsigned aq[2][2][4];
#pragma unroll
    for (int mq = 0; mq < 2; mq++) {
        const unsigned* q0 = qbh + (size_t)(qw + 16 * mq + g) * 16;
        const unsigned* q1 = qbh + (size_t)(qw + 16 * mq + 8 + g) * 16;
#pragma unroll
        for (int ks = 0; ks < 2; ks++) {
            aq[mq][ks][0] = q0[8 * ks + c];
            aq[mq][ks][1] = q1[8 * ks + c];
            aq[mq][ks][2] = q0[8 * ks + c + 4];
            aq[mq][ks][3] = q1[8 * ks + c + 4];
        }
    }

    float O[2][4][4];
    float Oex[2][4];
#pragma unroll
    for (int mq = 0; mq < 2; mq++) {
#pragma unroll
        for (int nd = 0; nd < 4; nd++)
#pragma unroll
            for (int r = 0; r < 4; r++) O[mq][nd][r] = 0.f;
#pragma unroll
        for (int r = 0; r < 4; r++) Oex[mq][r] = 0.f;
    }

    auto fill = [&](int it, int s) {
        unsigned base = sbase + (unsigned)(s * FSTAGE) * 4u;
        int j0 = it * 128;
#pragma unroll
        for (int r = 0; r < 4; r++) {
            int id = tid + r * 128;
            int row = id >> 2, j = id & 3;
            cpasync16(base + (unsigned)(row * SKH + 4 * j) * 4u,
                      kbh + (size_t)(j0 + row) * 16 + 4 * j);
            int d = id >> 4, jj = id & 15;
            cpasync16(base + (unsigned)(128 * SKH + d * SVH + 4 * jj) * 4u,
                      vbh + (size_t)d * (NPIX / 2) + j0 / 2 + 4 * jj);
        }
        asm volatile("cp.async.commit_group;");
    };

    fill(0, 0);

    for (int it = 0; it < 32; ++it) {
        asm volatile("cp.async.wait_group 0;");
        __syncthreads();
        if (it < 31) fill(it + 1, (it + 1) & 1);

        const unsigned kb = sbase + (unsigned)((it & 1) * FSTAGE) * 4u;
        const unsigned vb = kb + (unsigned)(128 * SKH) * 4u;

#pragma unroll
        for (int kc = 0; kc < 8; kc++) {
            unsigned kf0[4], kf1[4];
            ldm4(kf0, kb + ((unsigned)(16 * kc * SKH) + kOff) * 4u);
            ldm4(kf1, kb + ((unsigned)(16 * kc * SKH + 8) + kOff) * 4u);

            float acc[2][2][4];
#pragma unroll
            for (int mq = 0; mq < 2; mq++)
#pragma unroll
                for (int nt = 0; nt < 2; nt++) {
#pragma unroll
                    for (int r = 0; r < 4; r++) acc[mq][nt][r] = 0.f;
                    mma_f16(acc[mq][nt], aq[mq][0][0], aq[mq][0][1], aq[mq][0][2], aq[mq][0][3],
                            kf0[2 * nt], kf0[2 * nt + 1]);
                    mma_f16(acc[mq][nt], aq[mq][1][0], aq[mq][1][1], aq[mq][1][2], aq[mq][1][3],
                            kf1[2 * nt], kf1[2 * nt + 1]);
                }

            // Hoist V fragment loads: LDS latency overlaps pack/exp chain below.
            unsigned vf0[4], vf1[4];
            ldm4(vf0, vb + ((unsigned)(8 * kc) + vOff) * 4u);
            ldm4(vf1, vb + ((unsigned)(16 * SVH + 8 * kc) + vOff) * 4u);

            unsigned pa[2][4];
#pragma unroll
            for (int mq = 0; mq < 2; mq++) {
                pa[mq][0] = h2exp2(packh2(acc[mq][0][1], acc[mq][0][0]));
                pa[mq][1] = h2exp2(packh2(acc[mq][0][3], acc[mq][0][2]));
                pa[mq][2] = h2exp2(packh2(acc[mq][1][1], acc[mq][1][0]));
                pa[mq][3] = h2exp2(packh2(acc[mq][1][3], acc[mq][1][2]));
            }

#pragma unroll
            for (int mq = 0; mq < 2; mq++) {
                mma_f16(O[mq][0], pa[mq][0], pa[mq][1], pa[mq][2], pa[mq][3], vf0[0], vf0[1]);
                mma_f16(O[mq][1], pa[mq][0], pa[mq][1], pa[mq][2], pa[mq][3], vf0[2], vf0[3]);
                mma_f16(O[mq][2], pa[mq][0], pa[mq][1], pa[mq][2], pa[mq][3], vf1[0], vf1[1]);
                mma_f16(O[mq][3], pa[mq][0], pa[mq][1], pa[mq][2], pa[mq][3], vf1[2], vf1[3]);
                mma_f16(Oex[mq], pa[mq][0], pa[mq][1], pa[mq][2], pa[mq][3], H2ONES, H2ONES);
            }
        }
    }

    float linvq[2], linvq8[2];
#pragma unroll
    for (int mq = 0; mq < 2; mq++) {
        linvq[mq]  = 1.f / Oex[mq][0];
        linvq8[mq] = 1.f / Oex[mq][2];
    }

    unsigned* aoh = aohi + (size_t)b * NPIX * 64;
    unsigned* aol = aolo + (size_t)b * NPIX * 64;
#pragma unroll
    for (int mq = 0; mq < 2; mq++)
#pragma unroll
        for (int nd = 0; nd < 4; nd++) {
            int q0 = qw + 16 * mq + g;
            int pr = h * 16 + 4 * nd + c;
            float o0 = O[mq][nd][0] * linvq[mq];
            float o1 = O[mq][nd][1] * linvq[mq];
            __half h0 = __float2half_rn(o0), h1 = __float2half_rn(o1);
            aoh[(size_t)q0 * 64 + pr] =
                (unsigned)__half_as_ushort(h0) | ((unsigned)__half_as_ushort(h1) << 16);
            aol[(size_t)q0 * 64 + pr] =
                packh2(o1 - __half2float(h1), o0 - __half2float(h0));
            float o2 = O[mq][nd][2] * linvq8[mq];
            float o3 = O[mq][nd][3] * linvq8[mq];
            __half h2 = __float2half_rn(o2), h3 = __float2half_rn(o3);
            aoh[(size_t)(q0 + 8) * 64 + pr] =
                (unsigned)__half_as_ushort(h2) | ((unsigned)__half_as_ushort(h3) << 16);
            aol[(size_t)(q0 + 8) * 64 + pr] =
                packh2(o3 - __half2float(h3), o2 - __half2float(h2));
        }
}

// ---------------------------------------------------------------------------
extern "C" void kernel_launch(void* const* d_in, const int* in_sizes, int n_in,
                              void* d_out, int out_size)
{
    const float* x     = (const float*)d_in[0];
    const float* w_qkv = (const float*)d_in[1];
    const float* w_out = (const float*)d_in[2];
    const float* b_out = (const float*)d_in[3];
    float* out = (float*)d_out;

    static unsigned *qh = nullptr, *kh = nullptr, *vh = nullptr, *wh = nullptr, *xh = nullptr;
    static unsigned *w2hi = nullptr, *w2lo = nullptr, *aohi = nullptr, *aolo = nullptr;
    if (!qh) {
        cudaGetSymbolAddress((void**)&qh,   g_qh);
        cudaGetSymbolAddress((void**)&kh,   g_kh);
        cudaGetSymbolAddress((void**)&vh,   g_vh);
        cudaGetSymbolAddress((void**)&wh,   g_wh);
        cudaGetSymbolAddress((void**)&xh,   g_xh);
        cudaGetSymbolAddress((void**)&w2hi, g_w2hi);
        cudaGetSymbolAddress((void**)&w2lo, g_w2lo);
        cudaGetSymbolAddress((void**)&aohi, g_aohi);
        cudaGetSymbolAddress((void**)&aolo, g_aolo);
        cudaFuncSetAttribute(gemm_qkv_h, cudaFuncAttributeMaxDynamicSharedMemorySize, QKVSM);
    }

    cvtw_kernel<<<192, 256>>>(w_qkv, wh, w_out, w2hi, w2lo);
    xcvt_kernel<<<dim3(NPIX / 64, 256 / 64, NB), 256>>>(x, xh);

    dim3 g1(NPIX / 128, 3, NB);
    gemm_qkv_h<<<g1, 256, QKVSM>>>(wh, xh, qh, kh, vh);

    dim3 g3(NPIX / 128, 16);
    flash_h_kernel<<<g3, 128>>>(qh, kh, vh, aohi, aolo);

    dim3 g4(NPIX / 64, 2, NB);
    gemm_out_h<<<g4, 128>>>(w2hi, w2lo, aohi, aolo, out, b_out);
}